// round 4
// baseline (speedup 1.0000x reference)
#include <cuda_runtime.h>
#include <cuda_fp16.h>

// ---------------------------------------------------------------------------
// Packed f32x2 helpers (Blackwell FFMA2 via PTX fma.rn.f32x2)
// ---------------------------------------------------------------------------
__device__ __forceinline__ unsigned long long pack2(float a, float b) {
    unsigned long long r;
    asm("mov.b64 %0, {%1, %2};" : "=l"(r) : "f"(a), "f"(b));
    return r;
}
__device__ __forceinline__ void unpack2(unsigned long long v, float& a, float& b) {
    asm("mov.b64 {%0, %1}, %2;" : "=f"(a), "=f"(b) : "l"(v));
}
__device__ __forceinline__ void ffma2(unsigned long long& d,
                                      unsigned long long a,
                                      unsigned long long b) {
    asm("fma.rn.f32x2 %0, %1, %2, %0;" : "+l"(d) : "l"(a), "l"(b));
}

__device__ __forceinline__ unsigned h2bits(float a, float b) {
    __half2 h = __floats2half2_rn(a, b);
    return *reinterpret_cast<unsigned*>(&h);
}

// fp16 tensor-core mma, fp32 accumulate
__device__ __forceinline__ void mma16(float d[4], const unsigned a[4],
                                      unsigned b0, unsigned b1) {
    asm("mma.sync.aligned.m16n8k16.row.col.f32.f16.f16.f32 "
        "{%0,%1,%2,%3},{%4,%5,%6,%7},{%8,%9},{%0,%1,%2,%3};"
        : "+f"(d[0]), "+f"(d[1]), "+f"(d[2]), "+f"(d[3])
        : "r"(a[0]), "r"(a[1]), "r"(a[2]), "r"(a[3]), "r"(b0), "r"(b1));
}

// ---------------------------------------------------------------------------
// Scratch (device globals; allocation-free)
// ---------------------------------------------------------------------------
__device__ float g_w1 [ 2097152];  // [8,   4,256,256]
__device__ float g_cat2[16777216]; // [8,  32,256,256]  c1 @0..15, iwt(ic2) @16..31
__device__ float g_w2 [ 8388608];  // [8,  64,128,128]
__device__ float g_cat3[16777216]; // [8, 128,128,128]  c2 @0..63, iwt(ic3) @64..127
__device__ float g_w3 [ 8388608];  // [8, 256, 64, 64]
__device__ float g_cat4[16777216]; // [8, 512, 64, 64]  c3 @0..255, iwt(ic4) @256..511
__device__ float g_w4 [ 8388608];  // [8,1024, 32, 32]
__device__ float g_c4 [ 8388608];
__device__ float g_c5 [ 8388608];
__device__ float g_ic4[ 8388608];
__device__ float g_ic3[ 8388608];  // [8, 256, 64, 64]
__device__ float g_ic2[ 8388608];  // [8,  64,128,128]
__device__ float g_ic1[ 8388608];  // [8,  16,256,256]
__device__ float g_iw1[ 2097152];  // [8,   4,256,256]

// ---------------------------------------------------------------------------
// Haar wavelet forward
// ---------------------------------------------------------------------------
__global__ void wt_k(const float* __restrict__ in, int inCtot, int inCoff,
                     float* __restrict__ out, int C, int Ho, int Wo, int total) {
    int idx = blockIdx.x * blockDim.x + threadIdx.x;
    if (idx >= total) return;
    int wo = idx % Wo; int t = idx / Wo;
    int ho = t % Ho;  t /= Ho;
    int c  = t % C;   int b = t / C;
    int Wi = 2 * Wo, Hi = 2 * Ho;
    const float* p = in + (((long long)b * inCtot + inCoff + c) * Hi + 2 * ho) * Wi + 2 * wo;
    float x00 = p[0], x01 = p[1], x10 = p[Wi], x11 = p[Wi + 1];
    float y0 = 0.25f * (x00 + x01 + x10 + x11);
    float y1 = 0.5f  * (x00 + x01 - x10 - x11);
    float y2 = 0.5f  * (x00 - x01 + x10 - x11);
    float y3 = 0.5f  * (x00 - x01 - x10 + x11);
    long long s  = (long long)Ho * Wo;
    long long ob = (((long long)b * (4 * C) + c * 4) * Ho + ho) * Wo + wo;
    out[ob]         = y0;
    out[ob + s]     = 0.5f * y1 + 0.5f;
    out[ob + 2 * s] = 0.5f * y2 + 0.5f;
    out[ob + 3 * s] = 0.5f * y3 + 0.5f;
}

// ---------------------------------------------------------------------------
// Haar wavelet inverse (optional fused sigmoid)
// ---------------------------------------------------------------------------
__global__ void iwt_k(const float* __restrict__ in, int C, int H, int W,
                      float* __restrict__ out, int outCtot, int outCoff,
                      int doSigmoid, int total) {
    int idx = blockIdx.x * blockDim.x + threadIdx.x;
    if (idx >= total) return;
    int w = idx % W; int t = idx / W;
    int h = t % H;  t /= H;
    int c = t % C;  int b = t / C;
    long long s  = (long long)H * W;
    long long ib = (((long long)b * (4 * C) + 4 * c) * H + h) * W + w;
    float y0 = in[ib];
    float t1 = 2.f * in[ib + s]     - 1.f;
    float t2 = 2.f * in[ib + 2 * s] - 1.f;
    float t3 = 2.f * in[ib + 3 * s] - 1.f;
    float x00 = y0 + 0.5f * ( t1 + t2 + t3);
    float x01 = y0 + 0.5f * ( t1 - t2 - t3);
    float x10 = y0 + 0.5f * (-t1 + t2 - t3);
    float x11 = y0 + 0.5f * (-t1 - t2 + t3);
    if (doSigmoid) {
        x00 = 1.f / (1.f + expf(-x00));
        x01 = 1.f / (1.f + expf(-x01));
        x10 = 1.f / (1.f + expf(-x10));
        x11 = 1.f / (1.f + expf(-x11));
    }
    int W2 = 2 * W;
    float* o = out + (((long long)b * outCtot + outCoff + c) * (2 * H) + 2 * h) * W2 + 2 * w;
    o[0] = x00; o[1] = x01; o[W2] = x10; o[W2 + 1] = x11;
}

// ---------------------------------------------------------------------------
// Scalar FFMA2 direct 3x3 conv — used only for the tiny-channel layers
// ---------------------------------------------------------------------------
template <int PAIRS>
__global__ __launch_bounds__(256)
void conv3x3_k(const float* __restrict__ in, int Cin, int inCtot, int inCoff,
               const float* __restrict__ wgt, const float* __restrict__ bias,
               float* __restrict__ out, int outCtot, int outCoff,
               int H, int W, int numCog,
               const float* __restrict__ addend, int addCtot, int addCoff,
               int doLrelu) {
    __shared__ float patch[34 * 34];
    __shared__ unsigned long long wsm[PAIRS * 9];

    const int tx  = threadIdx.x;
    const int ty  = threadIdx.y;
    const int tid = ty * 32 + tx;
    const int b   = blockIdx.z / numCog;
    const int cog = blockIdx.z % numCog;
    const int ox  = blockIdx.x * 32 + tx;
    const int oy0 = blockIdx.y * 32 + ty * 4;
    const int co0 = cog * (2 * PAIRS);
    const int gx0 = blockIdx.x * 32 - 1;
    const int gy0 = blockIdx.y * 32 - 1;

    unsigned long long acc[PAIRS][4];
#pragma unroll
    for (int pr = 0; pr < PAIRS; pr++)
#pragma unroll
        for (int p = 0; p < 4; p++) acc[pr][p] = 0ULL;

    for (int ci = 0; ci < Cin; ci++) {
        __syncthreads();
        const float* inc = in + ((long long)b * inCtot + inCoff + ci) * H * W;
        for (int idx = tid; idx < 34 * 34; idx += 256) {
            int py = idx / 34, px = idx % 34;
            int gy = gy0 + py, gx = gx0 + px;
            float v = 0.f;
            if (gy >= 0 && gy < H && gx >= 0 && gx < W) v = inc[gy * W + gx];
            patch[idx] = v;
        }
        if (tid < PAIRS * 9) {
            int pr = tid / 9, j = tid % 9;
            int c0 = co0 + 2 * pr;
            wsm[tid] = pack2(wgt[((long long)c0 * Cin + ci) * 9 + j],
                             wgt[((long long)(c0 + 1) * Cin + ci) * 9 + j]);
        }
        __syncthreads();

        unsigned long long v2[6][3];
#pragma unroll
        for (int r = 0; r < 6; r++)
#pragma unroll
            for (int d = 0; d < 3; d++) {
                float v = patch[(ty * 4 + r) * 34 + tx + d];
                v2[r][d] = pack2(v, v);
            }

#pragma unroll
        for (int pr = 0; pr < PAIRS; pr++) {
            unsigned long long w2[9];
#pragma unroll
            for (int j = 0; j < 9; j++) w2[j] = wsm[pr * 9 + j];
#pragma unroll
            for (int p = 0; p < 4; p++) {
#pragma unroll
                for (int dy = 0; dy < 3; dy++)
#pragma unroll
                    for (int dx = 0; dx < 3; dx++)
                        ffma2(acc[pr][p], w2[dy * 3 + dx], v2[p + dy][dx]);
            }
        }
    }

#pragma unroll
    for (int pr = 0; pr < PAIRS; pr++) {
        int c0 = co0 + 2 * pr;
        float b0 = bias[c0], b1 = bias[c0 + 1];
#pragma unroll
        for (int p = 0; p < 4; p++) {
            float r0, r1;
            unpack2(acc[pr][p], r0, r1);
            r0 += b0; r1 += b1;
            int oy = oy0 + p;
            if (addend) {
                r0 += addend[(((long long)b * addCtot + addCoff + c0)     * H + oy) * W + ox];
                r1 += addend[(((long long)b * addCtot + addCoff + c0 + 1) * H + oy) * W + ox];
            }
            if (doLrelu) {
                r0 = r0 > 0.f ? r0 : 0.2f * r0;
                r1 = r1 > 0.f ? r1 : 0.2f * r1;
            }
            out[(((long long)b * outCtot + outCoff + c0)     * H + oy) * W + ox] = r0;
            out[(((long long)b * outCtot + outCoff + c0 + 1) * H + oy) * W + ox] = r1;
        }
    }
}

// ---------------------------------------------------------------------------
// fp16 tensor-core implicit-GEMM 3x3 conv (pad 1), fp32 accumulate.
// Block: 256 threads = 8 warps (2 M-warps x 4 N-warps).
// Block tile: 64 output channels x 256 pixels (16x16 spatial).
// K-loop: 16 input channels per chunk (m16n8k16); per chunk iterate 9 taps.
// SMEM layouts are conflict-free by construction:
//   patch[kg][y][20]  : bank = (8*kg + x) % 32, kg=tig, x=gid-varied -> perm
//   wsm[tap][kg][72]  : 72 % 32 == 8 -> same permutation
// Requires: Cout % 64 == 0, Cin % 16 == 0, H % 16 == 0, W % 16 == 0.
// ---------------------------------------------------------------------------
__global__ __launch_bounds__(256, 2)
void conv3x3_mma_k(const float* __restrict__ in, int Cin, int inCtot, int inCoff,
                   const float* __restrict__ wgt, const float* __restrict__ bias,
                   float* __restrict__ out, int outCtot, int outCoff,
                   int H, int W,
                   const float* __restrict__ addend, int addCtot, int addCoff,
                   int doLrelu) {
    __shared__ unsigned patch[8][18][20];   // half2(ci=2g, 2g+1) halo patch
    __shared__ unsigned wsm[9][8][72];      // [tap][kgroup][co pad 72], half2(k)

    const int tid  = threadIdx.x;
    const int lane = tid & 31;
    const int warp = tid >> 5;
    const int gid  = lane >> 2;   // 0..7
    const int tig  = lane & 3;    // 0..3
    const int mwarp = warp & 1;   // 0..1 -> 32 channels each
    const int nwarp = warp >> 1;  // 0..3 -> 64 pixels each

    const int tilesX = W >> 4;
    const int tx0 = (blockIdx.x % tilesX) << 4;
    const int ty0 = (blockIdx.x / tilesX) << 4;
    const int co0 = blockIdx.y << 6;
    const int b   = blockIdx.z;
    const int HW  = H * W;

    float acc[2][8][4];
#pragma unroll
    for (int mt = 0; mt < 2; mt++)
#pragma unroll
        for (int nt = 0; nt < 8; nt++)
#pragma unroll
            for (int r = 0; r < 4; r++) acc[mt][nt][r] = 0.f;

    const long long inBase = ((long long)b * inCtot + inCoff) * (long long)HW;

    for (int ci0 = 0; ci0 < Cin; ci0 += 16) {
        __syncthreads();
        // stage input patch: 8 half2-groups x 18x18 halo
        for (int idx = tid; idx < 8 * 324; idx += 256) {
            int g = idx / 324;
            int rem = idx - g * 324;
            int r = rem / 18, c = rem - r * 18;
            int gy = ty0 - 1 + r, gx = tx0 - 1 + c;
            float v0 = 0.f, v1 = 0.f;
            if ((unsigned)gy < (unsigned)H && (unsigned)gx < (unsigned)W) {
                const float* p = in + inBase + (long long)(ci0 + 2 * g) * HW + gy * W + gx;
                v0 = p[0];
                v1 = p[HW];
            }
            patch[g][r][c] = h2bits(v0, v1);
        }
        // stage weights: 9 taps x 8 kgroups x 64 co
        for (int idx = tid; idx < 9 * 8 * 64; idx += 256) {
            int j = idx / 512;
            int rem = idx - j * 512;
            int kg = rem >> 6;
            int co = rem & 63;
            const float* wp = wgt + ((long long)(co0 + co) * Cin + ci0 + 2 * kg) * 9 + j;
            wsm[j][kg][co] = h2bits(wp[0], wp[9]);
        }
        __syncthreads();

#pragma unroll
        for (int j = 0; j < 9; j++) {
            const int dy = j / 3, dx = j % 3;
            unsigned a[2][4];
#pragma unroll
            for (int mt = 0; mt < 2; mt++) {
                int cl = mwarp * 32 + mt * 16 + gid;
                a[mt][0] = wsm[j][tig][cl];
                a[mt][1] = wsm[j][tig][cl + 8];
                a[mt][2] = wsm[j][tig + 4][cl];
                a[mt][3] = wsm[j][tig + 4][cl + 8];
            }
            const unsigned* pb0 = &patch[tig][dy][dx + gid];
            const unsigned* pb1 = &patch[tig + 4][dy][dx + gid];
#pragma unroll
            for (int nt = 0; nt < 8; nt++) {
                int pix = nwarp * 64 + nt * 8;
                int off = (pix >> 4) * 20 + (pix & 15);  // py*20 + px0
                unsigned b0 = pb0[off];
                unsigned b1 = pb1[off];
                mma16(acc[0][nt], a[0], b0, b1);
                mma16(acc[1][nt], a[1], b0, b1);
            }
        }
    }

    // epilogue: bias (+addend) (+lrelu), float2 stores
#pragma unroll
    for (int mt = 0; mt < 2; mt++) {
#pragma unroll
        for (int rr = 0; rr < 2; rr++) {
            int co = co0 + mwarp * 32 + mt * 16 + rr * 8 + gid;
            float bv = bias[co];
            long long obase = ((long long)b * outCtot + outCoff + co) * H;
            long long abase = addend ? ((long long)b * addCtot + addCoff + co) * H : 0;
#pragma unroll
            for (int nt = 0; nt < 8; nt++) {
                int pix = nwarp * 64 + nt * 8;
                int oy = ty0 + (pix >> 4);
                int ox = tx0 + (pix & 15) + 2 * tig;
                float v0 = acc[mt][nt][rr * 2]     + bv;
                float v1 = acc[mt][nt][rr * 2 + 1] + bv;
                if (addend) {
                    const float* ap = addend + (abase + oy) * W + ox;
                    v0 += ap[0];
                    v1 += ap[1];
                }
                if (doLrelu) {
                    v0 = v0 > 0.f ? v0 : 0.2f * v0;
                    v1 = v1 > 0.f ? v1 : 0.2f * v1;
                }
                float2 val = make_float2(v0, v1);
                *reinterpret_cast<float2*>(out + (obase + oy) * W + ox) = val;
            }
        }
    }
}

// ---------------------------------------------------------------------------
// Orchestration
// ---------------------------------------------------------------------------
static inline void launch_conv_small(const float* in, int Cin, int inCtot, int inCoff,
                                     const float* w, const float* bvec,
                                     float* out, int Cout, int outCtot, int outCoff,
                                     int H, int W, int doLrelu) {
    dim3 bdim(32, 8);
    if (Cout >= 8) {
        int numCog = Cout / 8;
        dim3 grid(W / 32, H / 32, 8 * numCog);
        conv3x3_k<4><<<grid, bdim>>>(in, Cin, inCtot, inCoff, w, bvec,
                                     out, outCtot, outCoff, H, W, numCog,
                                     nullptr, 0, 0, doLrelu);
    } else {
        int numCog = Cout / 4;
        dim3 grid(W / 32, H / 32, 8 * numCog);
        conv3x3_k<2><<<grid, bdim>>>(in, Cin, inCtot, inCoff, w, bvec,
                                     out, outCtot, outCoff, H, W, numCog,
                                     nullptr, 0, 0, doLrelu);
    }
}

static inline void launch_conv_mma(const float* in, int Cin, int inCtot, int inCoff,
                                   const float* w, const float* bvec,
                                   float* out, int Cout, int outCtot, int outCoff,
                                   int H, int W,
                                   const float* addend, int addCtot, int addCoff,
                                   int doLrelu) {
    dim3 grid((W / 16) * (H / 16), Cout / 64, 8);
    conv3x3_mma_k<<<grid, 256>>>(in, Cin, inCtot, inCoff, w, bvec,
                                 out, outCtot, outCoff, H, W,
                                 addend, addCtot, addCoff, doLrelu);
}

extern "C" void kernel_launch(void* const* d_in, const int* in_sizes, int n_in,
                              void* d_out, int out_size) {
    const float* x        = (const float*)d_in[0];
    const float* conv1_w  = (const float*)d_in[1];
    const float* conv1_b  = (const float*)d_in[2];
    const float* conv2_w  = (const float*)d_in[3];
    const float* conv2_b  = (const float*)d_in[4];
    const float* conv3_w  = (const float*)d_in[5];
    const float* conv3_b  = (const float*)d_in[6];
    const float* conv4_w  = (const float*)d_in[7];
    const float* conv4_b  = (const float*)d_in[8];
    const float* convd1_w = (const float*)d_in[9];
    const float* convd1_b = (const float*)d_in[10];
    const float* convd2_w = (const float*)d_in[11];
    const float* convd2_b = (const float*)d_in[12];
    const float* convd3_w = (const float*)d_in[13];
    const float* convd3_b = (const float*)d_in[14];
    const float* convd4_w = (const float*)d_in[15];
    const float* convd4_b = (const float*)d_in[16];
    float* out = (float*)d_out;

    float *w1, *cat2, *w2, *cat3, *w3, *cat4, *w4, *c4, *c5, *ic4, *ic3, *ic2, *ic1, *iw1;
    cudaGetSymbolAddress((void**)&w1,  g_w1);
    cudaGetSymbolAddress((void**)&cat2, g_cat2);
    cudaGetSymbolAddress((void**)&w2,  g_w2);
    cudaGetSymbolAddress((void**)&cat3, g_cat3);
    cudaGetSymbolAddress((void**)&w3,  g_w3);
    cudaGetSymbolAddress((void**)&cat4, g_cat4);
    cudaGetSymbolAddress((void**)&w4,  g_w4);
    cudaGetSymbolAddress((void**)&c4,  g_c4);
    cudaGetSymbolAddress((void**)&c5,  g_c5);
    cudaGetSymbolAddress((void**)&ic4, g_ic4);
    cudaGetSymbolAddress((void**)&ic3, g_ic3);
    cudaGetSymbolAddress((void**)&ic2, g_ic2);
    cudaGetSymbolAddress((void**)&ic1, g_ic1);
    cudaGetSymbolAddress((void**)&iw1, g_iw1);

    const int B = 8;
    int tot;

    // --- encoder ---
    tot = B * 1 * 256 * 256;
    wt_k<<<(tot + 255) / 256, 256>>>(x, 1, 0, w1, 1, 256, 256, tot);

    // c1 = lrelu(conv1(w1)) -> cat2[ch 0..15]   (4->16 @256², scalar)
    launch_conv_small(w1, 4, 4, 0, conv1_w, conv1_b, cat2, 16, 32, 0, 256, 256, 1);

    tot = B * 16 * 128 * 128;
    wt_k<<<(tot + 255) / 256, 256>>>(cat2, 32, 0, w2, 16, 128, 128, tot);

    // c2 = lrelu(conv2(w2)) -> cat3[ch 0..63]   (64->64 @128², mma)
    launch_conv_mma(w2, 64, 64, 0, conv2_w, conv2_b, cat3, 64, 128, 0, 128, 128,
                    nullptr, 0, 0, 1);

    tot = B * 64 * 64 * 64;
    wt_k<<<(tot + 255) / 256, 256>>>(cat3, 128, 0, w3, 64, 64, 64, tot);

    // c3 = lrelu(conv3(w3)) -> cat4[ch 0..255]  (256->256 @64², mma)
    launch_conv_mma(w3, 256, 256, 0, conv3_w, conv3_b, cat4, 256, 512, 0, 64, 64,
                    nullptr, 0, 0, 1);

    tot = B * 256 * 32 * 32;
    wt_k<<<(tot + 255) / 256, 256>>>(cat4, 512, 0, w4, 256, 32, 32, tot);

    // --- bottleneck: conv4 x3 (1024->1024 @32², mma) ---
    launch_conv_mma(w4, 1024, 1024, 0, conv4_w, conv4_b, c4, 1024, 1024, 0, 32, 32,
                    nullptr, 0, 0, 1);
    launch_conv_mma(c4, 1024, 1024, 0, conv4_w, conv4_b, c5, 1024, 1024, 0, 32, 32,
                    nullptr, 0, 0, 1);
    launch_conv_mma(c5, 1024, 1024, 0, conv4_w, conv4_b, ic4, 1024, 1024, 0, 32, 32,
                    w4, 1024, 0, 1);   // + w4 residual, lrelu

    // --- decoder ---
    tot = B * 256 * 32 * 32;
    iwt_k<<<(tot + 255) / 256, 256>>>(ic4, 256, 32, 32, cat4, 512, 256, 0, tot);

    // ic3 = lrelu(convd4(cat4))  (512->256 @64², mma)
    launch_conv_mma(cat4, 512, 512, 0, convd4_w, convd4_b, ic3, 256, 256, 0, 64, 64,
                    nullptr, 0, 0, 1);

    tot = B * 64 * 64 * 64;
    iwt_k<<<(tot + 255) / 256, 256>>>(ic3, 64, 64, 64, cat3, 128, 64, 0, tot);

    // ic2 = lrelu(convd3(cat3))  (128->64 @128², mma)
    launch_conv_mma(cat3, 128, 128, 0, convd3_w, convd3_b, ic2, 64, 64, 0, 128, 128,
                    nullptr, 0, 0, 1);

    tot = B * 16 * 128 * 128;
    iwt_k<<<(tot + 255) / 256, 256>>>(ic2, 16, 128, 128, cat2, 32, 16, 0, tot);

    // ic1 = lrelu(convd2(cat2))  (32->16 @256², scalar)
    launch_conv_small(cat2, 32, 32, 0, convd2_w, convd2_b, ic1, 16, 16, 0, 256, 256, 1);

    // iw1 = lrelu(convd1(ic1))   (16->4 @256², scalar)
    launch_conv_small(ic1, 16, 16, 0, convd1_w, convd1_b, iw1, 4, 4, 0, 256, 256, 1);

    tot = B * 1 * 256 * 256;
    iwt_k<<<(tot + 255) / 256, 256>>>(iw1, 1, 256, 256, out, 1, 0, 1, tot);

    (void)in_sizes; (void)n_in; (void)out_size;
}

// round 5
// speedup vs baseline: 3.0299x; 3.0299x over previous
#include <cuda_runtime.h>
#include <cuda_fp16.h>

// ---------------------------------------------------------------------------
// helpers
// ---------------------------------------------------------------------------
__device__ __forceinline__ unsigned h2bits(float a, float b) {
    __half2 h = __floats2half2_rn(a, b);
    return *reinterpret_cast<unsigned*>(&h);
}

// fp16 tensor-core mma m16n8k16, fp32 accumulate
__device__ __forceinline__ void mma16(float d[4], const unsigned a[4],
                                      unsigned b0, unsigned b1) {
    asm("mma.sync.aligned.m16n8k16.row.col.f32.f16.f16.f32 "
        "{%0,%1,%2,%3},{%4,%5,%6,%7},{%8,%9},{%0,%1,%2,%3};"
        : "+f"(d[0]), "+f"(d[1]), "+f"(d[2]), "+f"(d[3])
        : "r"(a[0]), "r"(a[1]), "r"(a[2]), "r"(a[3]), "r"(b0), "r"(b1));
}

// ---------------------------------------------------------------------------
// Scratch (device globals; allocation-free)
// fp32 tensors (only where a fp32 consumer exists)
// ---------------------------------------------------------------------------
__device__ float g_c1 [ 8388608];  // [8,  16,256,256]
__device__ float g_c2 [ 8388608];  // [8,  64,128,128]
__device__ float g_c3 [ 8388608];  // [8, 256, 64, 64]
__device__ float g_w4 [ 8388608];  // [8,1024, 32, 32]  (residual addend)
__device__ float g_ic4[ 8388608];  // [8,1024, 32, 32]
__device__ float g_ic3[ 8388608];  // [8, 256, 64, 64]
__device__ float g_ic2[ 8388608];  // [8,  64,128,128]
__device__ float g_iw1[ 2097152];  // [8,   4,256,256]

// half2 channel-pair-packed activations: word(b,g,y,x) = h2(ch 2g, ch 2g+1)
__device__ unsigned g_w1h  [ 1048576]; // [8,  2g,256,256]
__device__ unsigned g_cat2h[ 8388608]; // [8, 16g,256,256] c1 g0..7 | iwt(ic2) g8..15
__device__ unsigned g_w2h  [ 4194304]; // [8, 32g,128,128]
__device__ unsigned g_cat3h[ 8388608]; // [8, 64g,128,128] c2 g0..31 | iwt(ic3) g32..63
__device__ unsigned g_w3h  [ 4194304]; // [8,128g, 64, 64]
__device__ unsigned g_cat4h[ 8388608]; // [8,256g, 64, 64] c3 g0..127 | iwt(ic4) g128..255
__device__ unsigned g_w4h  [ 4194304]; // [8,512g, 32, 32]
__device__ unsigned g_c4h  [ 4194304]; // [8,512g, 32, 32]
__device__ unsigned g_c5h  [ 4194304]; // [8,512g, 32, 32]
__device__ unsigned g_ic1h [ 4194304]; // [8,  8g,256,256]

// packed weights: [(CinPad/2) groups][9 taps][CoutPad] half2 over (2ci,2ci+1)
__device__ unsigned g_wp1 [   1152];   // CinPad16, CoutPad16
__device__ unsigned g_wp2 [  18432];   // 64x64
__device__ unsigned g_wp3 [ 294912];   // 256x256
__device__ unsigned g_wp4 [4718592];   // 1024x1024
__device__ unsigned g_wpd4[ 589824];   // 512->256
__device__ unsigned g_wpd3[  36864];   // 128->64
__device__ unsigned g_wpd2[   2304];   // 32->16
__device__ unsigned g_wpd1[   1152];   // 16->4 (CoutPad16)

// ---------------------------------------------------------------------------
// weight packing: out[(ci2*9+j)*CoutPad + co] = h2(w[co][2ci2][j], w[co][2ci2+1][j])
// ---------------------------------------------------------------------------
__global__ void pack_w_k(const float* __restrict__ w, unsigned* __restrict__ out,
                         int Cin, int Cout, int CoutPad, int total) {
    int idx = blockIdx.x * blockDim.x + threadIdx.x;
    if (idx >= total) return;
    int co = idx % CoutPad;
    int t  = idx / CoutPad;
    int j  = t % 9;
    int ci2 = t / 9;
    float v0 = 0.f, v1 = 0.f;
    if (co < Cout) {
        int c0 = 2 * ci2, c1 = 2 * ci2 + 1;
        if (c0 < Cin) v0 = w[((long long)co * Cin + c0) * 9 + j];
        if (c1 < Cin) v1 = w[((long long)co * Cin + c1) * 9 + j];
    }
    out[idx] = h2bits(v0, v1);
}

// ---------------------------------------------------------------------------
// Haar wavelet forward: in fp32 [B,C,2Ho,2Wo] -> h2 [B,2C,Ho,Wo] (+opt fp32 [B,4C,Ho,Wo])
// ---------------------------------------------------------------------------
__global__ void wt_k(const float* __restrict__ in, int C, int Ho, int Wo,
                     float* __restrict__ out32, unsigned* __restrict__ outH2,
                     int total) {
    int idx = blockIdx.x * blockDim.x + threadIdx.x;
    if (idx >= total) return;
    int wo = idx % Wo; int t = idx / Wo;
    int ho = t % Ho;  t /= Ho;
    int c  = t % C;   int b = t / C;
    int Wi = 2 * Wo;
    const float* p = in + (((long long)b * C + c) * (2 * Ho) + 2 * ho) * Wi + 2 * wo;
    float x00 = p[0], x01 = p[1], x10 = p[Wi], x11 = p[Wi + 1];
    float y0 = 0.25f * (x00 + x01 + x10 + x11);
    float y1 = 0.25f * (x00 + x01 - x10 - x11) + 0.5f;
    float y2 = 0.25f * (x00 - x01 + x10 - x11) + 0.5f;
    float y3 = 0.25f * (x00 - x01 - x10 + x11) + 0.5f;
    long long s = (long long)Ho * Wo;
    if (out32) {
        long long ob = (((long long)b * (4 * C) + 4 * c) * Ho + ho) * Wo + wo;
        out32[ob] = y0; out32[ob + s] = y1; out32[ob + 2 * s] = y2; out32[ob + 3 * s] = y3;
    }
    long long hb = (((long long)b * (2 * C) + 2 * c) * Ho + ho) * Wo + wo;
    outH2[hb]     = h2bits(y0, y1);
    outH2[hb + s] = h2bits(y2, y3);
}

// ---------------------------------------------------------------------------
// Haar inverse, channel-pair version: in fp32 [B,8*pairs,H,W] -> h2 [B,gTot,2H,2W] slice
// ---------------------------------------------------------------------------
__global__ void iwt_h2_k(const float* __restrict__ in, int pairs, int H, int W,
                         unsigned* __restrict__ outH2, int gTot, int gOff, int total) {
    int idx = blockIdx.x * blockDim.x + threadIdx.x;
    if (idx >= total) return;
    int w = idx % W; int t = idx / W;
    int h = t % H;  t /= H;
    int g = t % pairs; int b = t / pairs;
    long long s = (long long)H * W;
    float x00[2], x01[2], x10[2], x11[2];
#pragma unroll
    for (int cc = 0; cc < 2; cc++) {
        int c = 2 * g + cc;
        long long ib = (((long long)b * (8 * pairs) + 4 * c) * H + h) * W + w;
        float y0 = in[ib];
        float t1 = 2.f * in[ib + s]     - 1.f;
        float t2 = 2.f * in[ib + 2 * s] - 1.f;
        float t3 = 2.f * in[ib + 3 * s] - 1.f;
        x00[cc] = y0 + 0.5f * ( t1 + t2 + t3);
        x01[cc] = y0 + 0.5f * ( t1 - t2 - t3);
        x10[cc] = y0 + 0.5f * (-t1 + t2 - t3);
        x11[cc] = y0 + 0.5f * (-t1 - t2 + t3);
    }
    int W2 = 2 * W;
    long long ob = (((long long)b * gTot + gOff + g) * (2 * H) + 2 * h) * W2 + 2 * w;
    uint2 r0, r1;
    r0.x = h2bits(x00[0], x00[1]); r0.y = h2bits(x01[0], x01[1]);
    r1.x = h2bits(x10[0], x10[1]); r1.y = h2bits(x11[0], x11[1]);
    *reinterpret_cast<uint2*>(outH2 + ob)      = r0;
    *reinterpret_cast<uint2*>(outH2 + ob + W2) = r1;
}

// ---------------------------------------------------------------------------
// Final Haar inverse (C=1) + sigmoid, fp32 out
// ---------------------------------------------------------------------------
__global__ void iwt_sig_k(const float* __restrict__ in, int H, int W,
                          float* __restrict__ out, int total) {
    int idx = blockIdx.x * blockDim.x + threadIdx.x;
    if (idx >= total) return;
    int w = idx % W; int t = idx / W;
    int h = t % H;  int b = t / H;
    long long s = (long long)H * W;
    long long ib = (((long long)b * 4) * H + h) * W + w;
    float y0 = in[ib];
    float t1 = 2.f * in[ib + s]     - 1.f;
    float t2 = 2.f * in[ib + 2 * s] - 1.f;
    float t3 = 2.f * in[ib + 3 * s] - 1.f;
    float x00 = y0 + 0.5f * ( t1 + t2 + t3);
    float x01 = y0 + 0.5f * ( t1 - t2 - t3);
    float x10 = y0 + 0.5f * (-t1 + t2 - t3);
    float x11 = y0 + 0.5f * (-t1 - t2 + t3);
    x00 = 1.f / (1.f + expf(-x00));
    x01 = 1.f / (1.f + expf(-x01));
    x10 = 1.f / (1.f + expf(-x10));
    x11 = 1.f / (1.f + expf(-x11));
    int W2 = 2 * W;
    float* o = out + ((long long)b * (2 * H) + 2 * h) * W2 + 2 * w;
    o[0] = x00; o[1] = x01; o[W2] = x10; o[W2 + 1] = x11;
}

// ---------------------------------------------------------------------------
// fp16 tensor-core implicit-GEMM 3x3 conv (pad 1), fp32 accumulate.
// COTILE=64: 256 thr = 2 M-warps x 4 N-warps, tile 64co x 256pix (16x16).
// COTILE=16: 128 thr = 1x4, tile 16co x 256pix.
// Inputs are channel-pair-packed half2 tensors; weights pre-packed.
// ---------------------------------------------------------------------------
template <int COTILE>
__global__ __launch_bounds__((COTILE == 64) ? 256 : 128, (COTILE == 64) ? 2 : 4)
void conv_mma_k(const unsigned* __restrict__ inH2, int gInTot, int gInAct, int kTiles,
                const unsigned* __restrict__ wp, int coutPad,
                const float* __restrict__ bias,
                float* __restrict__ out32, int out32Ctot,
                unsigned* __restrict__ outH2, int gOutTot, int gOutOff,
                const float* __restrict__ addend, int addCtot,
                int H, int W, int coutAct, int lrelu) {
    constexpr int NTHREADS = (COTILE == 64) ? 256 : 128;
    constexpr int MT = (COTILE == 64) ? 2 : 1;
    __shared__ unsigned patch[8][18][20];
    __shared__ unsigned wsm[9][8][COTILE + 8];

    const int tid  = threadIdx.x;
    const int lane = tid & 31;
    const int warp = tid >> 5;
    const int gid  = lane >> 2;
    const int tig  = lane & 3;
    const int mwarp = (COTILE == 64) ? (warp & 1) : 0;
    const int nwarp = (COTILE == 64) ? (warp >> 1) : warp;

    const int tilesX = W >> 4;
    const int tx0 = (blockIdx.x % tilesX) << 4;
    const int ty0 = (blockIdx.x / tilesX) << 4;
    const int co0 = blockIdx.y * COTILE;
    const int b   = blockIdx.z;
    const int HW  = H * W;

    float acc[MT][8][4];
#pragma unroll
    for (int mt = 0; mt < MT; mt++)
#pragma unroll
        for (int nt = 0; nt < 8; nt++)
#pragma unroll
            for (int r = 0; r < 4; r++) acc[mt][nt][r] = 0.f;

    const long long inBase = (long long)b * gInTot * HW;

    for (int kt = 0; kt < kTiles; kt++) {
        const int g0 = kt * 8;
        __syncthreads();
        // stage halo patch (1 coalesced LDG.32 per half2 word)
        for (int idx = tid; idx < 8 * 324; idx += NTHREADS) {
            int g = idx / 324;
            int rem = idx - g * 324;
            int r = rem / 18, c = rem - r * 18;
            int gy = ty0 - 1 + r, gx = tx0 - 1 + c;
            unsigned v = 0;
            int absG = g0 + g;
            if (absG < gInAct && (unsigned)gy < (unsigned)H && (unsigned)gx < (unsigned)W)
                v = inH2[inBase + (long long)absG * HW + gy * W + gx];
            patch[g][r][c] = v;
        }
        // stage weights (coalesced uint2 loads of pre-packed half2)
        constexpr int WT2 = 9 * 8 * (COTILE / 2);
        for (int idx = tid; idx < WT2; idx += NTHREADS) {
            int co2 = idx % (COTILE / 2);
            int t   = idx / (COTILE / 2);
            int kg  = t % 8;
            int j   = t / 8;
            uint2 v = *reinterpret_cast<const uint2*>(
                wp + ((long long)(g0 + kg) * 9 + j) * coutPad + co0 + 2 * co2);
            *reinterpret_cast<uint2*>(&wsm[j][kg][2 * co2]) = v;
        }
        __syncthreads();

#pragma unroll
        for (int j = 0; j < 9; j++) {
            const int dy = j / 3, dx = j - 3 * dy;
            unsigned a[MT][4];
#pragma unroll
            for (int mt = 0; mt < MT; mt++) {
                int cl = mwarp * 32 + mt * 16 + gid;
                a[mt][0] = wsm[j][tig][cl];
                a[mt][1] = wsm[j][tig][cl + 8];
                a[mt][2] = wsm[j][tig + 4][cl];
                a[mt][3] = wsm[j][tig + 4][cl + 8];
            }
            const unsigned* pb0 = &patch[tig][dy][dx + gid];
            const unsigned* pb1 = &patch[tig + 4][dy][dx + gid];
#pragma unroll
            for (int nt = 0; nt < 8; nt++) {
                int pix = nwarp * 64 + nt * 8;
                int off = (pix >> 4) * 20 + (pix & 15);
                unsigned b0 = pb0[off];
                unsigned b1 = pb1[off];
#pragma unroll
                for (int mt = 0; mt < MT; mt++)
                    mma16(acc[mt][nt], a[mt], b0, b1);
            }
        }
    }

    // epilogue: bias (+addend) (+lrelu); fp32 float2 stores and/or half2 stores
#pragma unroll
    for (int mt = 0; mt < MT; mt++) {
#pragma unroll
        for (int rr = 0; rr < 2; rr++) {
            int co = co0 + mwarp * 32 + mt * 16 + rr * 8 + gid;
            float bv = (co < coutAct) ? bias[co] : 0.f;
#pragma unroll
            for (int nt = 0; nt < 8; nt++) {
                int pix = nwarp * 64 + nt * 8;
                int oy = ty0 + (pix >> 4);
                int ox = tx0 + (pix & 15) + 2 * tig;
                float v0 = acc[mt][nt][rr * 2]     + bv;
                float v1 = acc[mt][nt][rr * 2 + 1] + bv;
                if (addend) {
                    const float* ap = addend + (((long long)b * addCtot + co) * H + oy) * W + ox;
                    v0 += ap[0]; v1 += ap[1];
                }
                if (lrelu) {
                    v0 = v0 > 0.f ? v0 : 0.2f * v0;
                    v1 = v1 > 0.f ? v1 : 0.2f * v1;
                }
                if (out32 && co < coutAct) {
                    float2 val = make_float2(v0, v1);
                    *reinterpret_cast<float2*>(
                        out32 + (((long long)b * out32Ctot + co) * H + oy) * W + ox) = val;
                }
                if (outH2) {
                    float s0 = __shfl_xor_sync(0xffffffffu, v0, 4);
                    float s1 = __shfl_xor_sync(0xffffffffu, v1, 4);
                    if ((gid & 1) == 0) {
                        uint2 wv;
                        wv.x = h2bits(v0, s0);
                        wv.y = h2bits(v1, s1);
                        *reinterpret_cast<uint2*>(
                            outH2 + (((long long)b * gOutTot + gOutOff + (co >> 1)) * H + oy) * W + ox) = wv;
                    }
                }
            }
        }
    }
}

// ---------------------------------------------------------------------------
// Orchestration
// ---------------------------------------------------------------------------
extern "C" void kernel_launch(void* const* d_in, const int* in_sizes, int n_in,
                              void* d_out, int out_size) {
    const float* x        = (const float*)d_in[0];
    const float* conv1_w  = (const float*)d_in[1];
    const float* conv1_b  = (const float*)d_in[2];
    const float* conv2_w  = (const float*)d_in[3];
    const float* conv2_b  = (const float*)d_in[4];
    const float* conv3_w  = (const float*)d_in[5];
    const float* conv3_b  = (const float*)d_in[6];
    const float* conv4_w  = (const float*)d_in[7];
    const float* conv4_b  = (const float*)d_in[8];
    const float* convd1_w = (const float*)d_in[9];
    const float* convd1_b = (const float*)d_in[10];
    const float* convd2_w = (const float*)d_in[11];
    const float* convd2_b = (const float*)d_in[12];
    const float* convd3_w = (const float*)d_in[13];
    const float* convd3_b = (const float*)d_in[14];
    const float* convd4_w = (const float*)d_in[15];
    const float* convd4_b = (const float*)d_in[16];
    float* out = (float*)d_out;

    float *c1, *c2, *c3, *w4, *ic4, *ic3, *ic2, *iw1;
    unsigned *w1h, *cat2h, *w2h, *cat3h, *w3h, *cat4h, *w4h, *c4h, *c5h, *ic1h;
    unsigned *wp1, *wp2, *wp3, *wp4, *wpd4, *wpd3, *wpd2, *wpd1;
    cudaGetSymbolAddress((void**)&c1,  g_c1);
    cudaGetSymbolAddress((void**)&c2,  g_c2);
    cudaGetSymbolAddress((void**)&c3,  g_c3);
    cudaGetSymbolAddress((void**)&w4,  g_w4);
    cudaGetSymbolAddress((void**)&ic4, g_ic4);
    cudaGetSymbolAddress((void**)&ic3, g_ic3);
    cudaGetSymbolAddress((void**)&ic2, g_ic2);
    cudaGetSymbolAddress((void**)&iw1, g_iw1);
    cudaGetSymbolAddress((void**)&w1h,  g_w1h);
    cudaGetSymbolAddress((void**)&cat2h, g_cat2h);
    cudaGetSymbolAddress((void**)&w2h,  g_w2h);
    cudaGetSymbolAddress((void**)&cat3h, g_cat3h);
    cudaGetSymbolAddress((void**)&w3h,  g_w3h);
    cudaGetSymbolAddress((void**)&cat4h, g_cat4h);
    cudaGetSymbolAddress((void**)&w4h,  g_w4h);
    cudaGetSymbolAddress((void**)&c4h,  g_c4h);
    cudaGetSymbolAddress((void**)&c5h,  g_c5h);
    cudaGetSymbolAddress((void**)&ic1h, g_ic1h);
    cudaGetSymbolAddress((void**)&wp1,  g_wp1);
    cudaGetSymbolAddress((void**)&wp2,  g_wp2);
    cudaGetSymbolAddress((void**)&wp3,  g_wp3);
    cudaGetSymbolAddress((void**)&wp4,  g_wp4);
    cudaGetSymbolAddress((void**)&wpd4, g_wpd4);
    cudaGetSymbolAddress((void**)&wpd3, g_wpd3);
    cudaGetSymbolAddress((void**)&wpd2, g_wpd2);
    cudaGetSymbolAddress((void**)&wpd1, g_wpd1);

    const int B = 8;
    int tot;

    // --- pack all weights to half2 ---
    auto pack = [](const float* w, unsigned* outp, int Cin, int CinPad, int Cout, int CoutPad) {
        int total = (CinPad / 2) * 9 * CoutPad;
        pack_w_k<<<(total + 255) / 256, 256>>>(w, outp, Cin, Cout, CoutPad, total);
    };
    pack(conv1_w,  wp1,    4,   16,   16,   16);
    pack(conv2_w,  wp2,   64,   64,   64,   64);
    pack(conv3_w,  wp3,  256,  256,  256,  256);
    pack(conv4_w,  wp4, 1024, 1024, 1024, 1024);
    pack(convd4_w, wpd4, 512,  512,  256,  256);
    pack(convd3_w, wpd3, 128,  128,   64,   64);
    pack(convd2_w, wpd2,  32,   32,   16,   16);
    pack(convd1_w, wpd1,  16,   16,    4,   16);

    // --- encoder ---
    tot = B * 1 * 256 * 256;
    wt_k<<<(tot + 255) / 256, 256>>>(x, 1, 256, 256, nullptr, w1h, tot);

    // conv1: 4->16 @256²  -> c1 fp32 + cat2h g0..7
    conv_mma_k<16><<<dim3(256, 1, 8), 128>>>(w1h, 2, 2, 1, wp1, 16, conv1_b,
                                             c1, 16, cat2h, 16, 0, nullptr, 0,
                                             256, 256, 16, 1);

    tot = B * 16 * 128 * 128;
    wt_k<<<(tot + 255) / 256, 256>>>(c1, 16, 128, 128, nullptr, w2h, tot);

    // conv2: 64->64 @128² -> c2 fp32 + cat3h g0..31
    conv_mma_k<64><<<dim3(64, 1, 8), 256>>>(w2h, 32, 32, 4, wp2, 64, conv2_b,
                                            c2, 64, cat3h, 64, 0, nullptr, 0,
                                            128, 128, 64, 1);

    tot = B * 64 * 64 * 64;
    wt_k<<<(tot + 255) / 256, 256>>>(c2, 64, 64, 64, nullptr, w3h, tot);

    // conv3: 256->256 @64² -> c3 fp32 + cat4h g0..127
    conv_mma_k<64><<<dim3(16, 4, 8), 256>>>(w3h, 128, 128, 16, wp3, 256, conv3_b,
                                            c3, 256, cat4h, 256, 0, nullptr, 0,
                                            64, 64, 256, 1);

    tot = B * 256 * 32 * 32;
    wt_k<<<(tot + 255) / 256, 256>>>(c3, 256, 32, 32, w4, w4h, tot);

    // --- bottleneck: conv4 x3 (1024->1024 @32²) ---
    conv_mma_k<64><<<dim3(4, 16, 8), 256>>>(w4h, 512, 512, 64, wp4, 1024, conv4_b,
                                            nullptr, 0, c4h, 512, 0, nullptr, 0,
                                            32, 32, 1024, 1);
    conv_mma_k<64><<<dim3(4, 16, 8), 256>>>(c4h, 512, 512, 64, wp4, 1024, conv4_b,
                                            nullptr, 0, c5h, 512, 0, nullptr, 0,
                                            32, 32, 1024, 1);
    conv_mma_k<64><<<dim3(4, 16, 8), 256>>>(c5h, 512, 512, 64, wp4, 1024, conv4_b,
                                            ic4, 1024, nullptr, 0, 0, w4, 1024,
                                            32, 32, 1024, 1);

    // --- decoder ---
    tot = B * 128 * 32 * 32;   // iwt(ic4) -> cat4h g128..255
    iwt_h2_k<<<(tot + 255) / 256, 256>>>(ic4, 128, 32, 32, cat4h, 256, 128, tot);

    // convd4: 512->256 @64² -> ic3 fp32
    conv_mma_k<64><<<dim3(16, 4, 8), 256>>>(cat4h, 256, 256, 32, wpd4, 256, convd4_b,
                                            ic3, 256, nullptr, 0, 0, nullptr, 0,
                                            64, 64, 256, 1);

    tot = B * 32 * 64 * 64;    // iwt(ic3) -> cat3h g32..63
    iwt_h2_k<<<(tot + 255) / 256, 256>>>(ic3, 32, 64, 64, cat3h, 64, 32, tot);

    // convd3: 128->64 @128² -> ic2 fp32
    conv_mma_k<64><<<dim3(64, 1, 8), 256>>>(cat3h, 64, 64, 8, wpd3, 64, convd3_b,
                                            ic2, 64, nullptr, 0, 0, nullptr, 0,
                                            128, 128, 64, 1);

    tot = B * 8 * 128 * 128;   // iwt(ic2) -> cat2h g8..15
    iwt_h2_k<<<(tot + 255) / 256, 256>>>(ic2, 8, 128, 128, cat2h, 16, 8, tot);

    // convd2: 32->16 @256² -> ic1h only
    conv_mma_k<16><<<dim3(256, 1, 8), 128>>>(cat2h, 16, 16, 2, wpd2, 16, convd2_b,
                                             nullptr, 0, ic1h, 8, 0, nullptr, 0,
                                             256, 256, 16, 1);

    // convd1: 16->4 @256² -> iw1 fp32 (CoutPad 16, coutAct 4)
    conv_mma_k<16><<<dim3(256, 1, 8), 128>>>(ic1h, 8, 8, 1, wpd1, 16, convd1_b,
                                             iw1, 4, nullptr, 0, 0, nullptr, 0,
                                             256, 256, 4, 1);

    tot = B * 256 * 256;       // sigmoid(iwt(iw1)) -> out
    iwt_sig_k<<<(tot + 255) / 256, 256>>>(iw1, 256, 256, out, tot);

    (void)in_sizes; (void)n_in; (void)out_size;
}

// round 6
// speedup vs baseline: 3.3425x; 1.1032x over previous
#include <cuda_runtime.h>
#include <cuda_fp16.h>

// ---------------------------------------------------------------------------
// helpers
// ---------------------------------------------------------------------------
__device__ __forceinline__ unsigned h2bits(float a, float b) {
    __half2 h = __floats2half2_rn(a, b);
    return *reinterpret_cast<unsigned*>(&h);
}

__device__ __forceinline__ void mma16(float d[4], const unsigned a[4],
                                      unsigned b0, unsigned b1) {
    asm("mma.sync.aligned.m16n8k16.row.col.f32.f16.f16.f32 "
        "{%0,%1,%2,%3},{%4,%5,%6,%7},{%8,%9},{%0,%1,%2,%3};"
        : "+f"(d[0]), "+f"(d[1]), "+f"(d[2]), "+f"(d[3])
        : "r"(a[0]), "r"(a[1]), "r"(a[2]), "r"(a[3]), "r"(b0), "r"(b1));
}

__device__ __forceinline__ unsigned smem_u32(const void* p) {
    return (unsigned)__cvta_generic_to_shared(p);
}
__device__ __forceinline__ void cp4(unsigned dst, const void* src, bool ok) {
    int sz = ok ? 4 : 0;
    asm volatile("cp.async.ca.shared.global [%0], [%1], 4, %2;"
                 :: "r"(dst), "l"(src), "r"(sz));
}
__device__ __forceinline__ void cp16(unsigned dst, const void* src) {
    asm volatile("cp.async.cg.shared.global [%0], [%1], 16;" :: "r"(dst), "l"(src));
}
__device__ __forceinline__ void cp_commit() { asm volatile("cp.async.commit_group;"); }
__device__ __forceinline__ void cp_wait1() { asm volatile("cp.async.wait_group 1;"); }
__device__ __forceinline__ void cp_wait0() { asm volatile("cp.async.wait_group 0;"); }

// ---------------------------------------------------------------------------
// Scratch (device globals; allocation-free)
// ---------------------------------------------------------------------------
__device__ float g_c1 [ 8388608];  // [8,  16,256,256]
__device__ float g_c2 [ 8388608];  // [8,  64,128,128]
__device__ float g_c3 [ 8388608];  // [8, 256, 64, 64]
__device__ float g_w4 [ 8388608];  // [8,1024, 32, 32]  (residual addend)
__device__ float g_ic4[ 8388608];  // [8,1024, 32, 32]
__device__ float g_ic3[ 8388608];  // [8, 256, 64, 64]
__device__ float g_ic2[ 8388608];  // [8,  64,128,128]
__device__ float g_iw1[ 2097152];  // [8,   4,256,256]

// half2 channel-pair-packed activations
__device__ unsigned g_w1h  [ 1048576];
__device__ unsigned g_cat2h[ 8388608]; // c1 g0..7 | iwt(ic2) g8..15
__device__ unsigned g_w2h  [ 4194304];
__device__ unsigned g_cat3h[ 8388608]; // c2 g0..31 | iwt(ic3) g32..63
__device__ unsigned g_w3h  [ 4194304];
__device__ unsigned g_cat4h[ 8388608]; // c3 g0..127 | iwt(ic4) g128..255
__device__ unsigned g_w4h  [ 4194304];
__device__ unsigned g_c4h  [ 4194304];
__device__ unsigned g_c5h  [ 4194304];
__device__ unsigned g_ic1h [ 4194304];

// packed weights: [(CinPad/2)][9][CoutPad] half2 over (2ci,2ci+1)
__device__ unsigned g_wp1 [   1152];
__device__ unsigned g_wp2 [  18432];
__device__ unsigned g_wp3 [ 294912];
__device__ unsigned g_wp4 [4718592];
__device__ unsigned g_wpd4[ 589824];
__device__ unsigned g_wpd3[  36864];
__device__ unsigned g_wpd2[   2304];
__device__ unsigned g_wpd1[   1152];

// ---------------------------------------------------------------------------
// weight packing: out[(ci2*9+j)*CoutPad + co] = h2(w[co][2ci2][j], w[co][2ci2+1][j])
// grid: (ceil(CoutPad/256), 9, CinPad/2)
// ---------------------------------------------------------------------------
__global__ void pack_w_k(const float* __restrict__ w, unsigned* __restrict__ out,
                         int Cin, int Cout, int CoutPad) {
    int co  = blockIdx.x * blockDim.x + threadIdx.x;
    if (co >= CoutPad) return;
    int j   = blockIdx.y;
    int ci2 = blockIdx.z;
    float v0 = 0.f, v1 = 0.f;
    if (co < Cout) {
        int c0 = 2 * ci2, c1 = 2 * ci2 + 1;
        if (c0 < Cin) v0 = w[((long long)co * Cin + c0) * 9 + j];
        if (c1 < Cin) v1 = w[((long long)co * Cin + c1) * 9 + j];
    }
    out[((long long)ci2 * 9 + j) * CoutPad + co] = h2bits(v0, v1);
}

// ---------------------------------------------------------------------------
// Haar wavelet forward: fp32 [B,C,2Ho,2Wo] -> h2 [B,2C,Ho,Wo] (+opt fp32 [B,4C,...])
// ---------------------------------------------------------------------------
__global__ void wt_k(const float* __restrict__ in, int C, int Ho, int Wo,
                     float* __restrict__ out32, unsigned* __restrict__ outH2,
                     int total) {
    int idx = blockIdx.x * blockDim.x + threadIdx.x;
    if (idx >= total) return;
    int wo = idx % Wo; int t = idx / Wo;
    int ho = t % Ho;  t /= Ho;
    int c  = t % C;   int b = t / C;
    int Wi = 2 * Wo;
    const float* p = in + (((long long)b * C + c) * (2 * Ho) + 2 * ho) * Wi + 2 * wo;
    float x00 = p[0], x01 = p[1], x10 = p[Wi], x11 = p[Wi + 1];
    float y0 = 0.25f * (x00 + x01 + x10 + x11);
    float y1 = 0.25f * (x00 + x01 - x10 - x11) + 0.5f;
    float y2 = 0.25f * (x00 - x01 + x10 - x11) + 0.5f;
    float y3 = 0.25f * (x00 - x01 - x10 + x11) + 0.5f;
    long long s = (long long)Ho * Wo;
    if (out32) {
        long long ob = (((long long)b * (4 * C) + 4 * c) * Ho + ho) * Wo + wo;
        out32[ob] = y0; out32[ob + s] = y1; out32[ob + 2 * s] = y2; out32[ob + 3 * s] = y3;
    }
    long long hb = (((long long)b * (2 * C) + 2 * c) * Ho + ho) * Wo + wo;
    outH2[hb]     = h2bits(y0, y1);
    outH2[hb + s] = h2bits(y2, y3);
}

// ---------------------------------------------------------------------------
// Haar inverse, channel-pair: fp32 [B,8*pairs,H,W] -> h2 slice of [B,gTot,2H,2W]
// ---------------------------------------------------------------------------
__global__ void iwt_h2_k(const float* __restrict__ in, int pairs, int H, int W,
                         unsigned* __restrict__ outH2, int gTot, int gOff, int total) {
    int idx = blockIdx.x * blockDim.x + threadIdx.x;
    if (idx >= total) return;
    int w = idx % W; int t = idx / W;
    int h = t % H;  t /= H;
    int g = t % pairs; int b = t / pairs;
    long long s = (long long)H * W;
    float x00[2], x01[2], x10[2], x11[2];
#pragma unroll
    for (int cc = 0; cc < 2; cc++) {
        int c = 2 * g + cc;
        long long ib = (((long long)b * (8 * pairs) + 4 * c) * H + h) * W + w;
        float y0 = in[ib];
        float t1 = 2.f * in[ib + s]     - 1.f;
        float t2 = 2.f * in[ib + 2 * s] - 1.f;
        float t3 = 2.f * in[ib + 3 * s] - 1.f;
        x00[cc] = y0 + 0.5f * ( t1 + t2 + t3);
        x01[cc] = y0 + 0.5f * ( t1 - t2 - t3);
        x10[cc] = y0 + 0.5f * (-t1 + t2 - t3);
        x11[cc] = y0 + 0.5f * (-t1 - t2 + t3);
    }
    int W2 = 2 * W;
    long long ob = (((long long)b * gTot + gOff + g) * (2 * H) + 2 * h) * W2 + 2 * w;
    uint2 r0, r1;
    r0.x = h2bits(x00[0], x00[1]); r0.y = h2bits(x01[0], x01[1]);
    r1.x = h2bits(x10[0], x10[1]); r1.y = h2bits(x11[0], x11[1]);
    *reinterpret_cast<uint2*>(outH2 + ob)      = r0;
    *reinterpret_cast<uint2*>(outH2 + ob + W2) = r1;
}

// ---------------------------------------------------------------------------
// Final Haar inverse (C=1) + sigmoid, fp32 out
// ---------------------------------------------------------------------------
__global__ void iwt_sig_k(const float* __restrict__ in, int H, int W,
                          float* __restrict__ out, int total) {
    int idx = blockIdx.x * blockDim.x + threadIdx.x;
    if (idx >= total) return;
    int w = idx % W; int t = idx / W;
    int h = t % H;  int b = t / H;
    long long s = (long long)H * W;
    long long ib = (((long long)b * 4) * H + h) * W + w;
    float y0 = in[ib];
    float t1 = 2.f * in[ib + s]     - 1.f;
    float t2 = 2.f * in[ib + 2 * s] - 1.f;
    float t3 = 2.f * in[ib + 3 * s] - 1.f;
    float x00 = y0 + 0.5f * ( t1 + t2 + t3);
    float x01 = y0 + 0.5f * ( t1 - t2 - t3);
    float x10 = y0 + 0.5f * (-t1 + t2 - t3);
    float x11 = y0 + 0.5f * (-t1 - t2 + t3);
    x00 = 1.f / (1.f + expf(-x00));
    x01 = 1.f / (1.f + expf(-x01));
    x10 = 1.f / (1.f + expf(-x10));
    x11 = 1.f / (1.f + expf(-x11));
    int W2 = 2 * W;
    float* o = out + ((long long)b * (2 * H) + 2 * h) * W2 + 2 * w;
    o[0] = x00; o[1] = x01; o[W2] = x10; o[W2 + 1] = x11;
}

// ---------------------------------------------------------------------------
// Pipelined fp16 mma implicit-GEMM 3x3 conv (pad 1), cp.async double buffered.
// COTILE=64 : 256 thr = 2 M-warps x 4 N-warps
// COTILE=128: 512 thr = 4 M-warps x 4 N-warps
// Tile: COTILE cout x 256 pixels (16x16). Requires gIn % 8 == 0.
// ---------------------------------------------------------------------------
template <int COTILE>
__global__ __launch_bounds__(COTILE * 4, (COTILE == 64) ? 2 : 1)
void conv_mma_pipe_k(const unsigned* __restrict__ inH2, int gInTot, int kTiles,
                     const unsigned* __restrict__ wp, int coutPad,
                     const float* __restrict__ bias,
                     float* __restrict__ out32, int out32Ctot,
                     unsigned* __restrict__ outH2, int gOutTot, int gOutOff,
                     const float* __restrict__ addend, int addCtot,
                     int H, int W, int lrelu) {
    constexpr int NTHREADS = COTILE * 4;
    constexpr int MWMASK  = COTILE / 32 - 1;             // 1 or 3
    constexpr int NWSHIFT = (COTILE == 64) ? 1 : 2;
    constexpr int WROW    = COTILE + 8;                  // % 32 == 8 -> conflict-free
    constexpr int PATCH_W = 8 * 360;                     // [g][18 rows][20]
    constexpr int WSM_W   = 72 * WROW;                   // [j*8+kg][WROW]
    constexpr int STAGE   = PATCH_W + WSM_W;
    extern __shared__ unsigned sm[];

    const int tid  = threadIdx.x;
    const int lane = tid & 31;
    const int warp = tid >> 5;
    const int gid  = lane >> 2;
    const int tig  = lane & 3;
    const int mwarp = warp & MWMASK;
    const int nwarp = warp >> NWSHIFT;

    const int tilesX = W >> 4;
    const int tx0 = (blockIdx.x % tilesX) << 4;
    const int ty0 = (blockIdx.x / tilesX) << 4;
    const int co0 = blockIdx.y * COTILE;
    const int b   = blockIdx.z;
    const int HW  = H * W;
    const long long inBase = (long long)b * gInTot * HW;

    float acc[2][8][4];
#pragma unroll
    for (int mt = 0; mt < 2; mt++)
#pragma unroll
        for (int nt = 0; nt < 8; nt++)
#pragma unroll
            for (int r = 0; r < 4; r++) acc[mt][nt][r] = 0.f;

    auto stage = [&](int kt, int buf) {
        const int g0 = kt * 8;
        unsigned pb = smem_u32(sm + buf * STAGE);
        unsigned wb = pb + PATCH_W * 4;
        for (int idx = tid; idx < 8 * 324; idx += NTHREADS) {
            int g = idx / 324, rem = idx - g * 324;
            int r = rem / 18, c = rem - r * 18;
            int gy = ty0 - 1 + r, gx = tx0 - 1 + c;
            bool ok = (unsigned)gy < (unsigned)H && (unsigned)gx < (unsigned)W;
            const unsigned* src = ok
                ? inH2 + inBase + (long long)(g0 + g) * HW + gy * W + gx
                : inH2;
            cp4(pb + (unsigned)(g * 360 + r * 20 + c) * 4u, src, ok);
        }
        constexpr int WCH = 72 * (COTILE / 4);
        for (int idx = tid; idx < WCH; idx += NTHREADS) {
            int row = idx / (COTILE / 4);   // row = j*8 + kg
            int cw  = idx - row * (COTILE / 4);
            int j   = row >> 3;
            int kg  = row & 7;
            const unsigned* src = wp + ((long long)(g0 + kg) * 9 + j) * coutPad
                                  + co0 + cw * 4;
            cp16(wb + (unsigned)(row * WROW + cw * 4) * 4u, src);
        }
    };

    auto compute = [&](int buf) {
        const unsigned* pbuf = sm + buf * STAGE;
        const unsigned* wbuf = pbuf + PATCH_W;
#pragma unroll
        for (int j = 0; j < 9; j++) {
            const int dy = j / 3, dx = j - 3 * dy;
            unsigned a[2][4];
#pragma unroll
            for (int mt = 0; mt < 2; mt++) {
                int cl = mwarp * 32 + mt * 16 + gid;
                a[mt][0] = wbuf[(j * 8 + tig) * WROW + cl];
                a[mt][1] = wbuf[(j * 8 + tig) * WROW + cl + 8];
                a[mt][2] = wbuf[(j * 8 + tig + 4) * WROW + cl];
                a[mt][3] = wbuf[(j * 8 + tig + 4) * WROW + cl + 8];
            }
            const unsigned* pb0 = pbuf + tig * 360 + dy * 20 + dx + gid;
            const unsigned* pb1 = pbuf + (tig + 4) * 360 + dy * 20 + dx + gid;
#pragma unroll
            for (int nt = 0; nt < 8; nt++) {
                int pix = nwarp * 64 + nt * 8;
                int off = (pix >> 4) * 20 + (pix & 15);
                unsigned b0 = pb0[off];
                unsigned b1 = pb1[off];
                mma16(acc[0][nt], a[0], b0, b1);
                mma16(acc[1][nt], a[1], b0, b1);
            }
        }
    };

    stage(0, 0);
    cp_commit();
    for (int kt = 0; kt < kTiles; kt++) {
        int cur = kt & 1;
        if (kt + 1 < kTiles) {
            stage(kt + 1, cur ^ 1);
            cp_commit();
            cp_wait1();
        } else {
            cp_wait0();
        }
        __syncthreads();
        compute(cur);
        __syncthreads();
    }

    // epilogue
#pragma unroll
    for (int mt = 0; mt < 2; mt++) {
#pragma unroll
        for (int rr = 0; rr < 2; rr++) {
            int co = co0 + mwarp * 32 + mt * 16 + rr * 8 + gid;
            float bv = bias[co];
#pragma unroll
            for (int nt = 0; nt < 8; nt++) {
                int pix = nwarp * 64 + nt * 8;
                int oy = ty0 + (pix >> 4);
                int ox = tx0 + (pix & 15) + 2 * tig;
                float v0 = acc[mt][nt][rr * 2]     + bv;
                float v1 = acc[mt][nt][rr * 2 + 1] + bv;
                if (addend) {
                    const float* ap = addend + (((long long)b * addCtot + co) * H + oy) * W + ox;
                    v0 += ap[0]; v1 += ap[1];
                }
                if (lrelu) {
                    v0 = v0 > 0.f ? v0 : 0.2f * v0;
                    v1 = v1 > 0.f ? v1 : 0.2f * v1;
                }
                if (out32) {
                    float2 val = make_float2(v0, v1);
                    *reinterpret_cast<float2*>(
                        out32 + (((long long)b * out32Ctot + co) * H + oy) * W + ox) = val;
                }
                if (outH2) {
                    float s0 = __shfl_xor_sync(0xffffffffu, v0, 4);
                    float s1 = __shfl_xor_sync(0xffffffffu, v1, 4);
                    if ((gid & 1) == 0) {
                        uint2 wv;
                        wv.x = h2bits(v0, s0);
                        wv.y = h2bits(v1, s1);
                        *reinterpret_cast<uint2*>(
                            outH2 + (((long long)b * gOutTot + gOutOff + (co >> 1)) * H + oy) * W + ox) = wv;
                    }
                }
            }
        }
    }
}

// ---------------------------------------------------------------------------
// Small-layer fp16 mma conv (COTILE=16, non-pipelined, handles padded K)
// ---------------------------------------------------------------------------
__global__ __launch_bounds__(128, 4)
void conv_mma16_k(const unsigned* __restrict__ inH2, int gInTot, int gInAct, int kTiles,
                  const unsigned* __restrict__ wp, int coutPad,
                  const float* __restrict__ bias,
                  float* __restrict__ out32, int out32Ctot,
                  unsigned* __restrict__ outH2, int gOutTot, int gOutOff,
                  int H, int W, int coutAct, int lrelu) {
    constexpr int COTILE = 16;
    __shared__ unsigned patch[8][18][20];
    __shared__ unsigned wsm[9][8][COTILE + 8];

    const int tid  = threadIdx.x;
    const int lane = tid & 31;
    const int warp = tid >> 5;
    const int gid  = lane >> 2;
    const int tig  = lane & 3;
    const int nwarp = warp;

    const int tilesX = W >> 4;
    const int tx0 = (blockIdx.x % tilesX) << 4;
    const int ty0 = (blockIdx.x / tilesX) << 4;
    const int co0 = blockIdx.y * COTILE;
    const int b   = blockIdx.z;
    const int HW  = H * W;

    float acc[8][4];
#pragma unroll
    for (int nt = 0; nt < 8; nt++)
#pragma unroll
        for (int r = 0; r < 4; r++) acc[nt][r] = 0.f;

    const long long inBase = (long long)b * gInTot * HW;

    for (int kt = 0; kt < kTiles; kt++) {
        const int g0 = kt * 8;
        __syncthreads();
        for (int idx = tid; idx < 8 * 324; idx += 128) {
            int g = idx / 324;
            int rem = idx - g * 324;
            int r = rem / 18, c = rem - r * 18;
            int gy = ty0 - 1 + r, gx = tx0 - 1 + c;
            unsigned v = 0;
            int absG = g0 + g;
            if (absG < gInAct && (unsigned)gy < (unsigned)H && (unsigned)gx < (unsigned)W)
                v = inH2[inBase + (long long)absG * HW + gy * W + gx];
            patch[g][r][c] = v;
        }
        for (int idx = tid; idx < 9 * 8 * (COTILE / 2); idx += 128) {
            int co2 = idx % (COTILE / 2);
            int t   = idx / (COTILE / 2);
            int kg  = t % 8;
            int j   = t / 8;
            uint2 v = *reinterpret_cast<const uint2*>(
                wp + ((long long)(g0 + kg) * 9 + j) * coutPad + co0 + 2 * co2);
            *reinterpret_cast<uint2*>(&wsm[j][kg][2 * co2]) = v;
        }
        __syncthreads();

#pragma unroll
        for (int j = 0; j < 9; j++) {
            const int dy = j / 3, dx = j - 3 * dy;
            unsigned a[4];
            a[0] = wsm[j][tig][gid];
            a[1] = wsm[j][tig][gid + 8];
            a[2] = wsm[j][tig + 4][gid];
            a[3] = wsm[j][tig + 4][gid + 8];
            const unsigned* pb0 = &patch[tig][dy][dx + gid];
            const unsigned* pb1 = &patch[tig + 4][dy][dx + gid];
#pragma unroll
            for (int nt = 0; nt < 8; nt++) {
                int pix = nwarp * 64 + nt * 8;
                int off = (pix >> 4) * 20 + (pix & 15);
                mma16(acc[nt], a, pb0[off], pb1[off]);
            }
        }
    }

#pragma unroll
    for (int rr = 0; rr < 2; rr++) {
        int co = co0 + rr * 8 + gid;
        float bv = (co < coutAct) ? bias[co] : 0.f;
#pragma unroll
        for (int nt = 0; nt < 8; nt++) {
            int pix = nwarp * 64 + nt * 8;
            int oy = ty0 + (pix >> 4);
            int ox = tx0 + (pix & 15) + 2 * tig;
            float v0 = acc[nt][rr * 2]     + bv;
            float v1 = acc[nt][rr * 2 + 1] + bv;
            if (lrelu) {
                v0 = v0 > 0.f ? v0 : 0.2f * v0;
                v1 = v1 > 0.f ? v1 : 0.2f * v1;
            }
            if (out32 && co < coutAct) {
                float2 val = make_float2(v0, v1);
                *reinterpret_cast<float2*>(
                    out32 + (((long long)b * out32Ctot + co) * H + oy) * W + ox) = val;
            }
            if (outH2) {
                float s0 = __shfl_xor_sync(0xffffffffu, v0, 4);
                float s1 = __shfl_xor_sync(0xffffffffu, v1, 4);
                if ((gid & 1) == 0) {
                    uint2 wv;
                    wv.x = h2bits(v0, s0);
                    wv.y = h2bits(v1, s1);
                    *reinterpret_cast<uint2*>(
                        outH2 + (((long long)b * gOutTot + gOutOff + (co >> 1)) * H + oy) * W + ox) = wv;
                }
            }
        }
    }
}

// ---------------------------------------------------------------------------
// Orchestration
// ---------------------------------------------------------------------------
extern "C" void kernel_launch(void* const* d_in, const int* in_sizes, int n_in,
                              void* d_out, int out_size) {
    const float* x        = (const float*)d_in[0];
    const float* conv1_w  = (const float*)d_in[1];
    const float* conv1_b  = (const float*)d_in[2];
    const float* conv2_w  = (const float*)d_in[3];
    const float* conv2_b  = (const float*)d_in[4];
    const float* conv3_w  = (const float*)d_in[5];
    const float* conv3_b  = (const float*)d_in[6];
    const float* conv4_w  = (const float*)d_in[7];
    const float* conv4_b  = (const float*)d_in[8];
    const float* convd1_w = (const float*)d_in[9];
    const float* convd1_b = (const float*)d_in[10];
    const float* convd2_w = (const float*)d_in[11];
    const float* convd2_b = (const float*)d_in[12];
    const float* convd3_w = (const float*)d_in[13];
    const float* convd3_b = (const float*)d_in[14];
    const float* convd4_w = (const float*)d_in[15];
    const float* convd4_b = (const float*)d_in[16];
    float* out = (float*)d_out;

    float *c1, *c2, *c3, *w4, *ic4, *ic3, *ic2, *iw1;
    unsigned *w1h, *cat2h, *w2h, *cat3h, *w3h, *cat4h, *w4h, *c4h, *c5h, *ic1h;
    unsigned *wp1, *wp2, *wp3, *wp4, *wpd4, *wpd3, *wpd2, *wpd1;
    cudaGetSymbolAddress((void**)&c1,  g_c1);
    cudaGetSymbolAddress((void**)&c2,  g_c2);
    cudaGetSymbolAddress((void**)&c3,  g_c3);
    cudaGetSymbolAddress((void**)&w4,  g_w4);
    cudaGetSymbolAddress((void**)&ic4, g_ic4);
    cudaGetSymbolAddress((void**)&ic3, g_ic3);
    cudaGetSymbolAddress((void**)&ic2, g_ic2);
    cudaGetSymbolAddress((void**)&iw1, g_iw1);
    cudaGetSymbolAddress((void**)&w1h,  g_w1h);
    cudaGetSymbolAddress((void**)&cat2h, g_cat2h);
    cudaGetSymbolAddress((void**)&w2h,  g_w2h);
    cudaGetSymbolAddress((void**)&cat3h, g_cat3h);
    cudaGetSymbolAddress((void**)&w3h,  g_w3h);
    cudaGetSymbolAddress((void**)&cat4h, g_cat4h);
    cudaGetSymbolAddress((void**)&w4h,  g_w4h);
    cudaGetSymbolAddress((void**)&c4h,  g_c4h);
    cudaGetSymbolAddress((void**)&c5h,  g_c5h);
    cudaGetSymbolAddress((void**)&ic1h, g_ic1h);
    cudaGetSymbolAddress((void**)&wp1,  g_wp1);
    cudaGetSymbolAddress((void**)&wp2,  g_wp2);
    cudaGetSymbolAddress((void**)&wp3,  g_wp3);
    cudaGetSymbolAddress((void**)&wp4,  g_wp4);
    cudaGetSymbolAddress((void**)&wpd4, g_wpd4);
    cudaGetSymbolAddress((void**)&wpd3, g_wpd3);
    cudaGetSymbolAddress((void**)&wpd2, g_wpd2);
    cudaGetSymbolAddress((void**)&wpd1, g_wpd1);

    // dynamic smem sizes for pipelined kernels
    const int SMEM64  = 2 * (8 * 360 + 72 * 72)  * 4;   // 64512 B
    const int SMEM128 = 2 * (8 * 360 + 72 * 136) * 4;   // 101376 B
    static bool attrSet = false;
    if (!attrSet) {
        cudaFuncSetAttribute(conv_mma_pipe_k<64>,
                             cudaFuncAttributeMaxDynamicSharedMemorySize, SMEM64);
        cudaFuncSetAttribute(conv_mma_pipe_k<128>,
                             cudaFuncAttributeMaxDynamicSharedMemorySize, SMEM128);
        attrSet = true;
    }

    const int B = 8;
    int tot;

    // --- pack all weights to half2 ---
    auto pack = [](const float* w, unsigned* outp, int Cin, int CinPad, int Cout, int CoutPad) {
        dim3 grid((CoutPad + 255) / 256, 9, CinPad / 2);
        pack_w_k<<<grid, (CoutPad < 256) ? CoutPad : 256>>>(w, outp, Cin, Cout, CoutPad);
    };
    pack(conv1_w,  wp1,    4,   16,   16,   16);
    pack(conv2_w,  wp2,   64,   64,   64,   64);
    pack(conv3_w,  wp3,  256,  256,  256,  256);
    pack(conv4_w,  wp4, 1024, 1024, 1024, 1024);
    pack(convd4_w, wpd4, 512,  512,  256,  256);
    pack(convd3_w, wpd3, 128,  128,   64,   64);
    pack(convd2_w, wpd2,  32,   32,   16,   16);
    pack(convd1_w, wpd1,  16,   16,    4,   16);

    // --- encoder ---
    tot = B * 1 * 256 * 256;
    wt_k<<<(tot + 255) / 256, 256>>>(x, 1, 256, 256, nullptr, w1h, tot);

    // conv1: 4->16 @256²  -> c1 fp32 + cat2h g0..7
    conv_mma16_k<<<dim3(256, 1, 8), 128>>>(w1h, 2, 2, 1, wp1, 16, conv1_b,
                                           c1, 16, cat2h, 16, 0, 256, 256, 16, 1);

    tot = B * 16 * 128 * 128;
    wt_k<<<(tot + 255) / 256, 256>>>(c1, 16, 128, 128, nullptr, w2h, tot);

    // conv2: 64->64 @128² -> c2 fp32 + cat3h g0..31
    conv_mma_pipe_k<64><<<dim3(64, 1, 8), 256, SMEM64>>>(
        w2h, 32, 4, wp2, 64, conv2_b, c2, 64, cat3h, 64, 0, nullptr, 0, 128, 128, 1);

    tot = B * 64 * 64 * 64;
    wt_k<<<(tot + 255) / 256, 256>>>(c2, 64, 64, 64, nullptr, w3h, tot);

    // conv3: 256->256 @64² -> c3 fp32 + cat4h g0..127
    conv_mma_pipe_k<128><<<dim3(16, 2, 8), 512, SMEM128>>>(
        w3h, 128, 16, wp3, 256, conv3_b, c3, 256, cat4h, 256, 0, nullptr, 0, 64, 64, 1);

    tot = B * 256 * 32 * 32;
    wt_k<<<(tot + 255) / 256, 256>>>(c3, 256, 32, 32, w4, w4h, tot);

    // --- bottleneck: conv4 x3 (1024->1024 @32²) ---
    conv_mma_pipe_k<128><<<dim3(4, 8, 8), 512, SMEM128>>>(
        w4h, 512, 64, wp4, 1024, conv4_b, nullptr, 0, c4h, 512, 0, nullptr, 0, 32, 32, 1);
    conv_mma_pipe_k<128><<<dim3(4, 8, 8), 512, SMEM128>>>(
        c4h, 512, 64, wp4, 1024, conv4_b, nullptr, 0, c5h, 512, 0, nullptr, 0, 32, 32, 1);
    conv_mma_pipe_k<128><<<dim3(4, 8, 8), 512, SMEM128>>>(
        c5h, 512, 64, wp4, 1024, conv4_b, ic4, 1024, nullptr, 0, 0, w4, 1024, 32, 32, 1);

    // --- decoder ---
    tot = B * 128 * 32 * 32;   // iwt(ic4) -> cat4h g128..255
    iwt_h2_k<<<(tot + 255) / 256, 256>>>(ic4, 128, 32, 32, cat4h, 256, 128, tot);

    // convd4: 512->256 @64² -> ic3 fp32
    conv_mma_pipe_k<128><<<dim3(16, 2, 8), 512, SMEM128>>>(
        cat4h, 256, 32, wpd4, 256, convd4_b, ic3, 256, nullptr, 0, 0, nullptr, 0, 64, 64, 1);

    tot = B * 32 * 64 * 64;    // iwt(ic3) -> cat3h g32..63
    iwt_h2_k<<<(tot + 255) / 256, 256>>>(ic3, 32, 64, 64, cat3h, 64, 32, tot);

    // convd3: 128->64 @128² -> ic2 fp32
    conv_mma_pipe_k<64><<<dim3(64, 1, 8), 256, SMEM64>>>(
        cat3h, 64, 8, wpd3, 64, convd3_b, ic2, 64, nullptr, 0, 0, nullptr, 0, 128, 128, 1);

    tot = B * 8 * 128 * 128;   // iwt(ic2) -> cat2h g8..15
    iwt_h2_k<<<(tot + 255) / 256, 256>>>(ic2, 8, 128, 128, cat2h, 16, 8, tot);

    // convd2: 32->16 @256² -> ic1h only
    conv_mma16_k<<<dim3(256, 1, 8), 128>>>(cat2h, 16, 16, 2, wpd2, 16, convd2_b,
                                           nullptr, 0, ic1h, 8, 0, 256, 256, 16, 1);

    // convd1: 16->4 @256² -> iw1 fp32
    conv_mma16_k<<<dim3(256, 1, 8), 128>>>(ic1h, 8, 8, 1, wpd1, 16, convd1_b,
                                           iw1, 4, nullptr, 0, 0, 256, 256, 4, 1);

    tot = B * 256 * 256;       // sigmoid(iwt(iw1)) -> out
    iwt_sig_k<<<(tot + 255) / 256, 256>>>(iw1, 256, 256, out, tot);

    (void)in_sizes; (void)n_in; (void)out_size;
}

// round 7
// speedup vs baseline: 4.0656x; 1.2164x over previous
#include <cuda_runtime.h>
#include <cuda_fp16.h>

// ---------------------------------------------------------------------------
// helpers
// ---------------------------------------------------------------------------
__device__ __forceinline__ unsigned h2bits(float a, float b) {
    __half2 h = __floats2half2_rn(a, b);
    return *reinterpret_cast<unsigned*>(&h);
}

__device__ __forceinline__ void mma16(float d[4], const unsigned a[4],
                                      unsigned b0, unsigned b1) {
    asm("mma.sync.aligned.m16n8k16.row.col.f32.f16.f16.f32 "
        "{%0,%1,%2,%3},{%4,%5,%6,%7},{%8,%9},{%0,%1,%2,%3};"
        : "+f"(d[0]), "+f"(d[1]), "+f"(d[2]), "+f"(d[3])
        : "r"(a[0]), "r"(a[1]), "r"(a[2]), "r"(a[3]), "r"(b0), "r"(b1));
}

__device__ __forceinline__ unsigned smem_u32(const void* p) {
    return (unsigned)__cvta_generic_to_shared(p);
}
// 16B cp.async; sz=0 -> zero-fill destination
__device__ __forceinline__ void cp16z(unsigned dst, const void* src, bool ok) {
    int sz = ok ? 16 : 0;
    asm volatile("cp.async.cg.shared.global [%0], [%1], 16, %2;"
                 :: "r"(dst), "l"(src), "r"(sz));
}
__device__ __forceinline__ void cp16(unsigned dst, const void* src) {
    asm volatile("cp.async.cg.shared.global [%0], [%1], 16;" :: "r"(dst), "l"(src));
}
__device__ __forceinline__ void cp_commit() { asm volatile("cp.async.commit_group;"); }
__device__ __forceinline__ void cp_wait1() { asm volatile("cp.async.wait_group 1;"); }
__device__ __forceinline__ void cp_wait0() { asm volatile("cp.async.wait_group 0;"); }

// ---------------------------------------------------------------------------
// Scratch (device globals; allocation-free)
// ---------------------------------------------------------------------------
__device__ float g_c1 [ 8388608];  // [8,  16,256,256]
__device__ float g_c2 [ 8388608];  // [8,  64,128,128]
__device__ float g_c3 [ 8388608];  // [8, 256, 64, 64]
__device__ float g_w4 [ 8388608];  // [8,1024, 32, 32]  (residual addend)
__device__ float g_ic4[ 8388608];  // [8,1024, 32, 32]
__device__ float g_ic3[ 8388608];  // [8, 256, 64, 64]
__device__ float g_ic2[ 8388608];  // [8,  64,128,128]
__device__ float g_iw1[ 2097152];  // [8,   4,256,256]

// half2 channel-pair-packed activations
__device__ unsigned g_w1h  [ 1048576];
__device__ unsigned g_cat2h[ 8388608]; // c1 g0..7 | iwt(ic2) g8..15
__device__ unsigned g_w2h  [ 4194304];
__device__ unsigned g_cat3h[ 8388608]; // c2 g0..31 | iwt(ic3) g32..63
__device__ unsigned g_w3h  [ 4194304];
__device__ unsigned g_cat4h[ 8388608]; // c3 g0..127 | iwt(ic4) g128..255
__device__ unsigned g_w4h  [ 4194304];
__device__ unsigned g_c4h  [ 4194304];
__device__ unsigned g_c5h  [ 4194304];
__device__ unsigned g_ic1h [ 4194304];

// packed weights: [(CinPad/2)][9][CoutPad] half2 over (2ci,2ci+1)
__device__ unsigned g_wp1 [   1152];
__device__ unsigned g_wp2 [  18432];
__device__ unsigned g_wp3 [ 294912];
__device__ unsigned g_wp4 [4718592];
__device__ unsigned g_wpd4[ 589824];
__device__ unsigned g_wpd3[  36864];
__device__ unsigned g_wpd2[   2304];
__device__ unsigned g_wpd1[   1152];

// ---------------------------------------------------------------------------
// weight packing
// ---------------------------------------------------------------------------
__global__ void pack_w_k(const float* __restrict__ w, unsigned* __restrict__ out,
                         int Cin, int Cout, int CoutPad) {
    int co  = blockIdx.x * blockDim.x + threadIdx.x;
    if (co >= CoutPad) return;
    int j   = blockIdx.y;
    int ci2 = blockIdx.z;
    float v0 = 0.f, v1 = 0.f;
    if (co < Cout) {
        int c0 = 2 * ci2, c1 = 2 * ci2 + 1;
        if (c0 < Cin) v0 = w[((long long)co * Cin + c0) * 9 + j];
        if (c1 < Cin) v1 = w[((long long)co * Cin + c1) * 9 + j];
    }
    out[((long long)ci2 * 9 + j) * CoutPad + co] = h2bits(v0, v1);
}

// ---------------------------------------------------------------------------
// Haar wavelet forward
// ---------------------------------------------------------------------------
__global__ void wt_k(const float* __restrict__ in, int C, int Ho, int Wo,
                     float* __restrict__ out32, unsigned* __restrict__ outH2,
                     int total) {
    int idx = blockIdx.x * blockDim.x + threadIdx.x;
    if (idx >= total) return;
    int wo = idx % Wo; int t = idx / Wo;
    int ho = t % Ho;  t /= Ho;
    int c  = t % C;   int b = t / C;
    int Wi = 2 * Wo;
    const float* p = in + (((long long)b * C + c) * (2 * Ho) + 2 * ho) * Wi + 2 * wo;
    float x00 = p[0], x01 = p[1], x10 = p[Wi], x11 = p[Wi + 1];
    float y0 = 0.25f * (x00 + x01 + x10 + x11);
    float y1 = 0.25f * (x00 + x01 - x10 - x11) + 0.5f;
    float y2 = 0.25f * (x00 - x01 + x10 - x11) + 0.5f;
    float y3 = 0.25f * (x00 - x01 - x10 + x11) + 0.5f;
    long long s = (long long)Ho * Wo;
    if (out32) {
        long long ob = (((long long)b * (4 * C) + 4 * c) * Ho + ho) * Wo + wo;
        out32[ob] = y0; out32[ob + s] = y1; out32[ob + 2 * s] = y2; out32[ob + 3 * s] = y3;
    }
    long long hb = (((long long)b * (2 * C) + 2 * c) * Ho + ho) * Wo + wo;
    outH2[hb]     = h2bits(y0, y1);
    outH2[hb + s] = h2bits(y2, y3);
}

// ---------------------------------------------------------------------------
// Haar inverse, channel-pair: fp32 [B,8*pairs,H,W] -> h2 slice of [B,gTot,2H,2W]
// ---------------------------------------------------------------------------
__global__ void iwt_h2_k(const float* __restrict__ in, int pairs, int H, int W,
                         unsigned* __restrict__ outH2, int gTot, int gOff, int total) {
    int idx = blockIdx.x * blockDim.x + threadIdx.x;
    if (idx >= total) return;
    int w = idx % W; int t = idx / W;
    int h = t % H;  t /= H;
    int g = t % pairs; int b = t / pairs;
    long long s = (long long)H * W;
    float x00[2], x01[2], x10[2], x11[2];
#pragma unroll
    for (int cc = 0; cc < 2; cc++) {
        int c = 2 * g + cc;
        long long ib = (((long long)b * (8 * pairs) + 4 * c) * H + h) * W + w;
        float y0 = in[ib];
        float t1 = 2.f * in[ib + s]     - 1.f;
        float t2 = 2.f * in[ib + 2 * s] - 1.f;
        float t3 = 2.f * in[ib + 3 * s] - 1.f;
        x00[cc] = y0 + 0.5f * ( t1 + t2 + t3);
        x01[cc] = y0 + 0.5f * ( t1 - t2 - t3);
        x10[cc] = y0 + 0.5f * (-t1 + t2 - t3);
        x11[cc] = y0 + 0.5f * (-t1 - t2 + t3);
    }
    int W2 = 2 * W;
    long long ob = (((long long)b * gTot + gOff + g) * (2 * H) + 2 * h) * W2 + 2 * w;
    uint2 r0, r1;
    r0.x = h2bits(x00[0], x00[1]); r0.y = h2bits(x01[0], x01[1]);
    r1.x = h2bits(x10[0], x10[1]); r1.y = h2bits(x11[0], x11[1]);
    *reinterpret_cast<uint2*>(outH2 + ob)      = r0;
    *reinterpret_cast<uint2*>(outH2 + ob + W2) = r1;
}

// ---------------------------------------------------------------------------
// Final Haar inverse (C=1) + sigmoid, fp32 out
// ---------------------------------------------------------------------------
__global__ void iwt_sig_k(const float* __restrict__ in, int H, int W,
                          float* __restrict__ out, int total) {
    int idx = blockIdx.x * blockDim.x + threadIdx.x;
    if (idx >= total) return;
    int w = idx % W; int t = idx / W;
    int h = t % H;  int b = t / H;
    long long s = (long long)H * W;
    long long ib = (((long long)b * 4) * H + h) * W + w;
    float y0 = in[ib];
    float t1 = 2.f * in[ib + s]     - 1.f;
    float t2 = 2.f * in[ib + 2 * s] - 1.f;
    float t3 = 2.f * in[ib + 3 * s] - 1.f;
    float x00 = y0 + 0.5f * ( t1 + t2 + t3);
    float x01 = y0 + 0.5f * ( t1 - t2 - t3);
    float x10 = y0 + 0.5f * (-t1 + t2 - t3);
    float x11 = y0 + 0.5f * (-t1 - t2 + t3);
    x00 = 1.f / (1.f + expf(-x00));
    x01 = 1.f / (1.f + expf(-x01));
    x10 = 1.f / (1.f + expf(-x10));
    x11 = 1.f / (1.f + expf(-x11));
    int W2 = 2 * W;
    float* o = out + ((long long)b * (2 * H) + 2 * h) * W2 + 2 * w;
    o[0] = x00; o[1] = x01; o[W2] = x10; o[W2 + 1] = x11;
}

// ---------------------------------------------------------------------------
// Pipelined fp16 mma implicit-GEMM 3x3 conv (pad 1), cp.async double buffered.
// COTILE=64, 256 thr = 2 M-warps x 4 N-warps, 2 blocks/SM.
// Patch layout: [g][18 rows][28 words]; row holds gx in [tx0-4, tx0+20),
// so logical gx0-1+k lives at word k+3. g-stride 504 ≡ 24 (mod 32) and
// tig*24+gid is a permutation -> conflict-free LDS.
// Staging is pure 16B cp.async (chunks provably all-in/all-out at edges).
// ---------------------------------------------------------------------------
__global__ __launch_bounds__(256, 2)
void conv_mma_pipe_k(const unsigned* __restrict__ inH2, int gInTot, int kTiles,
                     const unsigned* __restrict__ wp, int coutPad,
                     const float* __restrict__ bias,
                     float* __restrict__ out32, int out32Ctot,
                     unsigned* __restrict__ outH2, int gOutTot, int gOutOff,
                     const float* __restrict__ addend, int addCtot,
                     int H, int W, int lrelu) {
    constexpr int NTHREADS = 256;
    constexpr int PW      = 28;            // patch row words
    constexpr int GSTRIDE = 18 * PW;       // 504
    constexpr int PATCH_W = 8 * GSTRIDE;   // 4032 words
    constexpr int WROW    = 72;            // 64 + 8, conflict-free
    constexpr int WSM_W   = 72 * WROW;     // 5184 words
    constexpr int STAGE   = PATCH_W + WSM_W;   // 9216 words
    extern __shared__ unsigned sm[];

    const int tid  = threadIdx.x;
    const int lane = tid & 31;
    const int warp = tid >> 5;
    const int gid  = lane >> 2;
    const int tig  = lane & 3;
    const int mwarp = warp & 1;
    const int nwarp = warp >> 1;

    const int tilesX = W >> 4;
    const int tx0 = (blockIdx.x % tilesX) << 4;
    const int ty0 = (blockIdx.x / tilesX) << 4;
    const int co0 = blockIdx.y << 6;
    const int b   = blockIdx.z;
    const int HW  = H * W;
    const long long inBase = (long long)b * gInTot * HW;

    float acc[2][8][4];
#pragma unroll
    for (int mt = 0; mt < 2; mt++)
#pragma unroll
        for (int nt = 0; nt < 8; nt++)
#pragma unroll
            for (int r = 0; r < 4; r++) acc[mt][nt][r] = 0.f;

    auto stage = [&](int kt, int buf) {
        const int g0 = kt * 8;
        unsigned pb = smem_u32(sm + buf * STAGE);
        unsigned wb = pb + PATCH_W * 4;
        // patch: 8 g x 18 rows x 6 x 16B chunks
        for (int idx = tid; idx < 8 * 18 * 6; idx += NTHREADS) {
            int g = idx / 108;
            int rem = idx - g * 108;
            int r = rem / 6, c = rem - r * 6;
            int gy = ty0 - 1 + r;
            int gxs = tx0 - 4 + 4 * c;
            bool ok = (unsigned)gy < (unsigned)H && gxs >= 0 && (gxs + 4) <= W;
            const unsigned* src = inH2 + inBase + (long long)(g0 + g) * HW
                                  + (ok ? (gy * W + gxs) : 0);
            cp16z(pb + (unsigned)(g * GSTRIDE + r * PW + 4 * c) * 4u, src, ok);
        }
        // weights: 72 rows x 16 x 16B chunks
        for (int idx = tid; idx < 72 * 16; idx += NTHREADS) {
            int row = idx >> 4;          // j*8 + kg
            int cw  = idx & 15;
            int j   = row >> 3;
            int kg  = row & 7;
            const unsigned* src = wp + ((long long)(g0 + kg) * 9 + j) * coutPad
                                  + co0 + cw * 4;
            cp16(wb + (unsigned)(row * WROW + cw * 4) * 4u, src);
        }
    };

    auto compute = [&](int buf) {
        const unsigned* pbuf = sm + buf * STAGE;
        const unsigned* wbuf = pbuf + PATCH_W;
#pragma unroll
        for (int j = 0; j < 9; j++) {
            const int dy = j / 3, dx = j - 3 * dy;
            unsigned a[2][4];
#pragma unroll
            for (int mt = 0; mt < 2; mt++) {
                int cl = mwarp * 32 + mt * 16 + gid;
                a[mt][0] = wbuf[(j * 8 + tig) * WROW + cl];
                a[mt][1] = wbuf[(j * 8 + tig) * WROW + cl + 8];
                a[mt][2] = wbuf[(j * 8 + tig + 4) * WROW + cl];
                a[mt][3] = wbuf[(j * 8 + tig + 4) * WROW + cl + 8];
            }
            const unsigned* pb0 = pbuf + tig * GSTRIDE + dy * PW + dx + gid + 3;
            const unsigned* pb1 = pbuf + (tig + 4) * GSTRIDE + dy * PW + dx + gid + 3;
#pragma unroll
            for (int nt = 0; nt < 8; nt++) {
                int pix = nwarp * 64 + nt * 8;
                int off = (pix >> 4) * PW + (pix & 15);
                unsigned b0 = pb0[off];
                unsigned b1 = pb1[off];
                mma16(acc[0][nt], a[0], b0, b1);
                mma16(acc[1][nt], a[1], b0, b1);
            }
        }
    };

    stage(0, 0);
    cp_commit();
    for (int kt = 0; kt < kTiles; kt++) {
        int cur = kt & 1;
        if (kt + 1 < kTiles) {
            stage(kt + 1, cur ^ 1);
            cp_commit();
            cp_wait1();
        } else {
            cp_wait0();
        }
        __syncthreads();
        compute(cur);
        __syncthreads();
    }

    // epilogue
#pragma unroll
    for (int mt = 0; mt < 2; mt++) {
#pragma unroll
        for (int rr = 0; rr < 2; rr++) {
            int co = co0 + mwarp * 32 + mt * 16 + rr * 8 + gid;
            float bv = bias[co];
#pragma unroll
            for (int nt = 0; nt < 8; nt++) {
                int pix = nwarp * 64 + nt * 8;
                int oy = ty0 + (pix >> 4);
                int ox = tx0 + (pix & 15) + 2 * tig;
                float v0 = acc[mt][nt][rr * 2]     + bv;
                float v1 = acc[mt][nt][rr * 2 + 1] + bv;
                if (addend) {
                    const float* ap = addend + (((long long)b * addCtot + co) * H + oy) * W + ox;
                    v0 += ap[0]; v1 += ap[1];
                }
                if (lrelu) {
                    v0 = v0 > 0.f ? v0 : 0.2f * v0;
                    v1 = v1 > 0.f ? v1 : 0.2f * v1;
                }
                if (out32) {
                    float2 val = make_float2(v0, v1);
                    *reinterpret_cast<float2*>(
                        out32 + (((long long)b * out32Ctot + co) * H + oy) * W + ox) = val;
                }
                if (outH2) {
                    float s0 = __shfl_xor_sync(0xffffffffu, v0, 4);
                    float s1 = __shfl_xor_sync(0xffffffffu, v1, 4);
                    if ((gid & 1) == 0) {
                        uint2 wv;
                        wv.x = h2bits(v0, s0);
                        wv.y = h2bits(v1, s1);
                        *reinterpret_cast<uint2*>(
                            outH2 + (((long long)b * gOutTot + gOutOff + (co >> 1)) * H + oy) * W + ox) = wv;
                    }
                }
            }
        }
    }
}

// ---------------------------------------------------------------------------
// Small-layer fp16 mma conv (COTILE=16, non-pipelined, handles padded K)
// ---------------------------------------------------------------------------
__global__ __launch_bounds__(128, 4)
void conv_mma16_k(const unsigned* __restrict__ inH2, int gInTot, int gInAct, int kTiles,
                  const unsigned* __restrict__ wp, int coutPad,
                  const float* __restrict__ bias,
                  float* __restrict__ out32, int out32Ctot,
                  unsigned* __restrict__ outH2, int gOutTot, int gOutOff,
                  int H, int W, int coutAct, int lrelu) {
    constexpr int COTILE = 16;
    __shared__ unsigned patch[8][18][20];
    __shared__ unsigned wsm[9][8][COTILE + 8];

    const int tid  = threadIdx.x;
    const int lane = tid & 31;
    const int warp = tid >> 5;
    const int gid  = lane >> 2;
    const int tig  = lane & 3;
    const int nwarp = warp;

    const int tilesX = W >> 4;
    const int tx0 = (blockIdx.x % tilesX) << 4;
    const int ty0 = (blockIdx.x / tilesX) << 4;
    const int co0 = blockIdx.y * COTILE;
    const int b   = blockIdx.z;
    const int HW  = H * W;

    float acc[8][4];
#pragma unroll
    for (int nt = 0; nt < 8; nt++)
#pragma unroll
        for (int r = 0; r < 4; r++) acc[nt][r] = 0.f;

    const long long inBase = (long long)b * gInTot * HW;

    for (int kt = 0; kt < kTiles; kt++) {
        const int g0 = kt * 8;
        __syncthreads();
        for (int idx = tid; idx < 8 * 324; idx += 128) {
            int g = idx / 324;
            int rem = idx - g * 324;
            int r = rem / 18, c = rem - r * 18;
            int gy = ty0 - 1 + r, gx = tx0 - 1 + c;
            unsigned v = 0;
            int absG = g0 + g;
            if (absG < gInAct && (unsigned)gy < (unsigned)H && (unsigned)gx < (unsigned)W)
                v = inH2[inBase + (long long)absG * HW + gy * W + gx];
            patch[g][r][c] = v;
        }
        for (int idx = tid; idx < 9 * 8 * (COTILE / 2); idx += 128) {
            int co2 = idx % (COTILE / 2);
            int t   = idx / (COTILE / 2);
            int kg  = t % 8;
            int j   = t / 8;
            uint2 v = *reinterpret_cast<const uint2*>(
                wp + ((long long)(g0 + kg) * 9 + j) * coutPad + co0 + 2 * co2);
            *reinterpret_cast<uint2*>(&wsm[j][kg][2 * co2]) = v;
        }
        __syncthreads();

#pragma unroll
        for (int j = 0; j < 9; j++) {
            const int dy = j / 3, dx = j - 3 * dy;
            unsigned a[4];
            a[0] = wsm[j][tig][gid];
            a[1] = wsm[j][tig][gid + 8];
            a[2] = wsm[j][tig + 4][gid];
            a[3] = wsm[j][tig + 4][gid + 8];
            const unsigned* pb0 = &patch[tig][dy][dx + gid];
            const unsigned* pb1 = &patch[tig + 4][dy][dx + gid];
#pragma unroll
            for (int nt = 0; nt < 8; nt++) {
                int pix = nwarp * 64 + nt * 8;
                int off = (pix >> 4) * 20 + (pix & 15);
                mma16(acc[nt], a, pb0[off], pb1[off]);
            }
        }
    }

#pragma unroll
    for (int rr = 0; rr < 2; rr++) {
        int co = co0 + rr * 8 + gid;
        float bv = (co < coutAct) ? bias[co] : 0.f;
#pragma unroll
        for (int nt = 0; nt < 8; nt++) {
            int pix = nwarp * 64 + nt * 8;
            int oy = ty0 + (pix >> 4);
            int ox = tx0 + (pix & 15) + 2 * tig;
            float v0 = acc[nt][rr * 2]     + bv;
            float v1 = acc[nt][rr * 2 + 1] + bv;
            if (lrelu) {
                v0 = v0 > 0.f ? v0 : 0.2f * v0;
                v1 = v1 > 0.f ? v1 : 0.2f * v1;
            }
            if (out32 && co < coutAct) {
                float2 val = make_float2(v0, v1);
                *reinterpret_cast<float2*>(
                    out32 + (((long long)b * out32Ctot + co) * H + oy) * W + ox) = val;
            }
            if (outH2) {
                float s0 = __shfl_xor_sync(0xffffffffu, v0, 4);
                float s1 = __shfl_xor_sync(0xffffffffu, v1, 4);
                if ((gid & 1) == 0) {
                    uint2 wv;
                    wv.x = h2bits(v0, s0);
                    wv.y = h2bits(v1, s1);
                    *reinterpret_cast<uint2*>(
                        outH2 + (((long long)b * gOutTot + gOutOff + (co >> 1)) * H + oy) * W + ox) = wv;
                }
            }
        }
    }
}

// ---------------------------------------------------------------------------
// Orchestration
// ---------------------------------------------------------------------------
extern "C" void kernel_launch(void* const* d_in, const int* in_sizes, int n_in,
                              void* d_out, int out_size) {
    const float* x        = (const float*)d_in[0];
    const float* conv1_w  = (const float*)d_in[1];
    const float* conv1_b  = (const float*)d_in[2];
    const float* conv2_w  = (const float*)d_in[3];
    const float* conv2_b  = (const float*)d_in[4];
    const float* conv3_w  = (const float*)d_in[5];
    const float* conv3_b  = (const float*)d_in[6];
    const float* conv4_w  = (const float*)d_in[7];
    const float* conv4_b  = (const float*)d_in[8];
    const float* convd1_w = (const float*)d_in[9];
    const float* convd1_b = (const float*)d_in[10];
    const float* convd2_w = (const float*)d_in[11];
    const float* convd2_b = (const float*)d_in[12];
    const float* convd3_w = (const float*)d_in[13];
    const float* convd3_b = (const float*)d_in[14];
    const float* convd4_w = (const float*)d_in[15];
    const float* convd4_b = (const float*)d_in[16];
    float* out = (float*)d_out;

    float *c1, *c2, *c3, *w4, *ic4, *ic3, *ic2, *iw1;
    unsigned *w1h, *cat2h, *w2h, *cat3h, *w3h, *cat4h, *w4h, *c4h, *c5h, *ic1h;
    unsigned *wp1, *wp2, *wp3, *wp4, *wpd4, *wpd3, *wpd2, *wpd1;
    cudaGetSymbolAddress((void**)&c1,  g_c1);
    cudaGetSymbolAddress((void**)&c2,  g_c2);
    cudaGetSymbolAddress((void**)&c3,  g_c3);
    cudaGetSymbolAddress((void**)&w4,  g_w4);
    cudaGetSymbolAddress((void**)&ic4, g_ic4);
    cudaGetSymbolAddress((void**)&ic3, g_ic3);
    cudaGetSymbolAddress((void**)&ic2, g_ic2);
    cudaGetSymbolAddress((void**)&iw1, g_iw1);
    cudaGetSymbolAddress((void**)&w1h,  g_w1h);
    cudaGetSymbolAddress((void**)&cat2h, g_cat2h);
    cudaGetSymbolAddress((void**)&w2h,  g_w2h);
    cudaGetSymbolAddress((void**)&cat3h, g_cat3h);
    cudaGetSymbolAddress((void**)&w3h,  g_w3h);
    cudaGetSymbolAddress((void**)&cat4h, g_cat4h);
    cudaGetSymbolAddress((void**)&w4h,  g_w4h);
    cudaGetSymbolAddress((void**)&c4h,  g_c4h);
    cudaGetSymbolAddress((void**)&c5h,  g_c5h);
    cudaGetSymbolAddress((void**)&ic1h, g_ic1h);
    cudaGetSymbolAddress((void**)&wp1,  g_wp1);
    cudaGetSymbolAddress((void**)&wp2,  g_wp2);
    cudaGetSymbolAddress((void**)&wp3,  g_wp3);
    cudaGetSymbolAddress((void**)&wp4,  g_wp4);
    cudaGetSymbolAddress((void**)&wpd4, g_wpd4);
    cudaGetSymbolAddress((void**)&wpd3, g_wpd3);
    cudaGetSymbolAddress((void**)&wpd2, g_wpd2);
    cudaGetSymbolAddress((void**)&wpd1, g_wpd1);

    const int SMEMP = 2 * (8 * 504 + 72 * 72) * 4;  // 73728 B
    static bool attrSet = false;
    if (!attrSet) {
        cudaFuncSetAttribute(conv_mma_pipe_k,
                             cudaFuncAttributeMaxDynamicSharedMemorySize, SMEMP);
        attrSet = true;
    }

    const int B = 8;
    int tot;

    // --- pack all weights to half2 ---
    auto pack = [](const float* w, unsigned* outp, int Cin, int CinPad, int Cout, int CoutPad) {
        dim3 grid((CoutPad + 255) / 256, 9, CinPad / 2);
        pack_w_k<<<grid, (CoutPad < 256) ? CoutPad : 256>>>(w, outp, Cin, Cout, CoutPad);
    };
    pack(conv1_w,  wp1,    4,   16,   16,   16);
    pack(conv2_w,  wp2,   64,   64,   64,   64);
    pack(conv3_w,  wp3,  256,  256,  256,  256);
    pack(conv4_w,  wp4, 1024, 1024, 1024, 1024);
    pack(convd4_w, wpd4, 512,  512,  256,  256);
    pack(convd3_w, wpd3, 128,  128,   64,   64);
    pack(convd2_w, wpd2,  32,   32,   16,   16);
    pack(convd1_w, wpd1,  16,   16,    4,   16);

    // --- encoder ---
    tot = B * 1 * 256 * 256;
    wt_k<<<(tot + 255) / 256, 256>>>(x, 1, 256, 256, nullptr, w1h, tot);

    // conv1: 4->16 @256²  -> c1 fp32 + cat2h g0..7
    conv_mma16_k<<<dim3(256, 1, 8), 128>>>(w1h, 2, 2, 1, wp1, 16, conv1_b,
                                           c1, 16, cat2h, 16, 0, 256, 256, 16, 1);

    tot = B * 16 * 128 * 128;
    wt_k<<<(tot + 255) / 256, 256>>>(c1, 16, 128, 128, nullptr, w2h, tot);

    // conv2: 64->64 @128² -> c2 fp32 + cat3h g0..31
    conv_mma_pipe_k<<<dim3(64, 1, 8), 256, SMEMP>>>(
        w2h, 32, 4, wp2, 64, conv2_b, c2, 64, cat3h, 64, 0, nullptr, 0, 128, 128, 1);

    tot = B * 64 * 64 * 64;
    wt_k<<<(tot + 255) / 256, 256>>>(c2, 64, 64, 64, nullptr, w3h, tot);

    // conv3: 256->256 @64² -> c3 fp32 + cat4h g0..127
    conv_mma_pipe_k<<<dim3(16, 4, 8), 256, SMEMP>>>(
        w3h, 128, 16, wp3, 256, conv3_b, c3, 256, cat4h, 256, 0, nullptr, 0, 64, 64, 1);

    tot = B * 256 * 32 * 32;
    wt_k<<<(tot + 255) / 256, 256>>>(c3, 256, 32, 32, w4, w4h, tot);

    // --- bottleneck: conv4 x3 (1024->1024 @32²) ---
    conv_mma_pipe_k<<<dim3(4, 16, 8), 256, SMEMP>>>(
        w4h, 512, 64, wp4, 1024, conv4_b, nullptr, 0, c4h, 512, 0, nullptr, 0, 32, 32, 1);
    conv_mma_pipe_k<<<dim3(4, 16, 8), 256, SMEMP>>>(
        c4h, 512, 64, wp4, 1024, conv4_b, nullptr, 0, c5h, 512, 0, nullptr, 0, 32, 32, 1);
    conv_mma_pipe_k<<<dim3(4, 16, 8), 256, SMEMP>>>(
        c5h, 512, 64, wp4, 1024, conv4_b, ic4, 1024, nullptr, 0, 0, w4, 1024, 32, 32, 1);

    // --- decoder ---
    tot = B * 128 * 32 * 32;   // iwt(ic4) -> cat4h g128..255
    iwt_h2_k<<<(tot + 255) / 256, 256>>>(ic4, 128, 32, 32, cat4h, 256, 128, tot);

    // convd4: 512->256 @64² -> ic3 fp32
    conv_mma_pipe_k<<<dim3(16, 4, 8), 256, SMEMP>>>(
        cat4h, 256, 32, wpd4, 256, convd4_b, ic3, 256, nullptr, 0, 0, nullptr, 0, 64, 64, 1);

    tot = B * 32 * 64 * 64;    // iwt(ic3) -> cat3h g32..63
    iwt_h2_k<<<(tot + 255) / 256, 256>>>(ic3, 32, 64, 64, cat3h, 64, 32, tot);

    // convd3: 128->64 @128² -> ic2 fp32
    conv_mma_pipe_k<<<dim3(64, 1, 8), 256, SMEMP>>>(
        cat3h, 64, 8, wpd3, 64, convd3_b, ic2, 64, nullptr, 0, 0, nullptr, 0, 128, 128, 1);

    tot = B * 8 * 128 * 128;   // iwt(ic2) -> cat2h g8..15
    iwt_h2_k<<<(tot + 255) / 256, 256>>>(ic2, 8, 128, 128, cat2h, 16, 8, tot);

    // convd2: 32->16 @256² -> ic1h only
    conv_mma16_k<<<dim3(256, 1, 8), 128>>>(cat2h, 16, 16, 2, wpd2, 16, convd2_b,
                                           nullptr, 0, ic1h, 8, 0, 256, 256, 16, 1);

    // convd1: 16->4 @256² -> iw1 fp32
    conv_mma16_k<<<dim3(256, 1, 8), 128>>>(ic1h, 8, 8, 1, wpd1, 16, convd1_b,
                                           iw1, 4, nullptr, 0, 0, 256, 256, 4, 1);

    tot = B * 256 * 256;       // sigmoid(iwt(iw1)) -> out
    iwt_sig_k<<<(tot + 255) / 256, 256>>>(iw1, 256, 256, out, tot);

    (void)in_sizes; (void)n_in; (void)out_size;
}

// round 9
// speedup vs baseline: 4.0946x; 1.0071x over previous
#include <cuda_runtime.h>
#include <cuda_fp16.h>

// ---------------------------------------------------------------------------
// helpers
// ---------------------------------------------------------------------------
__device__ __forceinline__ unsigned h2bits(float a, float b) {
    __half2 h = __floats2half2_rn(a, b);
    return *reinterpret_cast<unsigned*>(&h);
}
__device__ __forceinline__ float2 h2unpack(unsigned u) {
    return __half22float2(*reinterpret_cast<__half2*>(&u));
}

__device__ __forceinline__ void mma16(float d[4], const unsigned a[4],
                                      unsigned b0, unsigned b1) {
    asm("mma.sync.aligned.m16n8k16.row.col.f32.f16.f16.f32 "
        "{%0,%1,%2,%3},{%4,%5,%6,%7},{%8,%9},{%0,%1,%2,%3};"
        : "+f"(d[0]), "+f"(d[1]), "+f"(d[2]), "+f"(d[3])
        : "r"(a[0]), "r"(a[1]), "r"(a[2]), "r"(a[3]), "r"(b0), "r"(b1));
}

__device__ __forceinline__ unsigned smem_u32(const void* p) {
    return (unsigned)__cvta_generic_to_shared(p);
}
__device__ __forceinline__ void cp16z(unsigned dst, const void* src, bool ok) {
    int sz = ok ? 16 : 0;
    asm volatile("cp.async.cg.shared.global [%0], [%1], 16, %2;"
                 :: "r"(dst), "l"(src), "r"(sz));
}
__device__ __forceinline__ void cp16(unsigned dst, const void* src) {
    asm volatile("cp.async.cg.shared.global [%0], [%1], 16;" :: "r"(dst), "l"(src));
}
__device__ __forceinline__ void cp_commit() { asm volatile("cp.async.commit_group;"); }
__device__ __forceinline__ void cp_wait1() { asm volatile("cp.async.wait_group 1;"); }
__device__ __forceinline__ void cp_wait0() { asm volatile("cp.async.wait_group 0;"); }

// ---------------------------------------------------------------------------
// Scratch (device globals; allocation-free)
// ---------------------------------------------------------------------------
__device__ float g_w4 [ 8388608];  // [8,1024, 32, 32]  residual addend (fp32)
__device__ float g_iw1[ 2097152];  // [8,   4,256,256]  pre-sigmoid (fp32)

// half2 channel-pair-packed activations: word(b,g,y,x) = h2(ch 2g, ch 2g+1)
__device__ unsigned g_w1h  [ 1048576];
__device__ unsigned g_cat2h[ 8388608]; // c1 g0..7 | iwt(ic2) g8..15
__device__ unsigned g_w2h  [ 4194304];
__device__ unsigned g_cat3h[ 8388608]; // c2 g0..31 | iwt(ic3) g32..63
__device__ unsigned g_w3h  [ 4194304];
__device__ unsigned g_cat4h[ 8388608]; // c3 g0..127 | iwt(ic4) g128..255
__device__ unsigned g_w4h  [ 4194304];
__device__ unsigned g_c4h  [ 4194304];
__device__ unsigned g_c5h  [ 4194304];
__device__ unsigned g_ic4h [ 4194304]; // [8,512g,32,32]
__device__ unsigned g_ic3h [ 4194304]; // [8,128g,64,64]
__device__ unsigned g_ic2h [ 4194304]; // [8, 32g,128,128]
__device__ unsigned g_ic1h [ 4194304]; // [8,  8g,256,256]

// packed weights: [(CinPad/2)][9][CoutPad] half2 over (2ci,2ci+1)
__device__ unsigned g_wp1 [   1152];
__device__ unsigned g_wp2 [  18432];
__device__ unsigned g_wp3 [ 294912];
__device__ unsigned g_wp4 [4718592];
__device__ unsigned g_wpd4[ 589824];
__device__ unsigned g_wpd3[  36864];
__device__ unsigned g_wpd2[   2304];
__device__ unsigned g_wpd1[   1152];

// ---------------------------------------------------------------------------
// Coalesced weight packing via smem transpose.
// out[kj*CoutPad + co] = h2(w[co][2*ci2][j], w[co][2*ci2+1][j]), kj = ci2*9+j.
// ---------------------------------------------------------------------------
__global__ void pack_w_k(const float* __restrict__ w, unsigned* __restrict__ out,
                         int Cin, int Cout, int CoutPad, int K2) {
    __shared__ float sm[32][91];
    const int co0 = blockIdx.x * 32;
    const int kj0 = blockIdx.y * 32;
    const int ci2_lo = kj0 / 9;
    const int i_lo = ci2_lo * 18;
    const int Klen = Cin * 9;
    const int tid = threadIdx.y * 32 + threadIdx.x;

    for (int t = tid; t < 32 * 90; t += 256) {
        int r = t / 90, c = t - (t / 90) * 90;
        int co = co0 + r, i = i_lo + c;
        float v = 0.f;
        if (co < Cout && i < Klen) v = w[(long long)co * Klen + i];
        sm[r][c] = v;
    }
    __syncthreads();

    for (int t = tid; t < 32 * 32; t += 256) {
        int kr = t >> 5;
        int cl = t & 31;
        int kj = kj0 + kr;
        if (kj >= K2 || co0 + cl >= CoutPad) continue;   // <-- guard fixed
        int ci2 = kj / 9, j = kj - ci2 * 9;
        int ri = (ci2 - ci2_lo) * 18 + j;
        out[(long long)kj * CoutPad + co0 + cl] = h2bits(sm[cl][ri], sm[cl][ri + 9]);
    }
}

// ---------------------------------------------------------------------------
// Haar forward, fp32 input (layer 1 only, C=1)
// ---------------------------------------------------------------------------
__global__ void wt_k(const float* __restrict__ in, int C, int Ho, int Wo,
                     unsigned* __restrict__ outH2, int total) {
    int idx = blockIdx.x * blockDim.x + threadIdx.x;
    if (idx >= total) return;
    int wo = idx % Wo; int t = idx / Wo;
    int ho = t % Ho;  t /= Ho;
    int c  = t % C;   int b = t / C;
    int Wi = 2 * Wo;
    const float* p = in + (((long long)b * C + c) * (2 * Ho) + 2 * ho) * Wi + 2 * wo;
    float x00 = p[0], x01 = p[1], x10 = p[Wi], x11 = p[Wi + 1];
    float y0 = 0.25f * (x00 + x01 + x10 + x11);
    float y1 = 0.25f * (x00 + x01 - x10 - x11) + 0.5f;
    float y2 = 0.25f * (x00 - x01 + x10 - x11) + 0.5f;
    float y3 = 0.25f * (x00 - x01 - x10 + x11) + 0.5f;
    long long s = (long long)Ho * Wo;
    long long hb = (((long long)b * (2 * C) + 2 * c) * Ho + ho) * Wo + wo;
    outH2[hb]     = h2bits(y0, y1);
    outH2[hb + s] = h2bits(y2, y3);
}

// ---------------------------------------------------------------------------
// Haar forward, h2 input (channel pair g = channels 2g,2g+1).
// Optional fp32 out32 [B,4C,Ho,Wo] (residual addend for layer 4).
// ---------------------------------------------------------------------------
__global__ void wt_h2_k(const unsigned* __restrict__ in, int gInTot, int gInOff,
                        int Cg, int Ho, int Wo,
                        float* __restrict__ out32, int out32Ctot,
                        unsigned* __restrict__ outH2, int gOutTot, int total) {
    int idx = blockIdx.x * blockDim.x + threadIdx.x;
    if (idx >= total) return;
    int wo = idx % Wo; int t = idx / Wo;
    int ho = t % Ho;  t /= Ho;
    int g  = t % Cg;  int b = t / Cg;
    int Wi = 2 * Wo;
    const unsigned* p = in + (((long long)b * gInTot + gInOff + g) * (2 * Ho) + 2 * ho) * Wi + 2 * wo;
    float2 f00 = h2unpack(p[0]);
    float2 f01 = h2unpack(p[1]);
    float2 f10 = h2unpack(p[Wi]);
    float2 f11 = h2unpack(p[Wi + 1]);
    long long s = (long long)Ho * Wo;
#pragma unroll
    for (int cc = 0; cc < 2; cc++) {
        float x00 = cc ? f00.y : f00.x;
        float x01 = cc ? f01.y : f01.x;
        float x10 = cc ? f10.y : f10.x;
        float x11 = cc ? f11.y : f11.x;
        float y0 = 0.25f * (x00 + x01 + x10 + x11);
        float y1 = 0.25f * (x00 + x01 - x10 - x11) + 0.5f;
        float y2 = 0.25f * (x00 - x01 + x10 - x11) + 0.5f;
        float y3 = 0.25f * (x00 - x01 - x10 + x11) + 0.5f;
        long long hb = (((long long)b * gOutTot + 4 * g + 2 * cc) * Ho + ho) * Wo + wo;
        outH2[hb]     = h2bits(y0, y1);
        outH2[hb + s] = h2bits(y2, y3);
        if (out32) {
            int c = 2 * g + cc;
            long long ob = (((long long)b * out32Ctot + 4 * c) * Ho + ho) * Wo + wo;
            out32[ob]         = y0;
            out32[ob + s]     = y1;
            out32[ob + 2 * s] = y2;
            out32[ob + 3 * s] = y3;
        }
    }
}

// ---------------------------------------------------------------------------
// Haar inverse, h2 in / h2 out. Out pair g = out channels 2g,2g+1;
// reads input groups 4g..4g+3 (input has 4*pairs groups).
// ---------------------------------------------------------------------------
__global__ void iwt_h2_k(const unsigned* __restrict__ inH2, int pairs, int H, int W,
                         unsigned* __restrict__ outH2, int gTot, int gOff, int total) {
    int idx = blockIdx.x * blockDim.x + threadIdx.x;
    if (idx >= total) return;
    int w = idx % W; int t = idx / W;
    int h = t % H;  t /= H;
    int g = t % pairs; int b = t / pairs;
    long long s = (long long)H * W;
    long long base = (((long long)b * (4 * pairs) + 4 * g) * H + h) * W + w;
    float x00[2], x01[2], x10[2], x11[2];
#pragma unroll
    for (int cc = 0; cc < 2; cc++) {
        float2 fa = h2unpack(inH2[base + (2 * cc) * s]);      // (y0, y1)
        float2 fb = h2unpack(inH2[base + (2 * cc + 1) * s]);  // (y2, y3)
        float y0 = fa.x;
        float t1 = 2.f * fa.y - 1.f;
        float t2 = 2.f * fb.x - 1.f;
        float t3 = 2.f * fb.y - 1.f;
        x00[cc] = y0 + 0.5f * ( t1 + t2 + t3);
        x01[cc] = y0 + 0.5f * ( t1 - t2 - t3);
        x10[cc] = y0 + 0.5f * (-t1 + t2 - t3);
        x11[cc] = y0 + 0.5f * (-t1 - t2 + t3);
    }
    int W2 = 2 * W;
    long long ob = (((long long)b * gTot + gOff + g) * (2 * H) + 2 * h) * W2 + 2 * w;
    uint2 r0, r1;
    r0.x = h2bits(x00[0], x00[1]); r0.y = h2bits(x01[0], x01[1]);
    r1.x = h2bits(x10[0], x10[1]); r1.y = h2bits(x11[0], x11[1]);
    *reinterpret_cast<uint2*>(outH2 + ob)      = r0;
    *reinterpret_cast<uint2*>(outH2 + ob + W2) = r1;
}

// ---------------------------------------------------------------------------
// Final Haar inverse (C=1) + sigmoid, fp32 in/out
// ---------------------------------------------------------------------------
__global__ void iwt_sig_k(const float* __restrict__ in, int H, int W,
                          float* __restrict__ out, int total) {
    int idx = blockIdx.x * blockDim.x + threadIdx.x;
    if (idx >= total) return;
    int w = idx % W; int t = idx / W;
    int h = t % H;  int b = t / H;
    long long s = (long long)H * W;
    long long ib = (((long long)b * 4) * H + h) * W + w;
    float y0 = in[ib];
    float t1 = 2.f * in[ib + s]     - 1.f;
    float t2 = 2.f * in[ib + 2 * s] - 1.f;
    float t3 = 2.f * in[ib + 3 * s] - 1.f;
    float x00 = y0 + 0.5f * ( t1 + t2 + t3);
    float x01 = y0 + 0.5f * ( t1 - t2 - t3);
    float x10 = y0 + 0.5f * (-t1 + t2 - t3);
    float x11 = y0 + 0.5f * (-t1 - t2 + t3);
    x00 = 1.f / (1.f + expf(-x00));
    x01 = 1.f / (1.f + expf(-x01));
    x10 = 1.f / (1.f + expf(-x10));
    x11 = 1.f / (1.f + expf(-x11));
    int W2 = 2 * W;
    float* o = out + ((long long)b * (2 * H) + 2 * h) * W2 + 2 * w;
    o[0] = x00; o[1] = x01; o[W2] = x10; o[W2 + 1] = x11;
}

// ---------------------------------------------------------------------------
// Pipelined fp16 mma implicit-GEMM 3x3 conv (pad 1), cp.async double buffered.
// COTILE=64, 256 thr = 2 M-warps x 4 N-warps, 2 blocks/SM.
// ---------------------------------------------------------------------------
__global__ __launch_bounds__(256, 2)
void conv_mma_pipe_k(const unsigned* __restrict__ inH2, int gInTot, int kTiles,
                     const unsigned* __restrict__ wp, int coutPad,
                     const float* __restrict__ bias,
                     float* __restrict__ out32, int out32Ctot,
                     unsigned* __restrict__ outH2, int gOutTot, int gOutOff,
                     const float* __restrict__ addend, int addCtot,
                     int H, int W, int lrelu) {
    constexpr int NTHREADS = 256;
    constexpr int PW      = 28;
    constexpr int GSTRIDE = 18 * PW;       // 504
    constexpr int PATCH_W = 8 * GSTRIDE;   // 4032
    constexpr int WROW    = 72;
    constexpr int WSM_W   = 72 * WROW;     // 5184
    constexpr int STAGE   = PATCH_W + WSM_W;
    extern __shared__ unsigned sm[];

    const int tid  = threadIdx.x;
    const int lane = tid & 31;
    const int warp = tid >> 5;
    const int gid  = lane >> 2;
    const int tig  = lane & 3;
    const int mwarp = warp & 1;
    const int nwarp = warp >> 1;

    const int tilesX = W >> 4;
    const int tx0 = (blockIdx.x % tilesX) << 4;
    const int ty0 = (blockIdx.x / tilesX) << 4;
    const int co0 = blockIdx.y << 6;
    const int b   = blockIdx.z;
    const int HW  = H * W;
    const long long inBase = (long long)b * gInTot * HW;

    float acc[2][8][4];
#pragma unroll
    for (int mt = 0; mt < 2; mt++)
#pragma unroll
        for (int nt = 0; nt < 8; nt++)
#pragma unroll
            for (int r = 0; r < 4; r++) acc[mt][nt][r] = 0.f;

    auto stage = [&](int kt, int buf) {
        const int g0 = kt * 8;
        unsigned pb = smem_u32(sm + buf * STAGE);
        unsigned wb = pb + PATCH_W * 4;
        for (int idx = tid; idx < 8 * 18 * 6; idx += NTHREADS) {
            int g = idx / 108;
            int rem = idx - g * 108;
            int r = rem / 6, c = rem - r * 6;
            int gy = ty0 - 1 + r;
            int gxs = tx0 - 4 + 4 * c;
            bool ok = (unsigned)gy < (unsigned)H && gxs >= 0 && (gxs + 4) <= W;
            const unsigned* src = inH2 + inBase + (long long)(g0 + g) * HW
                                  + (ok ? (gy * W + gxs) : 0);
            cp16z(pb + (unsigned)(g * GSTRIDE + r * PW + 4 * c) * 4u, src, ok);
        }
        for (int idx = tid; idx < 72 * 16; idx += NTHREADS) {
            int row = idx >> 4;
            int cw  = idx & 15;
            int j   = row >> 3;
            int kg  = row & 7;
            const unsigned* src = wp + ((long long)(g0 + kg) * 9 + j) * coutPad
                                  + co0 + cw * 4;
            cp16(wb + (unsigned)(row * WROW + cw * 4) * 4u, src);
        }
    };

    auto compute = [&](int buf) {
        const unsigned* pbuf = sm + buf * STAGE;
        const unsigned* wbuf = pbuf + PATCH_W;
#pragma unroll
        for (int j = 0; j < 9; j++) {
            const int dy = j / 3, dx = j - 3 * dy;
            unsigned a[2][4];
#pragma unroll
            for (int mt = 0; mt < 2; mt++) {
                int cl = mwarp * 32 + mt * 16 + gid;
                a[mt][0] = wbuf[(j * 8 + tig) * WROW + cl];
                a[mt][1] = wbuf[(j * 8 + tig) * WROW + cl + 8];
                a[mt][2] = wbuf[(j * 8 + tig + 4) * WROW + cl];
                a[mt][3] = wbuf[(j * 8 + tig + 4) * WROW + cl + 8];
            }
            const unsigned* pb0 = pbuf + tig * GSTRIDE + dy * PW + dx + gid + 3;
            const unsigned* pb1 = pbuf + (tig + 4) * GSTRIDE + dy * PW + dx + gid + 3;
#pragma unroll
            for (int nt = 0; nt < 8; nt++) {
                int pix = nwarp * 64 + nt * 8;
                int off = (pix >> 4) * PW + (pix & 15);
                unsigned b0 = pb0[off];
                unsigned b1 = pb1[off];
                mma16(acc[0][nt], a[0], b0, b1);
                mma16(acc[1][nt], a[1], b0, b1);
            }
        }
    };

    stage(0, 0);
    cp_commit();
    for (int kt = 0; kt < kTiles; kt++) {
        int cur = kt & 1;
        if (kt + 1 < kTiles) {
            stage(kt + 1, cur ^ 1);
            cp_commit();
            cp_wait1();
        } else {
            cp_wait0();
        }
        __syncthreads();
        compute(cur);
        __syncthreads();
    }

#pragma unroll
    for (int mt = 0; mt < 2; mt++) {
#pragma unroll
        for (int rr = 0; rr < 2; rr++) {
            int co = co0 + mwarp * 32 + mt * 16 + rr * 8 + gid;
            float bv = bias[co];
#pragma unroll
            for (int nt = 0; nt < 8; nt++) {
                int pix = nwarp * 64 + nt * 8;
                int oy = ty0 + (pix >> 4);
                int ox = tx0 + (pix & 15) + 2 * tig;
                float v0 = acc[mt][nt][rr * 2]     + bv;
                float v1 = acc[mt][nt][rr * 2 + 1] + bv;
                if (addend) {
                    const float* ap = addend + (((long long)b * addCtot + co) * H + oy) * W + ox;
                    v0 += ap[0]; v1 += ap[1];
                }
                if (lrelu) {
                    v0 = v0 > 0.f ? v0 : 0.2f * v0;
                    v1 = v1 > 0.f ? v1 : 0.2f * v1;
                }
                if (out32) {
                    float2 val = make_float2(v0, v1);
                    *reinterpret_cast<float2*>(
                        out32 + (((long long)b * out32Ctot + co) * H + oy) * W + ox) = val;
                }
                if (outH2) {
                    float s0 = __shfl_xor_sync(0xffffffffu, v0, 4);
                    float s1 = __shfl_xor_sync(0xffffffffu, v1, 4);
                    if ((gid & 1) == 0) {
                        uint2 wv;
                        wv.x = h2bits(v0, s0);
                        wv.y = h2bits(v1, s1);
                        *reinterpret_cast<uint2*>(
                            outH2 + (((long long)b * gOutTot + gOutOff + (co >> 1)) * H + oy) * W + ox) = wv;
                    }
                }
            }
        }
    }
}

// ---------------------------------------------------------------------------
// Small-layer fp16 mma conv (COTILE=16, non-pipelined, handles padded K)
// ---------------------------------------------------------------------------
__global__ __launch_bounds__(128, 4)
void conv_mma16_k(const unsigned* __restrict__ inH2, int gInTot, int gInAct, int kTiles,
                  const unsigned* __restrict__ wp, int coutPad,
                  const float* __restrict__ bias,
                  float* __restrict__ out32, int out32Ctot,
                  unsigned* __restrict__ outH2, int gOutTot, int gOutOff,
                  int H, int W, int coutAct, int lrelu) {
    constexpr int COTILE = 16;
    __shared__ unsigned patch[8][18][20];
    __shared__ unsigned wsm[9][8][COTILE + 8];

    const int tid  = threadIdx.x;
    const int lane = tid & 31;
    const int warp = tid >> 5;
    const int gid  = lane >> 2;
    const int tig  = lane & 3;
    const int nwarp = warp;

    const int tilesX = W >> 4;
    const int tx0 = (blockIdx.x % tilesX) << 4;
    const int ty0 = (blockIdx.x / tilesX) << 4;
    const int co0 = blockIdx.y * COTILE;
    const int b   = blockIdx.z;
    const int HW  = H * W;

    float acc[8][4];
#pragma unroll
    for (int nt = 0; nt < 8; nt++)
#pragma unroll
        for (int r = 0; r < 4; r++) acc[nt][r] = 0.f;

    const long long inBase = (long long)b * gInTot * HW;

    for (int kt = 0; kt < kTiles; kt++) {
        const int g0 = kt * 8;
        __syncthreads();
        for (int idx = tid; idx < 8 * 324; idx += 128) {
            int g = idx / 324;
            int rem = idx - g * 324;
            int r = rem / 18, c = rem - r * 18;
            int gy = ty0 - 1 + r, gx = tx0 - 1 + c;
            unsigned v = 0;
            int absG = g0 + g;
            if (absG < gInAct && (unsigned)gy < (unsigned)H && (unsigned)gx < (unsigned)W)
                v = inH2[inBase + (long long)absG * HW + gy * W + gx];
            patch[g][r][c] = v;
        }
        for (int idx = tid; idx < 9 * 8 * (COTILE / 2); idx += 128) {
            int co2 = idx % (COTILE / 2);
            int t   = idx / (COTILE / 2);
            int kg  = t % 8;
            int j   = t / 8;
            uint2 v = *reinterpret_cast<const uint2*>(
                wp + ((long long)(g0 + kg) * 9 + j) * coutPad + co0 + 2 * co2);
            *reinterpret_cast<uint2*>(&wsm[j][kg][2 * co2]) = v;
        }
        __syncthreads();

#pragma unroll
        for (int j = 0; j < 9; j++) {
            const int dy = j / 3, dx = j - 3 * dy;
            unsigned a[4];
            a[0] = wsm[j][tig][gid];
            a[1] = wsm[j][tig][gid + 8];
            a[2] = wsm[j][tig + 4][gid];
            a[3] = wsm[j][tig + 4][gid + 8];
            const unsigned* pb0 = &patch[tig][dy][dx + gid];
            const unsigned* pb1 = &patch[tig + 4][dy][dx + gid];
#pragma unroll
            for (int nt = 0; nt < 8; nt++) {
                int pix = nwarp * 64 + nt * 8;
                int off = (pix >> 4) * 20 + (pix & 15);
                mma16(acc[nt], a, pb0[off], pb1[off]);
            }
        }
    }

#pragma unroll
    for (int rr = 0; rr < 2; rr++) {
        int co = co0 + rr * 8 + gid;
        float bv = (co < coutAct) ? bias[co] : 0.f;
#pragma unroll
        for (int nt = 0; nt < 8; nt++) {
            int pix = nwarp * 64 + nt * 8;
            int oy = ty0 + (pix >> 4);
            int ox = tx0 + (pix & 15) + 2 * tig;
            float v0 = acc[nt][rr * 2]     + bv;
            float v1 = acc[nt][rr * 2 + 1] + bv;
            if (lrelu) {
                v0 = v0 > 0.f ? v0 : 0.2f * v0;
                v1 = v1 > 0.f ? v1 : 0.2f * v1;
            }
            if (out32 && co < coutAct) {
                float2 val = make_float2(v0, v1);
                *reinterpret_cast<float2*>(
                    out32 + (((long long)b * out32Ctot + co) * H + oy) * W + ox) = val;
            }
            if (outH2) {
                float s0 = __shfl_xor_sync(0xffffffffu, v0, 4);
                float s1 = __shfl_xor_sync(0xffffffffu, v1, 4);
                if ((gid & 1) == 0) {
                    uint2 wv;
                    wv.x = h2bits(v0, s0);
                    wv.y = h2bits(v1, s1);
                    *reinterpret_cast<uint2*>(
                        outH2 + (((long long)b * gOutTot + gOutOff + (co >> 1)) * H + oy) * W + ox) = wv;
                }
            }
        }
    }
}

// ---------------------------------------------------------------------------
// Orchestration
// ---------------------------------------------------------------------------
extern "C" void kernel_launch(void* const* d_in, const int* in_sizes, int n_in,
                              void* d_out, int out_size) {
    const float* x        = (const float*)d_in[0];
    const float* conv1_w  = (const float*)d_in[1];
    const float* conv1_b  = (const float*)d_in[2];
    const float* conv2_w  = (const float*)d_in[3];
    const float* conv2_b  = (const float*)d_in[4];
    const float* conv3_w  = (const float*)d_in[5];
    const float* conv3_b  = (const float*)d_in[6];
    const float* conv4_w  = (const float*)d_in[7];
    const float* conv4_b  = (const float*)d_in[8];
    const float* convd1_w = (const float*)d_in[9];
    const float* convd1_b = (const float*)d_in[10];
    const float* convd2_w = (const float*)d_in[11];
    const float* convd2_b = (const float*)d_in[12];
    const float* convd3_w = (const float*)d_in[13];
    const float* convd3_b = (const float*)d_in[14];
    const float* convd4_w = (const float*)d_in[15];
    const float* convd4_b = (const float*)d_in[16];
    float* out = (float*)d_out;

    float *w4, *iw1;
    unsigned *w1h, *cat2h, *w2h, *cat3h, *w3h, *cat4h, *w4h, *c4h, *c5h;
    unsigned *ic4h, *ic3h, *ic2h, *ic1h;
    unsigned *wp1, *wp2, *wp3, *wp4, *wpd4, *wpd3, *wpd2, *wpd1;
    cudaGetSymbolAddress((void**)&w4,  g_w4);
    cudaGetSymbolAddress((void**)&iw1, g_iw1);
    cudaGetSymbolAddress((void**)&w1h,  g_w1h);
    cudaGetSymbolAddress((void**)&cat2h, g_cat2h);
    cudaGetSymbolAddress((void**)&w2h,  g_w2h);
    cudaGetSymbolAddress((void**)&cat3h, g_cat3h);
    cudaGetSymbolAddress((void**)&w3h,  g_w3h);
    cudaGetSymbolAddress((void**)&cat4h, g_cat4h);
    cudaGetSymbolAddress((void**)&w4h,  g_w4h);
    cudaGetSymbolAddress((void**)&c4h,  g_c4h);
    cudaGetSymbolAddress((void**)&c5h,  g_c5h);
    cudaGetSymbolAddress((void**)&ic4h, g_ic4h);
    cudaGetSymbolAddress((void**)&ic3h, g_ic3h);
    cudaGetSymbolAddress((void**)&ic2h, g_ic2h);
    cudaGetSymbolAddress((void**)&ic1h, g_ic1h);
    cudaGetSymbolAddress((void**)&wp1,  g_wp1);
    cudaGetSymbolAddress((void**)&wp2,  g_wp2);
    cudaGetSymbolAddress((void**)&wp3,  g_wp3);
    cudaGetSymbolAddress((void**)&wp4,  g_wp4);
    cudaGetSymbolAddress((void**)&wpd4, g_wpd4);
    cudaGetSymbolAddress((void**)&wpd3, g_wpd3);
    cudaGetSymbolAddress((void**)&wpd2, g_wpd2);
    cudaGetSymbolAddress((void**)&wpd1, g_wpd1);

    const int SMEMP = 2 * (8 * 504 + 72 * 72) * 4;  // 73728 B
    static bool attrSet = false;
    if (!attrSet) {
        cudaFuncSetAttribute(conv_mma_pipe_k,
                             cudaFuncAttributeMaxDynamicSharedMemorySize, SMEMP);
        attrSet = true;
    }

    const int B = 8;
    int tot;

    // --- pack all weights (coalesced transpose pack) ---
    auto pack = [](const float* w, unsigned* outp, int Cin, int CinPad, int Cout, int CoutPad) {
        int K2 = (CinPad / 2) * 9;
        dim3 grid((CoutPad + 31) / 32, (K2 + 31) / 32);
        pack_w_k<<<grid, dim3(32, 8)>>>(w, outp, Cin, Cout, CoutPad, K2);
    };
    pack(conv1_w,  wp1,    4,   16,   16,   16);
    pack(conv2_w,  wp2,   64,   64,   64,   64);
    pack(conv3_w,  wp3,  256,  256,  256,  256);
    pack(conv4_w,  wp4, 1024, 1024, 1024, 1024);
    pack(convd4_w, wpd4, 512,  512,  256,  256);
    pack(convd3_w, wpd3, 128,  128,   64,   64);
    pack(convd2_w, wpd2,  32,   32,   16,   16);
    pack(convd1_w, wpd1,  16,   16,    4,   16);

    // --- encoder ---
    tot = B * 1 * 256 * 256;
    wt_k<<<(tot + 255) / 256, 256>>>(x, 1, 256, 256, w1h, tot);

    // conv1: 4->16 @256²  -> cat2h g0..7 (h2 only)
    conv_mma16_k<<<dim3(256, 1, 8), 128>>>(w1h, 2, 2, 1, wp1, 16, conv1_b,
                                           nullptr, 0, cat2h, 16, 0, 256, 256, 16, 1);

    // wt(c1): h2 in (cat2h g0..7, Cg=8) -> w2h
    tot = B * 8 * 128 * 128;
    wt_h2_k<<<(tot + 255) / 256, 256>>>(cat2h, 16, 0, 8, 128, 128,
                                        nullptr, 0, w2h, 32, tot);

    // conv2: 64->64 @128² -> cat3h g0..31
    conv_mma_pipe_k<<<dim3(64, 1, 8), 256, SMEMP>>>(
        w2h, 32, 4, wp2, 64, conv2_b, nullptr, 0, cat3h, 64, 0, nullptr, 0, 128, 128, 1);

    // wt(c2): h2 in (cat3h g0..31, Cg=32) -> w3h
    tot = B * 32 * 64 * 64;
    wt_h2_k<<<(tot + 255) / 256, 256>>>(cat3h, 64, 0, 32, 64, 64,
                                        nullptr, 0, w3h, 128, tot);

    // conv3: 256->256 @64² -> cat4h g0..127
    conv_mma_pipe_k<<<dim3(16, 4, 8), 256, SMEMP>>>(
        w3h, 128, 16, wp3, 256, conv3_b, nullptr, 0, cat4h, 256, 0, nullptr, 0, 64, 64, 1);

    // wt(c3): h2 in (cat4h g0..127, Cg=128) -> w4h + fp32 w4 (residual addend)
    tot = B * 128 * 32 * 32;
    wt_h2_k<<<(tot + 255) / 256, 256>>>(cat4h, 256, 0, 128, 32, 32,
                                        w4, 1024, w4h, 512, tot);

    // --- bottleneck: conv4 x3 (1024->1024 @32²) ---
    conv_mma_pipe_k<<<dim3(4, 16, 8), 256, SMEMP>>>(
        w4h, 512, 64, wp4, 1024, conv4_b, nullptr, 0, c4h, 512, 0, nullptr, 0, 32, 32, 1);
    conv_mma_pipe_k<<<dim3(4, 16, 8), 256, SMEMP>>>(
        c4h, 512, 64, wp4, 1024, conv4_b, nullptr, 0, c5h, 512, 0, nullptr, 0, 32, 32, 1);
    conv_mma_pipe_k<<<dim3(4, 16, 8), 256, SMEMP>>>(
        c5h, 512, 64, wp4, 1024, conv4_b, nullptr, 0, ic4h, 512, 0, w4, 1024, 32, 32, 1);

    // --- decoder ---
    tot = B * 128 * 32 * 32;   // iwt(ic4): h2 -> cat4h g128..255
    iwt_h2_k<<<(tot + 255) / 256, 256>>>(ic4h, 128, 32, 32, cat4h, 256, 128, tot);

    // convd4: 512->256 @64² -> ic3h (h2)
    conv_mma_pipe_k<<<dim3(16, 4, 8), 256, SMEMP>>>(
        cat4h, 256, 32, wpd4, 256, convd4_b, nullptr, 0, ic3h, 128, 0, nullptr, 0, 64, 64, 1);

    tot = B * 32 * 64 * 64;    // iwt(ic3): h2 -> cat3h g32..63
    iwt_h2_k<<<(tot + 255) / 256, 256>>>(ic3h, 32, 64, 64, cat3h, 64, 32, tot);

    // convd3: 128->64 @128² -> ic2h (h2)
    conv_mma_pipe_k<<<dim3(64, 1, 8), 256, SMEMP>>>(
        cat3h, 64, 8, wpd3, 64, convd3_b, nullptr, 0, ic2h, 32, 0, nullptr, 0, 128, 128, 1);

    tot = B * 8 * 128 * 128;   // iwt(ic2): h2 -> cat2h g8..15
    iwt_h2_k<<<(tot + 255) / 256, 256>>>(ic2h, 8, 128, 128, cat2h, 16, 8, tot);

    // convd2: 32->16 @256² -> ic1h
    conv_mma16_k<<<dim3(256, 1, 8), 128>>>(cat2h, 16, 16, 2, wpd2, 16, convd2_b,
                                           nullptr, 0, ic1h, 8, 0, 256, 256, 16, 1);

    // convd1: 16->4 @256² -> iw1 fp32
    conv_mma16_k<<<dim3(256, 1, 8), 128>>>(ic1h, 8, 8, 1, wpd1, 16, convd1_b,
                                           iw1, 4, nullptr, 0, 0, 256, 256, 4, 1);

    tot = B * 256 * 256;       // sigmoid(iwt(iw1)) -> out
    iwt_sig_k<<<(tot + 255) / 256, 256>>>(iw1, 256, 256, out, tot);

    (void)in_sizes; (void)n_in; (void)out_size;
}

// round 10
// speedup vs baseline: 4.0985x; 1.0010x over previous
#include <cuda_runtime.h>
#include <cuda_fp16.h>

// ---------------------------------------------------------------------------
// helpers
// ---------------------------------------------------------------------------
__device__ __forceinline__ unsigned h2bits(float a, float b) {
    __half2 h = __floats2half2_rn(a, b);
    return *reinterpret_cast<unsigned*>(&h);
}
__device__ __forceinline__ float2 h2unpack(unsigned u) {
    return __half22float2(*reinterpret_cast<__half2*>(&u));
}

__device__ __forceinline__ void mma16(float d[4], const unsigned a[4],
                                      unsigned b0, unsigned b1) {
    asm("mma.sync.aligned.m16n8k16.row.col.f32.f16.f16.f32 "
        "{%0,%1,%2,%3},{%4,%5,%6,%7},{%8,%9},{%0,%1,%2,%3};"
        : "+f"(d[0]), "+f"(d[1]), "+f"(d[2]), "+f"(d[3])
        : "r"(a[0]), "r"(a[1]), "r"(a[2]), "r"(a[3]), "r"(b0), "r"(b1));
}

__device__ __forceinline__ unsigned smem_u32(const void* p) {
    return (unsigned)__cvta_generic_to_shared(p);
}
__device__ __forceinline__ void cp16z(unsigned dst, const void* src, bool ok) {
    int sz = ok ? 16 : 0;
    asm volatile("cp.async.cg.shared.global [%0], [%1], 16, %2;"
                 :: "r"(dst), "l"(src), "r"(sz));
}
__device__ __forceinline__ void cp16(unsigned dst, const void* src) {
    asm volatile("cp.async.cg.shared.global [%0], [%1], 16;" :: "r"(dst), "l"(src));
}
__device__ __forceinline__ void cp_commit() { asm volatile("cp.async.commit_group;"); }
__device__ __forceinline__ void cp_wait1() { asm volatile("cp.async.wait_group 1;"); }
__device__ __forceinline__ void cp_wait0() { asm volatile("cp.async.wait_group 0;"); }

// ---------------------------------------------------------------------------
// Scratch (device globals; allocation-free)
// ---------------------------------------------------------------------------
__device__ float g_w4 [ 8388608];  // [8,1024, 32, 32]  residual addend (fp32)
__device__ float g_iw1[ 2097152];  // [8,   4,256,256]  pre-sigmoid (fp32)

// half2 channel-pair-packed activations: word(b,g,y,x) = h2(ch 2g, ch 2g+1)
__device__ unsigned g_w1h  [ 1048576];
__device__ unsigned g_cat2h[ 8388608]; // c1 g0..7 | iwt(ic2) g8..15
__device__ unsigned g_w2h  [ 4194304];
__device__ unsigned g_cat3h[ 8388608]; // c2 g0..31 | iwt(ic3) g32..63
__device__ unsigned g_w3h  [ 4194304];
__device__ unsigned g_cat4h[ 8388608]; // c3 g0..127 | iwt(ic4) g128..255
__device__ unsigned g_w4h  [ 4194304];
__device__ unsigned g_c4h  [ 4194304];
__device__ unsigned g_c5h  [ 4194304];
__device__ unsigned g_ic4h [ 4194304]; // [8,512g,32,32]
__device__ unsigned g_ic3h [ 4194304]; // [8,128g,64,64]
__device__ unsigned g_ic2h [ 4194304]; // [8, 32g,128,128]
__device__ unsigned g_ic1h [ 4194304]; // [8,  8g,256,256]

// packed weights: [(CinPad/2)][9][CoutPad] half2 over (2ci,2ci+1)
__device__ unsigned g_wp1 [   1152];
__device__ unsigned g_wp2 [  18432];
__device__ unsigned g_wp3 [ 294912];
__device__ unsigned g_wp4 [4718592];
__device__ unsigned g_wpd4[ 589824];
__device__ unsigned g_wpd3[  36864];
__device__ unsigned g_wpd2[   2304];
__device__ unsigned g_wpd1[   1152];

// ---------------------------------------------------------------------------
// Coalesced weight packing via smem transpose.
// out[kj*CoutPad + co] = h2(w[co][2*ci2][j], w[co][2*ci2+1][j]), kj = ci2*9+j.
// ---------------------------------------------------------------------------
__global__ void pack_w_k(const float* __restrict__ w, unsigned* __restrict__ out,
                         int Cin, int Cout, int CoutPad, int K2) {
    __shared__ float sm[32][91];
    const int co0 = blockIdx.x * 32;
    const int kj0 = blockIdx.y * 32;
    const int ci2_lo = kj0 / 9;
    const int i_lo = ci2_lo * 18;
    const int Klen = Cin * 9;
    const int tid = threadIdx.y * 32 + threadIdx.x;

    for (int t = tid; t < 32 * 90; t += 256) {
        int r = t / 90, c = t - (t / 90) * 90;
        int co = co0 + r, i = i_lo + c;
        float v = 0.f;
        if (co < Cout && i < Klen) v = w[(long long)co * Klen + i];
        sm[r][c] = v;
    }
    __syncthreads();

    for (int t = tid; t < 32 * 32; t += 256) {
        int kr = t >> 5;
        int cl = t & 31;
        int kj = kj0 + kr;
        if (kj >= K2 || co0 + cl >= CoutPad) continue;   // <-- guard fixed
        int ci2 = kj / 9, j = kj - ci2 * 9;
        int ri = (ci2 - ci2_lo) * 18 + j;
        out[(long long)kj * CoutPad + co0 + cl] = h2bits(sm[cl][ri], sm[cl][ri + 9]);
    }
}

// ---------------------------------------------------------------------------
// Haar forward, fp32 input (layer 1 only, C=1)
// ---------------------------------------------------------------------------
__global__ void wt_k(const float* __restrict__ in, int C, int Ho, int Wo,
                     unsigned* __restrict__ outH2, int total) {
    int idx = blockIdx.x * blockDim.x + threadIdx.x;
    if (idx >= total) return;
    int wo = idx % Wo; int t = idx / Wo;
    int ho = t % Ho;  t /= Ho;
    int c  = t % C;   int b = t / C;
    int Wi = 2 * Wo;
    const float* p = in + (((long long)b * C + c) * (2 * Ho) + 2 * ho) * Wi + 2 * wo;
    float x00 = p[0], x01 = p[1], x10 = p[Wi], x11 = p[Wi + 1];
    float y0 = 0.25f * (x00 + x01 + x10 + x11);
    float y1 = 0.25f * (x00 + x01 - x10 - x11) + 0.5f;
    float y2 = 0.25f * (x00 - x01 + x10 - x11) + 0.5f;
    float y3 = 0.25f * (x00 - x01 - x10 + x11) + 0.5f;
    long long s = (long long)Ho * Wo;
    long long hb = (((long long)b * (2 * C) + 2 * c) * Ho + ho) * Wo + wo;
    outH2[hb]     = h2bits(y0, y1);
    outH2[hb + s] = h2bits(y2, y3);
}

// ---------------------------------------------------------------------------
// Haar forward, h2 input (channel pair g = channels 2g,2g+1).
// Optional fp32 out32 [B,4C,Ho,Wo] (residual addend for layer 4).
// ---------------------------------------------------------------------------
__global__ void wt_h2_k(const unsigned* __restrict__ in, int gInTot, int gInOff,
                        int Cg, int Ho, int Wo,
                        float* __restrict__ out32, int out32Ctot,
                        unsigned* __restrict__ outH2, int gOutTot, int total) {
    int idx = blockIdx.x * blockDim.x + threadIdx.x;
    if (idx >= total) return;
    int wo = idx % Wo; int t = idx / Wo;
    int ho = t % Ho;  t /= Ho;
    int g  = t % Cg;  int b = t / Cg;
    int Wi = 2 * Wo;
    const unsigned* p = in + (((long long)b * gInTot + gInOff + g) * (2 * Ho) + 2 * ho) * Wi + 2 * wo;
    float2 f00 = h2unpack(p[0]);
    float2 f01 = h2unpack(p[1]);
    float2 f10 = h2unpack(p[Wi]);
    float2 f11 = h2unpack(p[Wi + 1]);
    long long s = (long long)Ho * Wo;
#pragma unroll
    for (int cc = 0; cc < 2; cc++) {
        float x00 = cc ? f00.y : f00.x;
        float x01 = cc ? f01.y : f01.x;
        float x10 = cc ? f10.y : f10.x;
        float x11 = cc ? f11.y : f11.x;
        float y0 = 0.25f * (x00 + x01 + x10 + x11);
        float y1 = 0.25f * (x00 + x01 - x10 - x11) + 0.5f;
        float y2 = 0.25f * (x00 - x01 + x10 - x11) + 0.5f;
        float y3 = 0.25f * (x00 - x01 - x10 + x11) + 0.5f;
        long long hb = (((long long)b * gOutTot + 4 * g + 2 * cc) * Ho + ho) * Wo + wo;
        outH2[hb]     = h2bits(y0, y1);
        outH2[hb + s] = h2bits(y2, y3);
        if (out32) {
            int c = 2 * g + cc;
            long long ob = (((long long)b * out32Ctot + 4 * c) * Ho + ho) * Wo + wo;
            out32[ob]         = y0;
            out32[ob + s]     = y1;
            out32[ob + 2 * s] = y2;
            out32[ob + 3 * s] = y3;
        }
    }
}

// ---------------------------------------------------------------------------
// Haar inverse, h2 in / h2 out. Out pair g = out channels 2g,2g+1;
// reads input groups 4g..4g+3 (input has 4*pairs groups).
// ---------------------------------------------------------------------------
__global__ void iwt_h2_k(const unsigned* __restrict__ inH2, int pairs, int H, int W,
                         unsigned* __restrict__ outH2, int gTot, int gOff, int total) {
    int idx = blockIdx.x * blockDim.x + threadIdx.x;
    if (idx >= total) return;
    int w = idx % W; int t = idx / W;
    int h = t % H;  t /= H;
    int g = t % pairs; int b = t / pairs;
    long long s = (long long)H * W;
    long long base = (((long long)b * (4 * pairs) + 4 * g) * H + h) * W + w;
    float x00[2], x01[2], x10[2], x11[2];
#pragma unroll
    for (int cc = 0; cc < 2; cc++) {
        float2 fa = h2unpack(inH2[base + (2 * cc) * s]);      // (y0, y1)
        float2 fb = h2unpack(inH2[base + (2 * cc + 1) * s]);  // (y2, y3)
        float y0 = fa.x;
        float t1 = 2.f * fa.y - 1.f;
        float t2 = 2.f * fb.x - 1.f;
        float t3 = 2.f * fb.y - 1.f;
        x00[cc] = y0 + 0.5f * ( t1 + t2 + t3);
        x01[cc] = y0 + 0.5f * ( t1 - t2 - t3);
        x10[cc] = y0 + 0.5f * (-t1 + t2 - t3);
        x11[cc] = y0 + 0.5f * (-t1 - t2 + t3);
    }
    int W2 = 2 * W;
    long long ob = (((long long)b * gTot + gOff + g) * (2 * H) + 2 * h) * W2 + 2 * w;
    uint2 r0, r1;
    r0.x = h2bits(x00[0], x00[1]); r0.y = h2bits(x01[0], x01[1]);
    r1.x = h2bits(x10[0], x10[1]); r1.y = h2bits(x11[0], x11[1]);
    *reinterpret_cast<uint2*>(outH2 + ob)      = r0;
    *reinterpret_cast<uint2*>(outH2 + ob + W2) = r1;
}

// ---------------------------------------------------------------------------
// Final Haar inverse (C=1) + sigmoid, fp32 in/out
// ---------------------------------------------------------------------------
__global__ void iwt_sig_k(const float* __restrict__ in, int H, int W,
                          float* __restrict__ out, int total) {
    int idx = blockIdx.x * blockDim.x + threadIdx.x;
    if (idx >= total) return;
    int w = idx % W; int t = idx / W;
    int h = t % H;  int b = t / H;
    long long s = (long long)H * W;
    long long ib = (((long long)b * 4) * H + h) * W + w;
    float y0 = in[ib];
    float t1 = 2.f * in[ib + s]     - 1.f;
    float t2 = 2.f * in[ib + 2 * s] - 1.f;
    float t3 = 2.f * in[ib + 3 * s] - 1.f;
    float x00 = y0 + 0.5f * ( t1 + t2 + t3);
    float x01 = y0 + 0.5f * ( t1 - t2 - t3);
    float x10 = y0 + 0.5f * (-t1 + t2 - t3);
    float x11 = y0 + 0.5f * (-t1 - t2 + t3);
    x00 = 1.f / (1.f + expf(-x00));
    x01 = 1.f / (1.f + expf(-x01));
    x10 = 1.f / (1.f + expf(-x10));
    x11 = 1.f / (1.f + expf(-x11));
    int W2 = 2 * W;
    float* o = out + ((long long)b * (2 * H) + 2 * h) * W2 + 2 * w;
    o[0] = x00; o[1] = x01; o[W2] = x10; o[W2 + 1] = x11;
}

// ---------------------------------------------------------------------------
// Pipelined fp16 mma implicit-GEMM 3x3 conv (pad 1), cp.async double buffered.
// COTILE=64, 256 thr = 2 M-warps x 4 N-warps, 2 blocks/SM.
// ---------------------------------------------------------------------------
__global__ __launch_bounds__(256, 2)
void conv_mma_pipe_k(const unsigned* __restrict__ inH2, int gInTot, int kTiles,
                     const unsigned* __restrict__ wp, int coutPad,
                     const float* __restrict__ bias,
                     float* __restrict__ out32, int out32Ctot,
                     unsigned* __restrict__ outH2, int gOutTot, int gOutOff,
                     const float* __restrict__ addend, int addCtot,
                     int H, int W, int lrelu) {
    constexpr int NTHREADS = 256;
    constexpr int PW      = 28;
    constexpr int GSTRIDE = 18 * PW;       // 504
    constexpr int PATCH_W = 8 * GSTRIDE;   // 4032
    constexpr int WROW    = 72;
    constexpr int WSM_W   = 72 * WROW;     // 5184
    constexpr int STAGE   = PATCH_W + WSM_W;
    extern __shared__ unsigned sm[];

    const int tid  = threadIdx.x;
    const int lane = tid & 31;
    const int warp = tid >> 5;
    const int gid  = lane >> 2;
    const int tig  = lane & 3;
    const int mwarp = warp & 1;
    const int nwarp = warp >> 1;

    const int tilesX = W >> 4;
    const int tx0 = (blockIdx.x % tilesX) << 4;
    const int ty0 = (blockIdx.x / tilesX) << 4;
    const int co0 = blockIdx.y << 6;
    const int b   = blockIdx.z;
    const int HW  = H * W;
    const long long inBase = (long long)b * gInTot * HW;

    float acc[2][8][4];
#pragma unroll
    for (int mt = 0; mt < 2; mt++)
#pragma unroll
        for (int nt = 0; nt < 8; nt++)
#pragma unroll
            for (int r = 0; r < 4; r++) acc[mt][nt][r] = 0.f;

    auto stage = [&](int kt, int buf) {
        const int g0 = kt * 8;
        unsigned pb = smem_u32(sm + buf * STAGE);
        unsigned wb = pb + PATCH_W * 4;
        for (int idx = tid; idx < 8 * 18 * 6; idx += NTHREADS) {
            int g = idx / 108;
            int rem = idx - g * 108;
            int r = rem / 6, c = rem - r * 6;
            int gy = ty0 - 1 + r;
            int gxs = tx0 - 4 + 4 * c;
            bool ok = (unsigned)gy < (unsigned)H && gxs >= 0 && (gxs + 4) <= W;
            const unsigned* src = inH2 + inBase + (long long)(g0 + g) * HW
                                  + (ok ? (gy * W + gxs) : 0);
            cp16z(pb + (unsigned)(g * GSTRIDE + r * PW + 4 * c) * 4u, src, ok);
        }
        for (int idx = tid; idx < 72 * 16; idx += NTHREADS) {
            int row = idx >> 4;
            int cw  = idx & 15;
            int j   = row >> 3;
            int kg  = row & 7;
            const unsigned* src = wp + ((long long)(g0 + kg) * 9 + j) * coutPad
                                  + co0 + cw * 4;
            cp16(wb + (unsigned)(row * WROW + cw * 4) * 4u, src);
        }
    };

    auto compute = [&](int buf) {
        const unsigned* pbuf = sm + buf * STAGE;
        const unsigned* wbuf = pbuf + PATCH_W;
#pragma unroll
        for (int j = 0; j < 9; j++) {
            const int dy = j / 3, dx = j - 3 * dy;
            unsigned a[2][4];
#pragma unroll
            for (int mt = 0; mt < 2; mt++) {
                int cl = mwarp * 32 + mt * 16 + gid;
                a[mt][0] = wbuf[(j * 8 + tig) * WROW + cl];
                a[mt][1] = wbuf[(j * 8 + tig) * WROW + cl + 8];
                a[mt][2] = wbuf[(j * 8 + tig + 4) * WROW + cl];
                a[mt][3] = wbuf[(j * 8 + tig + 4) * WROW + cl + 8];
            }
            const unsigned* pb0 = pbuf + tig * GSTRIDE + dy * PW + dx + gid + 3;
            const unsigned* pb1 = pbuf + (tig + 4) * GSTRIDE + dy * PW + dx + gid + 3;
#pragma unroll
            for (int nt = 0; nt < 8; nt++) {
                int pix = nwarp * 64 + nt * 8;
                int off = (pix >> 4) * PW + (pix & 15);
                unsigned b0 = pb0[off];
                unsigned b1 = pb1[off];
                mma16(acc[0][nt], a[0], b0, b1);
                mma16(acc[1][nt], a[1], b0, b1);
            }
        }
    };

    stage(0, 0);
    cp_commit();
    for (int kt = 0; kt < kTiles; kt++) {
        int cur = kt & 1;
        if (kt + 1 < kTiles) {
            stage(kt + 1, cur ^ 1);
            cp_commit();
            cp_wait1();
        } else {
            cp_wait0();
        }
        __syncthreads();
        compute(cur);
        __syncthreads();
    }

#pragma unroll
    for (int mt = 0; mt < 2; mt++) {
#pragma unroll
        for (int rr = 0; rr < 2; rr++) {
            int co = co0 + mwarp * 32 + mt * 16 + rr * 8 + gid;
            float bv = bias[co];
#pragma unroll
            for (int nt = 0; nt < 8; nt++) {
                int pix = nwarp * 64 + nt * 8;
                int oy = ty0 + (pix >> 4);
                int ox = tx0 + (pix & 15) + 2 * tig;
                float v0 = acc[mt][nt][rr * 2]     + bv;
                float v1 = acc[mt][nt][rr * 2 + 1] + bv;
                if (addend) {
                    const float* ap = addend + (((long long)b * addCtot + co) * H + oy) * W + ox;
                    v0 += ap[0]; v1 += ap[1];
                }
                if (lrelu) {
                    v0 = v0 > 0.f ? v0 : 0.2f * v0;
                    v1 = v1 > 0.f ? v1 : 0.2f * v1;
                }
                if (out32) {
                    float2 val = make_float2(v0, v1);
                    *reinterpret_cast<float2*>(
                        out32 + (((long long)b * out32Ctot + co) * H + oy) * W + ox) = val;
                }
                if (outH2) {
                    float s0 = __shfl_xor_sync(0xffffffffu, v0, 4);
                    float s1 = __shfl_xor_sync(0xffffffffu, v1, 4);
                    if ((gid & 1) == 0) {
                        uint2 wv;
                        wv.x = h2bits(v0, s0);
                        wv.y = h2bits(v1, s1);
                        *reinterpret_cast<uint2*>(
                            outH2 + (((long long)b * gOutTot + gOutOff + (co >> 1)) * H + oy) * W + ox) = wv;
                    }
                }
            }
        }
    }
}

// ---------------------------------------------------------------------------
// Small-layer fp16 mma conv (COTILE=16, non-pipelined, handles padded K)
// ---------------------------------------------------------------------------
__global__ __launch_bounds__(128, 4)
void conv_mma16_k(const unsigned* __restrict__ inH2, int gInTot, int gInAct, int kTiles,
                  const unsigned* __restrict__ wp, int coutPad,
                  const float* __restrict__ bias,
                  float* __restrict__ out32, int out32Ctot,
                  unsigned* __restrict__ outH2, int gOutTot, int gOutOff,
                  int H, int W, int coutAct, int lrelu) {
    constexpr int COTILE = 16;
    __shared__ unsigned patch[8][18][20];
    __shared__ unsigned wsm[9][8][COTILE + 8];

    const int tid  = threadIdx.x;
    const int lane = tid & 31;
    const int warp = tid >> 5;
    const int gid  = lane >> 2;
    const int tig  = lane & 3;
    const int nwarp = warp;

    const int tilesX = W >> 4;
    const int tx0 = (blockIdx.x % tilesX) << 4;
    const int ty0 = (blockIdx.x / tilesX) << 4;
    const int co0 = blockIdx.y * COTILE;
    const int b   = blockIdx.z;
    const int HW  = H * W;

    float acc[8][4];
#pragma unroll
    for (int nt = 0; nt < 8; nt++)
#pragma unroll
        for (int r = 0; r < 4; r++) acc[nt][r] = 0.f;

    const long long inBase = (long long)b * gInTot * HW;

    for (int kt = 0; kt < kTiles; kt++) {
        const int g0 = kt * 8;
        __syncthreads();
        for (int idx = tid; idx < 8 * 324; idx += 128) {
            int g = idx / 324;
            int rem = idx - g * 324;
            int r = rem / 18, c = rem - r * 18;
            int gy = ty0 - 1 + r, gx = tx0 - 1 + c;
            unsigned v = 0;
            int absG = g0 + g;
            if (absG < gInAct && (unsigned)gy < (unsigned)H && (unsigned)gx < (unsigned)W)
                v = inH2[inBase + (long long)absG * HW + gy * W + gx];
            patch[g][r][c] = v;
        }
        for (int idx = tid; idx < 9 * 8 * (COTILE / 2); idx += 128) {
            int co2 = idx % (COTILE / 2);
            int t   = idx / (COTILE / 2);
            int kg  = t % 8;
            int j   = t / 8;
            uint2 v = *reinterpret_cast<const uint2*>(
                wp + ((long long)(g0 + kg) * 9 + j) * coutPad + co0 + 2 * co2);
            *reinterpret_cast<uint2*>(&wsm[j][kg][2 * co2]) = v;
        }
        __syncthreads();

#pragma unroll
        for (int j = 0; j < 9; j++) {
            const int dy = j / 3, dx = j - 3 * dy;
            unsigned a[4];
            a[0] = wsm[j][tig][gid];
            a[1] = wsm[j][tig][gid + 8];
            a[2] = wsm[j][tig + 4][gid];
            a[3] = wsm[j][tig + 4][gid + 8];
            const unsigned* pb0 = &patch[tig][dy][dx + gid];
            const unsigned* pb1 = &patch[tig + 4][dy][dx + gid];
#pragma unroll
            for (int nt = 0; nt < 8; nt++) {
                int pix = nwarp * 64 + nt * 8;
                int off = (pix >> 4) * 20 + (pix & 15);
                mma16(acc[nt], a, pb0[off], pb1[off]);
            }
        }
    }

#pragma unroll
    for (int rr = 0; rr < 2; rr++) {
        int co = co0 + rr * 8 + gid;
        float bv = (co < coutAct) ? bias[co] : 0.f;
#pragma unroll
        for (int nt = 0; nt < 8; nt++) {
            int pix = nwarp * 64 + nt * 8;
            int oy = ty0 + (pix >> 4);
            int ox = tx0 + (pix & 15) + 2 * tig;
            float v0 = acc[nt][rr * 2]     + bv;
            float v1 = acc[nt][rr * 2 + 1] + bv;
            if (lrelu) {
                v0 = v0 > 0.f ? v0 : 0.2f * v0;
                v1 = v1 > 0.f ? v1 : 0.2f * v1;
            }
            if (out32 && co < coutAct) {
                float2 val = make_float2(v0, v1);
                *reinterpret_cast<float2*>(
                    out32 + (((long long)b * out32Ctot + co) * H + oy) * W + ox) = val;
            }
            if (outH2) {
                float s0 = __shfl_xor_sync(0xffffffffu, v0, 4);
                float s1 = __shfl_xor_sync(0xffffffffu, v1, 4);
                if ((gid & 1) == 0) {
                    uint2 wv;
                    wv.x = h2bits(v0, s0);
                    wv.y = h2bits(v1, s1);
                    *reinterpret_cast<uint2*>(
                        outH2 + (((long long)b * gOutTot + gOutOff + (co >> 1)) * H + oy) * W + ox) = wv;
                }
            }
        }
    }
}

// ---------------------------------------------------------------------------
// Orchestration
// ---------------------------------------------------------------------------
extern "C" void kernel_launch(void* const* d_in, const int* in_sizes, int n_in,
                              void* d_out, int out_size) {
    const float* x        = (const float*)d_in[0];
    const float* conv1_w  = (const float*)d_in[1];
    const float* conv1_b  = (const float*)d_in[2];
    const float* conv2_w  = (const float*)d_in[3];
    const float* conv2_b  = (const float*)d_in[4];
    const float* conv3_w  = (const float*)d_in[5];
    const float* conv3_b  = (const float*)d_in[6];
    const float* conv4_w  = (const float*)d_in[7];
    const float* conv4_b  = (const float*)d_in[8];
    const float* convd1_w = (const float*)d_in[9];
    const float* convd1_b = (const float*)d_in[10];
    const float* convd2_w = (const float*)d_in[11];
    const float* convd2_b = (const float*)d_in[12];
    const float* convd3_w = (const float*)d_in[13];
    const float* convd3_b = (const float*)d_in[14];
    const float* convd4_w = (const float*)d_in[15];
    const float* convd4_b = (const float*)d_in[16];
    float* out = (float*)d_out;

    float *w4, *iw1;
    unsigned *w1h, *cat2h, *w2h, *cat3h, *w3h, *cat4h, *w4h, *c4h, *c5h;
    unsigned *ic4h, *ic3h, *ic2h, *ic1h;
    unsigned *wp1, *wp2, *wp3, *wp4, *wpd4, *wpd3, *wpd2, *wpd1;
    cudaGetSymbolAddress((void**)&w4,  g_w4);
    cudaGetSymbolAddress((void**)&iw1, g_iw1);
    cudaGetSymbolAddress((void**)&w1h,  g_w1h);
    cudaGetSymbolAddress((void**)&cat2h, g_cat2h);
    cudaGetSymbolAddress((void**)&w2h,  g_w2h);
    cudaGetSymbolAddress((void**)&cat3h, g_cat3h);
    cudaGetSymbolAddress((void**)&w3h,  g_w3h);
    cudaGetSymbolAddress((void**)&cat4h, g_cat4h);
    cudaGetSymbolAddress((void**)&w4h,  g_w4h);
    cudaGetSymbolAddress((void**)&c4h,  g_c4h);
    cudaGetSymbolAddress((void**)&c5h,  g_c5h);
    cudaGetSymbolAddress((void**)&ic4h, g_ic4h);
    cudaGetSymbolAddress((void**)&ic3h, g_ic3h);
    cudaGetSymbolAddress((void**)&ic2h, g_ic2h);
    cudaGetSymbolAddress((void**)&ic1h, g_ic1h);
    cudaGetSymbolAddress((void**)&wp1,  g_wp1);
    cudaGetSymbolAddress((void**)&wp2,  g_wp2);
    cudaGetSymbolAddress((void**)&wp3,  g_wp3);
    cudaGetSymbolAddress((void**)&wp4,  g_wp4);
    cudaGetSymbolAddress((void**)&wpd4, g_wpd4);
    cudaGetSymbolAddress((void**)&wpd3, g_wpd3);
    cudaGetSymbolAddress((void**)&wpd2, g_wpd2);
    cudaGetSymbolAddress((void**)&wpd1, g_wpd1);

    const int SMEMP = 2 * (8 * 504 + 72 * 72) * 4;  // 73728 B
    static bool attrSet = false;
    if (!attrSet) {
        cudaFuncSetAttribute(conv_mma_pipe_k,
                             cudaFuncAttributeMaxDynamicSharedMemorySize, SMEMP);
        attrSet = true;
    }

    const int B = 8;
    int tot;

    // --- pack all weights (coalesced transpose pack) ---
    auto pack = [](const float* w, unsigned* outp, int Cin, int CinPad, int Cout, int CoutPad) {
        int K2 = (CinPad / 2) * 9;
        dim3 grid((CoutPad + 31) / 32, (K2 + 31) / 32);
        pack_w_k<<<grid, dim3(32, 8)>>>(w, outp, Cin, Cout, CoutPad, K2);
    };
    pack(conv1_w,  wp1,    4,   16,   16,   16);
    pack(conv2_w,  wp2,   64,   64,   64,   64);
    pack(conv3_w,  wp3,  256,  256,  256,  256);
    pack(conv4_w,  wp4, 1024, 1024, 1024, 1024);
    pack(convd4_w, wpd4, 512,  512,  256,  256);
    pack(convd3_w, wpd3, 128,  128,   64,   64);
    pack(convd2_w, wpd2,  32,   32,   16,   16);
    pack(convd1_w, wpd1,  16,   16,    4,   16);

    // --- encoder ---
    tot = B * 1 * 256 * 256;
    wt_k<<<(tot + 255) / 256, 256>>>(x, 1, 256, 256, w1h, tot);

    // conv1: 4->16 @256²  -> cat2h g0..7 (h2 only)
    conv_mma16_k<<<dim3(256, 1, 8), 128>>>(w1h, 2, 2, 1, wp1, 16, conv1_b,
                                           nullptr, 0, cat2h, 16, 0, 256, 256, 16, 1);

    // wt(c1): h2 in (cat2h g0..7, Cg=8) -> w2h
    tot = B * 8 * 128 * 128;
    wt_h2_k<<<(tot + 255) / 256, 256>>>(cat2h, 16, 0, 8, 128, 128,
                                        nullptr, 0, w2h, 32, tot);

    // conv2: 64->64 @128² -> cat3h g0..31
    conv_mma_pipe_k<<<dim3(64, 1, 8), 256, SMEMP>>>(
        w2h, 32, 4, wp2, 64, conv2_b, nullptr, 0, cat3h, 64, 0, nullptr, 0, 128, 128, 1);

    // wt(c2): h2 in (cat3h g0..31, Cg=32) -> w3h
    tot = B * 32 * 64 * 64;
    wt_h2_k<<<(tot + 255) / 256, 256>>>(cat3h, 64, 0, 32, 64, 64,
                                        nullptr, 0, w3h, 128, tot);

    // conv3: 256->256 @64² -> cat4h g0..127
    conv_mma_pipe_k<<<dim3(16, 4, 8), 256, SMEMP>>>(
        w3h, 128, 16, wp3, 256, conv3_b, nullptr, 0, cat4h, 256, 0, nullptr, 0, 64, 64, 1);

    // wt(c3): h2 in (cat4h g0..127, Cg=128) -> w4h + fp32 w4 (residual addend)
    tot = B * 128 * 32 * 32;
    wt_h2_k<<<(tot + 255) / 256, 256>>>(cat4h, 256, 0, 128, 32, 32,
                                        w4, 1024, w4h, 512, tot);

    // --- bottleneck: conv4 x3 (1024->1024 @32²) ---
    conv_mma_pipe_k<<<dim3(4, 16, 8), 256, SMEMP>>>(
        w4h, 512, 64, wp4, 1024, conv4_b, nullptr, 0, c4h, 512, 0, nullptr, 0, 32, 32, 1);
    conv_mma_pipe_k<<<dim3(4, 16, 8), 256, SMEMP>>>(
        c4h, 512, 64, wp4, 1024, conv4_b, nullptr, 0, c5h, 512, 0, nullptr, 0, 32, 32, 1);
    conv_mma_pipe_k<<<dim3(4, 16, 8), 256, SMEMP>>>(
        c5h, 512, 64, wp4, 1024, conv4_b, nullptr, 0, ic4h, 512, 0, w4, 1024, 32, 32, 1);

    // --- decoder ---
    tot = B * 128 * 32 * 32;   // iwt(ic4): h2 -> cat4h g128..255
    iwt_h2_k<<<(tot + 255) / 256, 256>>>(ic4h, 128, 32, 32, cat4h, 256, 128, tot);

    // convd4: 512->256 @64² -> ic3h (h2)
    conv_mma_pipe_k<<<dim3(16, 4, 8), 256, SMEMP>>>(
        cat4h, 256, 32, wpd4, 256, convd4_b, nullptr, 0, ic3h, 128, 0, nullptr, 0, 64, 64, 1);

    tot = B * 32 * 64 * 64;    // iwt(ic3): h2 -> cat3h g32..63
    iwt_h2_k<<<(tot + 255) / 256, 256>>>(ic3h, 32, 64, 64, cat3h, 64, 32, tot);

    // convd3: 128->64 @128² -> ic2h (h2)
    conv_mma_pipe_k<<<dim3(64, 1, 8), 256, SMEMP>>>(
        cat3h, 64, 8, wpd3, 64, convd3_b, nullptr, 0, ic2h, 32, 0, nullptr, 0, 128, 128, 1);

    tot = B * 8 * 128 * 128;   // iwt(ic2): h2 -> cat2h g8..15
    iwt_h2_k<<<(tot + 255) / 256, 256>>>(ic2h, 8, 128, 128, cat2h, 16, 8, tot);

    // convd2: 32->16 @256² -> ic1h
    conv_mma16_k<<<dim3(256, 1, 8), 128>>>(cat2h, 16, 16, 2, wpd2, 16, convd2_b,
                                           nullptr, 0, ic1h, 8, 0, 256, 256, 16, 1);

    // convd1: 16->4 @256² -> iw1 fp32
    conv_mma16_k<<<dim3(256, 1, 8), 128>>>(ic1h, 8, 8, 1, wpd1, 16, convd1_b,
                                           iw1, 4, nullptr, 0, 0, 256, 256, 4, 1);

    tot = B * 256 * 256;       // sigmoid(iwt(iw1)) -> out
    iwt_sig_k<<<(tot + 255) / 256, 256>>>(iw1, 256, 256, out, tot);

    (void)in_sizes; (void)n_in; (void)out_size;
}

// round 12
// speedup vs baseline: 4.1831x; 1.0206x over previous
#include <cuda_runtime.h>
#include <cuda_fp16.h>
#include <cstdint>

__device__ __forceinline__ unsigned h2bits(float a, float b) {
    __half2 h = __floats2half2_rn(a, b);
    return *reinterpret_cast<unsigned*>(&h);
}
__device__ __forceinline__ float2 h2unpack(unsigned u) {
    return __half22float2(*reinterpret_cast<__half2*>(&u));
}
__device__ __forceinline__ void mma16(float d[4], const unsigned a[4],
                                      unsigned b0, unsigned b1) {
    asm("mma.sync.aligned.m16n8k16.row.col.f32.f16.f16.f32 "
        "{%0,%1,%2,%3},{%4,%5,%6,%7},{%8,%9},{%0,%1,%2,%3};"
        : "+f"(d[0]), "+f"(d[1]), "+f"(d[2]), "+f"(d[3])
        : "r"(a[0]), "r"(a[1]), "r"(a[2]), "r"(a[3]), "r"(b0), "r"(b1));
}
__device__ __forceinline__ void ldsm_x4(unsigned a[4], unsigned addr) {
    asm volatile("ldmatrix.sync.aligned.m8n8.x4.shared.b16 {%0,%1,%2,%3}, [%4];"
                 : "=r"(a[0]), "=r"(a[1]), "=r"(a[2]), "=r"(a[3]) : "r"(addr));
}
__device__ __forceinline__ unsigned smem_u32(const void* p) {
    return (unsigned)__cvta_generic_to_shared(p);
}
__device__ __forceinline__ void cp16z(unsigned dst, const void* src, bool ok) {
    int sz = ok ? 16 : 0;
    asm volatile("cp.async.cg.shared.global [%0], [%1], 16, %2;" :: "r"(dst), "l"(src), "r"(sz));
}
__device__ __forceinline__ void cp16(unsigned dst, const void* src) {
    asm volatile("cp.async.cg.shared.global [%0], [%1], 16;" :: "r"(dst), "l"(src));
}
__device__ __forceinline__ void cp_commit() { asm volatile("cp.async.commit_group;"); }
__device__ __forceinline__ void cp_wait1() { asm volatile("cp.async.wait_group 1;"); }
__device__ __forceinline__ void cp_wait0() { asm volatile("cp.async.wait_group 0;"); }

// ----- scratch -----
__device__ float g_w4 [8388608];   // [8,1024,32,32] residual (fp32)
__device__ float g_iw1[2097152];
__device__ unsigned g_w1h  [1048576];
__device__ unsigned g_cat2h[8388608];
__device__ unsigned g_w2h  [4194304];
__device__ unsigned g_cat3h[8388608];
__device__ unsigned g_w3h  [4194304];
__device__ unsigned g_cat4h[8388608];
__device__ unsigned g_w4h  [4194304];
__device__ unsigned g_c4h  [4194304];
__device__ unsigned g_c5h  [4194304];
__device__ unsigned g_ic4h [4194304];
__device__ unsigned g_ic3h [4194304];
__device__ unsigned g_ic2h [4194304];
__device__ unsigned g_ic1h [4194304];
// small-layer packed weights [(CinPad/2)][9][CoutPad]
__device__ unsigned g_wp1 [  1152];
__device__ unsigned g_wpd2[  2304];
__device__ unsigned g_wpd1[  1152];
// big-layer packed weights [kt16][tap][co][8 h2-words]
__device__ unsigned g_wp2 [  36864];  // 4*9*64*8*... = 4*9*64*8=18432? (alloc margin)
__device__ unsigned g_wp3 [ 331776];
__device__ unsigned g_wp4 [5308416];  // 64*9*1024*8 = 4718592 (+margin)
__device__ unsigned g_wpd4[ 663552];
__device__ unsigned g_wpd3[  73728];

// small-layer pack: out[kj*CoutPad+co]=h2(w[co][2ci2][j], w[co][2ci2+1][j])
__global__ void pack_w_k(const float* __restrict__ w, unsigned* __restrict__ out,
                         int Cin, int Cout, int CoutPad, int K2) {
    __shared__ float sm[32][91];
    const int co0 = blockIdx.x * 32, kj0 = blockIdx.y * 32;
    const int ci2_lo = kj0 / 9, i_lo = ci2_lo * 18, Klen = Cin * 9;
    const int tid = threadIdx.x;
    for (int t = tid; t < 32 * 90; t += 256) {
        int r = t / 90, c = t - r * 90;
        int co = co0 + r, i = i_lo + c;
        sm[r][c] = (co < Cout && i < Klen) ? w[(long long)co * Klen + i] : 0.f;
    }
    __syncthreads();
    for (int t = tid; t < 1024; t += 256) {
        int kr = t >> 5, cl = t & 31, kj = kj0 + kr;
        if (kj >= K2 || co0 + cl >= CoutPad) continue;
        int ci2 = kj / 9, j = kj - ci2 * 9, ri = (ci2 - ci2_lo) * 18 + j;
        out[(long long)kj * CoutPad + co0 + cl] = h2bits(sm[cl][ri], sm[cl][ri + 9]);
    }
}
// big-layer pack: out[((kt*9+tap)*Cout+co)*8+wd] = h2(w[co][kt*16+2wd][tap], +1)
__global__ void pack_wL_k(const float* __restrict__ w, unsigned* __restrict__ out,
                          int Cin, int Cout) {
    __shared__ float sm[32][145];
    const int co0 = blockIdx.x * 32, kt = blockIdx.y, tid = threadIdx.x;
    for (int t = tid; t < 32 * 144; t += 256) {
        int r = t / 144, c = t - r * 144;
        sm[r][c] = w[((long long)(co0 + r) * Cin + kt * 16) * 9 + c];
    }
    __syncthreads();
    for (int t = tid; t < 2304; t += 256) {
        int wd = t & 7, c = (t >> 3) & 31, tap = t >> 8;
        out[(((long long)kt * 9 + tap) * Cout + co0 + c) * 8 + wd] =
            h2bits(sm[c][(2 * wd) * 9 + tap], sm[c][(2 * wd + 1) * 9 + tap]);
    }
}

__global__ void wt_k(const float* __restrict__ in, int Ho, int Wo,
                     unsigned* __restrict__ outH2, int total) {
    int idx = blockIdx.x * blockDim.x + threadIdx.x;
    if (idx >= total) return;
    int wo = idx % Wo; int t = idx / Wo;
    int ho = t % Ho;  int b = t / Ho;
    int Wi = 2 * Wo;
    const float* p = in + ((long long)b * (2 * Ho) + 2 * ho) * Wi + 2 * wo;
    float x00 = p[0], x01 = p[1], x10 = p[Wi], x11 = p[Wi + 1];
    float y0 = 0.25f * (x00 + x01 + x10 + x11);
    float y1 = 0.25f * (x00 + x01 - x10 - x11) + 0.5f;
    float y2 = 0.25f * (x00 - x01 + x10 - x11) + 0.5f;
    float y3 = 0.25f * (x00 - x01 - x10 + x11) + 0.5f;
    long long s = (long long)Ho * Wo;
    long long hb = ((long long)b * 2 * Ho + ho) * Wo + wo;
    outH2[hb] = h2bits(y0, y1);
    outH2[hb + s] = h2bits(y2, y3);
}

__global__ void iwt_h2_k(const unsigned* __restrict__ inH2, int pairs, int H, int W,
                         unsigned* __restrict__ outH2, int gTot, int gOff, int total) {
    int idx = blockIdx.x * blockDim.x + threadIdx.x;
    if (idx >= total) return;
    int w = idx % W; int t = idx / W;
    int h = t % H;  t /= H;
    int g = t % pairs; int b = t / pairs;
    long long s = (long long)H * W;
    long long base = (((long long)b * (4 * pairs) + 4 * g) * H + h) * W + w;
    float x00[2], x01[2], x10[2], x11[2];
#pragma unroll
    for (int cc = 0; cc < 2; cc++) {
        float2 fa = h2unpack(inH2[base + (2 * cc) * s]);
        float2 fb = h2unpack(inH2[base + (2 * cc + 1) * s]);
        float y0 = fa.x, t1 = 2.f * fa.y - 1.f, t2 = 2.f * fb.x - 1.f, t3 = 2.f * fb.y - 1.f;
        x00[cc] = y0 + 0.5f * ( t1 + t2 + t3);
        x01[cc] = y0 + 0.5f * ( t1 - t2 - t3);
        x10[cc] = y0 + 0.5f * (-t1 + t2 - t3);
        x11[cc] = y0 + 0.5f * (-t1 - t2 + t3);
    }
    int W2 = 2 * W;
    long long ob = (((long long)b * gTot + gOff + g) * (2 * H) + 2 * h) * W2 + 2 * w;
    uint2 r0, r1;
    r0.x = h2bits(x00[0], x00[1]); r0.y = h2bits(x01[0], x01[1]);
    r1.x = h2bits(x10[0], x10[1]); r1.y = h2bits(x11[0], x11[1]);
    *reinterpret_cast<uint2*>(outH2 + ob) = r0;
    *reinterpret_cast<uint2*>(outH2 + ob + W2) = r1;
}

__global__ void iwt_sig_k(const float* __restrict__ in, int H, int W,
                          float* __restrict__ out, int total) {
    int idx = blockIdx.x * blockDim.x + threadIdx.x;
    if (idx >= total) return;
    int w = idx % W; int t = idx / W;
    int h = t % H;  int b = t / H;
    long long s = (long long)H * W;
    long long ib = (((long long)b * 4) * H + h) * W + w;
    float y0 = in[ib];
    float t1 = 2.f * in[ib + s] - 1.f, t2 = 2.f * in[ib + 2 * s] - 1.f, t3 = 2.f * in[ib + 3 * s] - 1.f;
    float x00 = y0 + 0.5f * ( t1 + t2 + t3);
    float x01 = y0 + 0.5f * ( t1 - t2 - t3);
    float x10 = y0 + 0.5f * (-t1 + t2 - t3);
    float x11 = y0 + 0.5f * (-t1 - t2 + t3);
    x00 = 1.f / (1.f + expf(-x00)); x01 = 1.f / (1.f + expf(-x01));
    x10 = 1.f / (1.f + expf(-x10)); x11 = 1.f / (1.f + expf(-x11));
    int W2 = 2 * W;
    float* o = out + ((long long)b * (2 * H) + 2 * h) * W2 + 2 * w;
    o[0] = x00; o[1] = x01; o[W2] = x10; o[W2 + 1] = x11;
}

// ---------------------------------------------------------------------------
// Pipelined fp16 mma conv: COTILE=64, 256 thr, 2 blocks/SM. A via ldmatrix.x4
// from wsmL[9][64 co][12-word rows]. Optional fused wt output (+fp32 wt copy).
// ---------------------------------------------------------------------------
__global__ __launch_bounds__(256, 2)
void conv_mma_pipe_k(const unsigned* __restrict__ inH2, int gInTot, int kTiles,
                     const unsigned* __restrict__ wp, int coutTot,
                     const float* __restrict__ bias,
                     unsigned* __restrict__ outH2, int gOutTot, int gOutOff,
                     unsigned* __restrict__ wtH2, float* __restrict__ wt32,
                     const float* __restrict__ addend, int addCtot,
                     int H, int W) {
    constexpr int PW = 28, GSTRIDE = 18 * PW, PATCH_W = 8 * GSTRIDE;  // 4032
    constexpr int WSM_W = 9 * 64 * 12;                                // 6912
    constexpr int STAGE = PATCH_W + WSM_W;                            // 10944
    extern __shared__ unsigned sm[];
    const int tid = threadIdx.x, lane = tid & 31, warp = tid >> 5;
    const int gid = lane >> 2, tig = lane & 3;
    const int mwarp = warp & 1, nwarp = warp >> 1;
    const int tilesX = W >> 4;
    const int tx0 = (blockIdx.x % tilesX) << 4, ty0 = (blockIdx.x / tilesX) << 4;
    const int co0 = blockIdx.y << 6, b = blockIdx.z;
    const int HW = H * W;
    const long long inBase = (long long)b * gInTot * HW;

    float acc[2][8][4];
#pragma unroll
    for (int mt = 0; mt < 2; mt++)
#pragma unroll
        for (int nt = 0; nt < 8; nt++)
#pragma unroll
            for (int r = 0; r < 4; r++) acc[mt][nt][r] = 0.f;

    auto stage = [&](int kt, int buf) {
        unsigned pb = smem_u32(sm + buf * STAGE);
        unsigned wb = pb + PATCH_W * 4;
        const int g0 = kt * 8;
        for (int idx = tid; idx < 864; idx += 256) {
            int g = idx / 108, rem = idx - g * 108;
            int r = rem / 6, c = rem - r * 6;
            int gy = ty0 - 1 + r, gxs = tx0 - 4 + 4 * c;
            bool ok = (unsigned)gy < (unsigned)H && gxs >= 0 && gxs + 4 <= W;
            const unsigned* src = inH2 + inBase + (long long)(g0 + g) * HW + (ok ? (gy * W + gxs) : 0);
            cp16z(pb + (unsigned)(g * GSTRIDE + r * PW + 4 * c) * 4u, src, ok);
        }
        for (int idx = tid; idx < 1152; idx += 256) {
            int half = idx & 1, row = idx >> 1;     // row = j*64 + co
            int j = row >> 6, co = row & 63;
            const unsigned* src = wp + (((long long)kt * 9 + j) * coutTot + co0 + co) * 8 + half * 4;
            cp16(wb + (unsigned)((j * 64 + co) * 12 + half * 4) * 4u, src);
        }
    };
    auto compute = [&](int buf) {
        const unsigned* pbuf = sm + buf * STAGE;
        unsigned wbase = smem_u32(sm + buf * STAGE + PATCH_W);
        int lr = lane & 7, hb = (lane >> 3) & 1, kq = (lane >> 4) & 1;
        unsigned aoff0 = wbase + (unsigned)(((mwarp * 32 + hb * 8 + lr) * 12 + kq * 4) << 2);
        unsigned aoff1 = aoff0 + (16 * 12) * 4;
#pragma unroll
        for (int j = 0; j < 9; j++) {
            const int dy = j / 3, dx = j - 3 * dy;
            unsigned a0[4], a1[4];
            ldsm_x4(a0, aoff0 + (unsigned)(j * 768 * 4));
            ldsm_x4(a1, aoff1 + (unsigned)(j * 768 * 4));
            const unsigned* pb0 = pbuf + tig * GSTRIDE + dy * PW + dx + gid + 3;
            const unsigned* pb1 = pbuf + (tig + 4) * GSTRIDE + dy * PW + dx + gid + 3;
#pragma unroll
            for (int nt = 0; nt < 8; nt++) {
                int pix = nwarp * 64 + nt * 8;
                int off = (pix >> 4) * PW + (pix & 15);
                mma16(acc[0][nt], a0, pb0[off], pb1[off]);
                mma16(acc[1][nt], a1, pb0[off], pb1[off]);
            }
        }
    };

    stage(0, 0); cp_commit();
    for (int kt = 0; kt < kTiles; kt++) {
        int cur = kt & 1;
        if (kt + 1 < kTiles) { stage(kt + 1, cur ^ 1); cp_commit(); cp_wait1(); }
        else cp_wait0();
        __syncthreads();
        compute(cur);
        __syncthreads();
    }

    const int Ho = H >> 1, Wo = W >> 1;
#pragma unroll
    for (int mt = 0; mt < 2; mt++)
#pragma unroll
        for (int rr = 0; rr < 2; rr++) {
            int co = co0 + mwarp * 32 + mt * 16 + rr * 8 + gid;
            float bv = bias[co];
#pragma unroll
            for (int np = 0; np < 4; np++) {
                int ntT = (np & 1) | ((np >> 1) << 2);   // 0,1,4,5
                int ntB = ntT + 2;
                int pixT = nwarp * 64 + ntT * 8;
                int oy = ty0 + (pixT >> 4);
                int ox = tx0 + (pixT & 15) + 2 * tig;
                float x00 = acc[mt][ntT][rr * 2] + bv, x01 = acc[mt][ntT][rr * 2 + 1] + bv;
                float x10 = acc[mt][ntB][rr * 2] + bv, x11 = acc[mt][ntB][rr * 2 + 1] + bv;
                if (addend) {
                    const float* ap = addend + (((long long)b * addCtot + co) * H + oy) * W + ox;
                    x00 += ap[0]; x01 += ap[1]; x10 += ap[W]; x11 += ap[W + 1];
                }
                x00 = x00 > 0.f ? x00 : 0.2f * x00;
                x01 = x01 > 0.f ? x01 : 0.2f * x01;
                x10 = x10 > 0.f ? x10 : 0.2f * x10;
                x11 = x11 > 0.f ? x11 : 0.2f * x11;
                // cat h2 stores (shfl pair across gid bit0)
                float sT0 = __shfl_xor_sync(0xffffffffu, x00, 4);
                float sT1 = __shfl_xor_sync(0xffffffffu, x01, 4);
                float sB0 = __shfl_xor_sync(0xffffffffu, x10, 4);
                float sB1 = __shfl_xor_sync(0xffffffffu, x11, 4);
                if ((gid & 1) == 0) {
                    long long ob = (((long long)b * gOutTot + gOutOff + (co >> 1)) * H + oy) * W + ox;
                    uint2 wT, wB;
                    wT.x = h2bits(x00, sT0); wT.y = h2bits(x01, sT1);
                    wB.x = h2bits(x10, sB0); wB.y = h2bits(x11, sB1);
                    *reinterpret_cast<uint2*>(outH2 + ob)     = wT;
                    *reinterpret_cast<uint2*>(outH2 + ob + W) = wB;
                }
                if (wtH2) {
                    float y0 = 0.25f * (x00 + x01 + x10 + x11);
                    float y1 = 0.25f * (x00 + x01 - x10 - x11) + 0.5f;
                    float y2 = 0.25f * (x00 - x01 + x10 - x11) + 0.5f;
                    float y3 = 0.25f * (x00 - x01 - x10 + x11) + 0.5f;
                    int ho = oy >> 1, wo = ox >> 1;
                    long long wbs = (((long long)b * (2 * coutTot) + 2 * co) * Ho + ho) * Wo + wo;
                    wtH2[wbs] = h2bits(y0, y1);
                    wtH2[wbs + (long long)Ho * Wo] = h2bits(y2, y3);
                    if (wt32) {
                        long long fb = (((long long)b * (4 * coutTot) + 4 * co) * Ho + ho) * Wo + wo;
                        long long sw = (long long)Ho * Wo;
                        wt32[fb] = y0; wt32[fb + sw] = y1;
                        wt32[fb + 2 * sw] = y2; wt32[fb + 3 * sw] = y3;
                    }
                }
            }
        }
}

// ----- small-layer mma conv (COTILE=16), optional fused wt -----
__global__ __launch_bounds__(128, 4)
void conv_mma16_k(const unsigned* __restrict__ inH2, int gInTot, int gInAct, int kTiles,
                  const unsigned* __restrict__ wp, int coutPad,
                  const float* __restrict__ bias,
                  float* __restrict__ out32, int out32Ctot,
                  unsigned* __restrict__ outH2, int gOutTot, int gOutOff,
                  unsigned* __restrict__ wtH2, int coutTot,
                  int H, int W, int coutAct) {
    __shared__ unsigned patch[8][18][20];
    __shared__ unsigned wsm[9][8][24];
    const int tid = threadIdx.x, lane = tid & 31, warp = tid >> 5;
    const int gid = lane >> 2, tig = lane & 3;
    const int tilesX = W >> 4;
    const int tx0 = (blockIdx.x % tilesX) << 4, ty0 = (blockIdx.x / tilesX) << 4;
    const int co0 = blockIdx.y * 16, b = blockIdx.z;
    const int HW = H * W;
    float acc[8][4];
#pragma unroll
    for (int nt = 0; nt < 8; nt++)
#pragma unroll
        for (int r = 0; r < 4; r++) acc[nt][r] = 0.f;
    const long long inBase = (long long)b * gInTot * HW;
    for (int kt = 0; kt < kTiles; kt++) {
        const int g0 = kt * 8;
        __syncthreads();
        for (int idx = tid; idx < 8 * 324; idx += 128) {
            int g = idx / 324, rem = idx - g * 324;
            int r = rem / 18, c = rem - r * 18;
            int gy = ty0 - 1 + r, gx = tx0 - 1 + c;
            unsigned v = 0;
            int aG = g0 + g;
            if (aG < gInAct && (unsigned)gy < (unsigned)H && (unsigned)gx < (unsigned)W)
                v = inH2[inBase + (long long)aG * HW + gy * W + gx];
            patch[g][r][c] = v;
        }
        for (int idx = tid; idx < 576; idx += 128) {
            int co2 = idx % 8, t = idx / 8;
            int kg = t % 8, j = t / 8;
            uint2 v = *reinterpret_cast<const uint2*>(
                wp + ((long long)(g0 + kg) * 9 + j) * coutPad + co0 + 2 * co2);
            *reinterpret_cast<uint2*>(&wsm[j][kg][2 * co2]) = v;
        }
        __syncthreads();
#pragma unroll
        for (int j = 0; j < 9; j++) {
            const int dy = j / 3, dx = j - 3 * dy;
            unsigned a[4];
            a[0] = wsm[j][tig][gid];     a[1] = wsm[j][tig][gid + 8];
            a[2] = wsm[j][tig + 4][gid]; a[3] = wsm[j][tig + 4][gid + 8];
            const unsigned* pb0 = &patch[tig][dy][dx + gid];
            const unsigned* pb1 = &patch[tig + 4][dy][dx + gid];
#pragma unroll
            for (int nt = 0; nt < 8; nt++) {
                int pix = warp * 64 + nt * 8;
                int off = (pix >> 4) * 20 + (pix & 15);
                mma16(acc[nt], a, pb0[off], pb1[off]);
            }
        }
    }
    const int Ho = H >> 1, Wo = W >> 1;
#pragma unroll
    for (int rr = 0; rr < 2; rr++) {
        int co = co0 + rr * 8 + gid;
        float bv = (co < coutAct) ? bias[co] : 0.f;
#pragma unroll
        for (int np = 0; np < 4; np++) {
            int ntT = (np & 1) | ((np >> 1) << 2);
            int ntB = ntT + 2;
            int pixT = warp * 64 + ntT * 8;
            int oy = ty0 + (pixT >> 4);
            int ox = tx0 + (pixT & 15) + 2 * tig;
            float x00 = acc[ntT][rr * 2] + bv, x01 = acc[ntT][rr * 2 + 1] + bv;
            float x10 = acc[ntB][rr * 2] + bv, x11 = acc[ntB][rr * 2 + 1] + bv;
            x00 = x00 > 0.f ? x00 : 0.2f * x00;
            x01 = x01 > 0.f ? x01 : 0.2f * x01;
            x10 = x10 > 0.f ? x10 : 0.2f * x10;
            x11 = x11 > 0.f ? x11 : 0.2f * x11;
            if (out32 && co < coutAct) {
                float* op = out32 + (((long long)b * out32Ctot + co) * H + oy) * W + ox;
                *reinterpret_cast<float2*>(op)     = make_float2(x00, x01);
                *reinterpret_cast<float2*>(op + W) = make_float2(x10, x11);
            }
            float sT0 = __shfl_xor_sync(0xffffffffu, x00, 4);
            float sT1 = __shfl_xor_sync(0xffffffffu, x01, 4);
            float sB0 = __shfl_xor_sync(0xffffffffu, x10, 4);
            float sB1 = __shfl_xor_sync(0xffffffffu, x11, 4);
            if (outH2 && (gid & 1) == 0) {
                long long ob = (((long long)b * gOutTot + gOutOff + (co >> 1)) * H + oy) * W + ox;
                uint2 wT, wB;
                wT.x = h2bits(x00, sT0); wT.y = h2bits(x01, sT1);
                wB.x = h2bits(x10, sB0); wB.y = h2bits(x11, sB1);
                *reinterpret_cast<uint2*>(outH2 + ob)     = wT;
                *reinterpret_cast<uint2*>(outH2 + ob + W) = wB;
            }
            if (wtH2 && co < coutAct) {
                float y0 = 0.25f * (x00 + x01 + x10 + x11);
                float y1 = 0.25f * (x00 + x01 - x10 - x11) + 0.5f;
                float y2 = 0.25f * (x00 - x01 + x10 - x11) + 0.5f;
                float y3 = 0.25f * (x00 - x01 - x10 + x11) + 0.5f;
                int ho = oy >> 1, wo = ox >> 1;
                long long wbs = (((long long)b * (2 * coutTot) + 2 * co) * Ho + ho) * Wo + wo;
                wtH2[wbs] = h2bits(y0, y1);
                wtH2[wbs + (long long)Ho * Wo] = h2bits(y2, y3);
            }
        }
    }
}

extern "C" void kernel_launch(void* const* d_in, const int* in_sizes, int n_in,
                              void* d_out, int out_size) {
    const float* x        = (const float*)d_in[0];
    const float* conv1_w  = (const float*)d_in[1];
    const float* conv1_b  = (const float*)d_in[2];
    const float* conv2_w  = (const float*)d_in[3];
    const float* conv2_b  = (const float*)d_in[4];
    const float* conv3_w  = (const float*)d_in[5];
    const float* conv3_b  = (const float*)d_in[6];
    const float* conv4_w  = (const float*)d_in[7];
    const float* conv4_b  = (const float*)d_in[8];
    const float* convd1_w = (const float*)d_in[9];
    const float* convd1_b = (const float*)d_in[10];
    const float* convd2_w = (const float*)d_in[11];
    const float* convd2_b = (const float*)d_in[12];
    const float* convd3_w = (const float*)d_in[13];
    const float* convd3_b = (const float*)d_in[14];
    const float* convd4_w = (const float*)d_in[15];
    const float* convd4_b = (const float*)d_in[16];
    float* out = (float*)d_out;

    float *w4, *iw1;
    unsigned *w1h, *cat2h, *w2h, *cat3h, *w3h, *cat4h, *w4h, *c4h, *c5h;
    unsigned *ic4h, *ic3h, *ic2h, *ic1h;
    unsigned *wp1, *wp2, *wp3, *wp4, *wpd4, *wpd3, *wpd2, *wpd1;
    cudaGetSymbolAddress((void**)&w4, g_w4);
    cudaGetSymbolAddress((void**)&iw1, g_iw1);
    cudaGetSymbolAddress((void**)&w1h, g_w1h);
    cudaGetSymbolAddress((void**)&cat2h, g_cat2h);
    cudaGetSymbolAddress((void**)&w2h, g_w2h);
    cudaGetSymbolAddress((void**)&cat3h, g_cat3h);
    cudaGetSymbolAddress((void**)&w3h, g_w3h);
    cudaGetSymbolAddress((void**)&cat4h, g_cat4h);
    cudaGetSymbolAddress((void**)&w4h, g_w4h);
    cudaGetSymbolAddress((void**)&c4h, g_c4h);
    cudaGetSymbolAddress((void**)&c5h, g_c5h);
    cudaGetSymbolAddress((void**)&ic4h, g_ic4h);
    cudaGetSymbolAddress((void**)&ic3h, g_ic3h);
    cudaGetSymbolAddress((void**)&ic2h, g_ic2h);
    cudaGetSymbolAddress((void**)&ic1h, g_ic1h);
    cudaGetSymbolAddress((void**)&wp1, g_wp1);
    cudaGetSymbolAddress((void**)&wp2, g_wp2);
    cudaGetSymbolAddress((void**)&wp3, g_wp3);
    cudaGetSymbolAddress((void**)&wp4, g_wp4);
    cudaGetSymbolAddress((void**)&wpd4, g_wpd4);
    cudaGetSymbolAddress((void**)&wpd3, g_wpd3);
    cudaGetSymbolAddress((void**)&wpd2, g_wpd2);
    cudaGetSymbolAddress((void**)&wpd1, g_wpd1);

    const int SMEMP = 2 * (4032 + 6912) * 4;   // 87552 B
    static bool attrSet = false;
    if (!attrSet) {
        cudaFuncSetAttribute(conv_mma_pipe_k, cudaFuncAttributeMaxDynamicSharedMemorySize, SMEMP);
        attrSet = true;
    }
    const int B = 8;
    int tot;

    auto packS = [](const float* w, unsigned* outp, int Cin, int CinPad, int Cout, int CoutPad) {
        int K2 = (CinPad / 2) * 9;
        dim3 grid((CoutPad + 31) / 32, (K2 + 31) / 32);
        pack_w_k<<<grid, 256>>>(w, outp, Cin, Cout, CoutPad, K2);
    };
    auto packL = [](const float* w, unsigned* outp, int Cin, int Cout) {
        pack_wL_k<<<dim3(Cout / 32, Cin / 16), 256>>>(w, outp, Cin, Cout);
    };
    packS(conv1_w,  wp1,    4,  16,  16,  16);
    packS(convd2_w, wpd2,  32,  32,  16,  16);
    packS(convd1_w, wpd1,  16,  16,   4,  16);
    packL(conv2_w,  wp2,   64,  64);
    packL(conv3_w,  wp3,  256, 256);
    packL(conv4_w,  wp4, 1024, 1024);
    packL(convd4_w, wpd4, 512, 256);
    packL(convd3_w, wpd3, 128,  64);

    tot = B * 256 * 256;
    wt_k<<<(tot + 255) / 256, 256>>>(x, 256, 256, w1h, tot);

    // conv1: 4->16 @256² -> cat2h g0..7 + fused wt -> w2h
    conv_mma16_k<<<dim3(256, 1, 8), 128>>>(w1h, 2, 2, 1, wp1, 16, conv1_b,
                                           nullptr, 0, cat2h, 16, 0, w2h, 16, 256, 256, 16);
    // conv2: 64->64 @128² -> cat3h g0..31 + wt -> w3h
    conv_mma_pipe_k<<<dim3(64, 1, 8), 256, SMEMP>>>(w2h, 32, 4, wp2, 64, conv2_b,
        cat3h, 64, 0, w3h, nullptr, nullptr, 0, 128, 128);
    // conv3: 256->256 @64² -> cat4h g0..127 + wt -> w4h + w4(fp32)
    conv_mma_pipe_k<<<dim3(16, 4, 8), 256, SMEMP>>>(w3h, 128, 16, wp3, 256, conv3_b,
        cat4h, 256, 0, w4h, w4, nullptr, 0, 64, 64);
    // conv4 x3
    conv_mma_pipe_k<<<dim3(4, 16, 8), 256, SMEMP>>>(w4h, 512, 64, wp4, 1024, conv4_b,
        c4h, 512, 0, nullptr, nullptr, nullptr, 0, 32, 32);
    conv_mma_pipe_k<<<dim3(4, 16, 8), 256, SMEMP>>>(c4h, 512, 64, wp4, 1024, conv4_b,
        c5h, 512, 0, nullptr, nullptr, nullptr, 0, 32, 32);
    conv_mma_pipe_k<<<dim3(4, 16, 8), 256, SMEMP>>>(c5h, 512, 64, wp4, 1024, conv4_b,
        ic4h, 512, 0, nullptr, nullptr, w4, 1024, 32, 32);

    tot = B * 128 * 32 * 32;
    iwt_h2_k<<<(tot + 255) / 256, 256>>>(ic4h, 128, 32, 32, cat4h, 256, 128, tot);

    conv_mma_pipe_k<<<dim3(16, 4, 8), 256, SMEMP>>>(cat4h, 256, 32, wpd4, 256, convd4_b,
        ic3h, 128, 0, nullptr, nullptr, nullptr, 0, 64, 64);
    tot = B * 32 * 64 * 64;
    iwt_h2_k<<<(tot + 255) / 256, 256>>>(ic3h, 32, 64, 64, cat3h, 64, 32, tot);

    conv_mma_pipe_k<<<dim3(64, 1, 8), 256, SMEMP>>>(cat3h, 64, 8, wpd3, 64, convd3_b,
        ic2h, 32, 0, nullptr, nullptr, nullptr, 0, 128, 128);
    tot = B * 8 * 128 * 128;
    iwt_h2_k<<<(tot + 255) / 256, 256>>>(ic2h, 8, 128, 128, cat2h, 16, 8, tot);

    conv_mma16_k<<<dim3(256, 1, 8), 128>>>(cat2h, 16, 16, 2, wpd2, 16, convd2_b,
                                           nullptr, 0, ic1h, 8, 0, nullptr, 16, 256, 256, 16);
    conv_mma16_k<<<dim3(256, 1, 8), 128>>>(ic1h, 8, 8, 1, wpd1, 16, convd1_b,
                                           iw1, 4, nullptr, 0, 0, nullptr, 4, 256, 256, 4);

    tot = B * 256 * 256;
    iwt_sig_k<<<(tot + 255) / 256, 256>>>(iw1, 256, 256, out, tot);

    (void)in_sizes; (void)n_in; (void)out_size;
}